// round 7
// baseline (speedup 1.0000x reference)
#include <cuda_runtime.h>
#include <cuda_bf16.h>
#include <cstdint>

#define BB   2
#define SS   2048
#define DD   512
#define HH   8
#define MM   (BB*SS)        // 4096
#define NQKV 1536
#define KK   512
#define YELEMS ((size_t)MM*DD)
#define ATTN_ELEMS ((size_t)BB*HH*SS*SS)
#define ATTN_SMEM (134*68*2*4)   // K + V tiles, rows padded to 68 floats

// Scratch (static device globals — no allocation)
__device__ float g_qkv[(size_t)MM*NQKV];      // Q|K|V packed per row
__device__ float g_attno[MM*DD];              // attention output (pre O-proj)
__device__ float g_y0[MM*DD];                 // residual + O-proj (pre-LN)
__device__ float g_probs[(size_t)BB*HH*SS*8]; // band softmax probs (padded to 8)

// ---------------------------------------------------------------------------
// pack float2 -> (hi bf16x2, lo bf16x2); element .x in low 16 bits
__device__ __forceinline__ void packhl(float2 v, uint32_t& h, uint32_t& l) {
    __nv_bfloat162 hb = __floats2bfloat162_rn(v.x, v.y);
    h = *reinterpret_cast<uint32_t*>(&hb);
    float hx = __bfloat162float(hb.x), hy = __bfloat162float(hb.y);
    __nv_bfloat162 lb = __floats2bfloat162_rn(v.x - hx, v.y - hy);
    l = *reinterpret_cast<uint32_t*>(&lb);
}

__device__ __forceinline__ void mma16(float* c, const uint32_t* a, const uint32_t* b) {
    asm volatile(
      "mma.sync.aligned.m16n8k16.row.col.f32.bf16.bf16.f32 "
      "{%0,%1,%2,%3},{%4,%5,%6,%7},{%8,%9},{%0,%1,%2,%3};"
      : "+f"(c[0]), "+f"(c[1]), "+f"(c[2]), "+f"(c[3])
      : "r"(a[0]), "r"(a[1]), "r"(a[2]), "r"(a[3]), "r"(b[0]), "r"(b[1]));
}

// ---------------------------------------------------------------------------
// Streaming zero-fill of the big attn output (replaces cudaMemsetAsync).
__global__ __launch_bounds__(256)
void zero_fill(float4* __restrict__ p, size_t n4) {
    size_t i = (size_t)blockIdx.x * blockDim.x + threadIdx.x;
    size_t stride = (size_t)gridDim.x * blockDim.x;
    const float4 z = make_float4(0.f, 0.f, 0.f, 0.f);
    for (; i < n4; i += stride) __stcs(&p[i], z);
}

// ---------------------------------------------------------------------------
// C[m,n] = sum_k A'[m,k]*W[n,k] + bias[n] (+ res[m,n]),  A' = A (+ pe row)
// bf16x3 split GEMM. Block tile 128x128, BK=32, 256 threads (8 warps),
// warp tile 32(M)x64(N). Per-lane frag smem layout (conflict-free LDS.128).
__global__ __launch_bounds__(256, 2)
void gemm_bf16x3(const float* __restrict__ A, const float* __restrict__ pe,
                 const float* __restrict__ W0, const float* __restrict__ W1, const float* __restrict__ W2,
                 const float* __restrict__ bi0, const float* __restrict__ bi1, const float* __restrict__ bi2,
                 const float* __restrict__ res, float* __restrict__ C, int ldc)
{
    __shared__ uint4 AsH[512], AsL[512];      // 16 frags x 32 lanes
    __shared__ uint2 BsH[1024], BsL[1024];    // 32 frags x 32 lanes

    const int t = threadIdx.x, lane = t & 31, w = t >> 5;
    const int g = lane >> 2, tg = lane & 3;
    const int bm = blockIdx.y * 128, bn = blockIdx.x * 128;
    const int seg = bn >> 9;
    const float* W  = (seg == 0) ? W0 : (seg == 1) ? W1 : W2;
    const float* bi = (seg == 0) ? bi0 : (seg == 1) ? bi1 : bi2;
    const int bnl = bn & 511;

    int a_r0[2], a_c0[2];
    #pragma unroll
    for (int s = 0; s < 2; s++) {
        int fa = w + 8*s;
        a_r0[s] = bm + (fa >> 1)*16 + g;
        a_c0[s] = (fa & 1)*16 + tg*2;
    }
    int b_n0[4], b_c0[4];
    #pragma unroll
    for (int s = 0; s < 4; s++) {
        int fb = w + 8*s;
        b_n0[s] = bnl + (fb >> 1)*8 + g;
        b_c0[s] = (fb & 1)*16 + tg*2;
    }

    float2 pa[2][4], pb[4][2];

    auto ldA = [&](int k0) {
        #pragma unroll
        for (int s = 0; s < 2; s++) {
            const float* p = A + (size_t)a_r0[s]*KK + a_c0[s] + k0;
            pa[s][0] = *(const float2*)p;
            pa[s][1] = *(const float2*)(p + 8*KK);
            pa[s][2] = *(const float2*)(p + 8);
            pa[s][3] = *(const float2*)(p + 8*KK + 8);
            if (pe) {
                const float* q0p = pe + (size_t)(a_r0[s] & (SS-1))*KK + a_c0[s] + k0;
                const float* q1p = pe + (size_t)((a_r0[s]+8) & (SS-1))*KK + a_c0[s] + k0;
                float2 e;
                e = *(const float2*)q0p;      pa[s][0].x += e.x; pa[s][0].y += e.y;
                e = *(const float2*)q1p;      pa[s][1].x += e.x; pa[s][1].y += e.y;
                e = *(const float2*)(q0p+8);  pa[s][2].x += e.x; pa[s][2].y += e.y;
                e = *(const float2*)(q1p+8);  pa[s][3].x += e.x; pa[s][3].y += e.y;
            }
        }
        #pragma unroll
        for (int s = 0; s < 4; s++) {
            const float* p = W + (size_t)b_n0[s]*KK + b_c0[s] + k0;
            pb[s][0] = *(const float2*)p;
            pb[s][1] = *(const float2*)(p + 8);
        }
    };

    auto stS = [&]() {
        #pragma unroll
        for (int s = 0; s < 2; s++) {
            uint4 hv, lv;
            packhl(pa[s][0], hv.x, lv.x);
            packhl(pa[s][1], hv.y, lv.y);
            packhl(pa[s][2], hv.z, lv.z);
            packhl(pa[s][3], hv.w, lv.w);
            AsH[(w + 8*s)*32 + lane] = hv;
            AsL[(w + 8*s)*32 + lane] = lv;
        }
        #pragma unroll
        for (int s = 0; s < 4; s++) {
            uint2 hv, lv;
            packhl(pb[s][0], hv.x, lv.x);
            packhl(pb[s][1], hv.y, lv.y);
            BsH[(w + 8*s)*32 + lane] = hv;
            BsL[(w + 8*s)*32 + lane] = lv;
        }
    };

    float acc[2][8][4] = {};
    const int wmt = (w & 3)*2, wnt = (w >> 2)*8;

    ldA(0);
    for (int k0 = 0; k0 < KK; k0 += 32) {
        stS();
        __syncthreads();
        if (k0 + 32 < KK) ldA(k0 + 32);

        #pragma unroll
        for (int kt = 0; kt < 2; kt++) {
            uint4 ah[2], al[2];
            uint2 bh[8], bl[8];
            #pragma unroll
            for (int m = 0; m < 2; m++) ah[m] = AsH[((wmt+m)*2 + kt)*32 + lane];
            #pragma unroll
            for (int n = 0; n < 8; n++) bh[n] = BsH[((wnt+n)*2 + kt)*32 + lane];
            #pragma unroll
            for (int m = 0; m < 2; m++)
                #pragma unroll
                for (int n = 0; n < 8; n++)
                    mma16(acc[m][n], (const uint32_t*)&ah[m], (const uint32_t*)&bh[n]);
            #pragma unroll
            for (int n = 0; n < 8; n++) bl[n] = BsL[((wnt+n)*2 + kt)*32 + lane];
            #pragma unroll
            for (int m = 0; m < 2; m++)
                #pragma unroll
                for (int n = 0; n < 8; n++)
                    mma16(acc[m][n], (const uint32_t*)&ah[m], (const uint32_t*)&bl[n]);
            #pragma unroll
            for (int m = 0; m < 2; m++) al[m] = AsL[((wmt+m)*2 + kt)*32 + lane];
            #pragma unroll
            for (int m = 0; m < 2; m++)
                #pragma unroll
                for (int n = 0; n < 8; n++)
                    mma16(acc[m][n], (const uint32_t*)&al[m], (const uint32_t*)&bh[n]);
        }
        __syncthreads();
    }

    #pragma unroll
    for (int m = 0; m < 2; m++) {
        const int gm = bm + (wmt + m)*16 + g;
        #pragma unroll
        for (int n = 0; n < 8; n++) {
            const int gn = bn + (wnt + n)*8 + tg*2;
            const int gl = gn & 511;
            float c0 = acc[m][n][0] + bi[gl];
            float c1 = acc[m][n][1] + bi[gl + 1];
            float c2 = acc[m][n][2] + bi[gl];
            float c3 = acc[m][n][3] + bi[gl + 1];
            if (res) {
                c0 += res[(size_t)gm*ldc + gn];
                c1 += res[(size_t)gm*ldc + gn + 1];
                c2 += res[(size_t)(gm+8)*ldc + gn];
                c3 += res[(size_t)(gm+8)*ldc + gn + 1];
            }
            *(float2*)&C[(size_t)gm*ldc + gn]     = make_float2(c0, c1);
            *(float2*)&C[(size_t)(gm+8)*ldc + gn] = make_float2(c2, c3);
        }
    }
}

// ---------------------------------------------------------------------------
// Banded attention: block = 128 q's of one (b,h). WIN=7, half=3.
// Writes attno and band probs to scratch (NOT the huge attn_out — no dep on
// zero_fill, so it can overlap it).
__global__ __launch_bounds__(128)
void attn2(const float* __restrict__ qkv, float* __restrict__ attno,
           float* __restrict__ probs)
{
    extern __shared__ float sh[];
    float* Ks = sh;               // [134][68]
    float* Vs = sh + 134*68;      // [134][68]

    const int t  = threadIdx.x;
    const int q0 = blockIdx.x * 128;
    const int h  = blockIdx.y;
    const int b  = blockIdx.z;

    for (int i = t; i < 134*16; i += 128) {
        int r = i >> 4, d4 = i & 15;
        int row = q0 - 3 + r;
        float4 kv = make_float4(0.f, 0.f, 0.f, 0.f);
        float4 vv = kv;
        if ((unsigned)row < SS) {
            size_t base = (size_t)(b*SS + row)*NQKV + h*64 + d4*4;
            kv = *(const float4*)&qkv[base + 512];
            vv = *(const float4*)&qkv[base + 1024];
        }
        *(float4*)&Ks[r*68 + d4*4] = kv;
        *(float4*)&Vs[r*68 + d4*4] = vv;
    }
    __syncthreads();

    const int q = q0 + t;
    float sc[7] = {0.f,0.f,0.f,0.f,0.f,0.f,0.f};
    const float* Qrow = &qkv[(size_t)(b*SS + q)*NQKV + h*64];

    for (int d4 = 0; d4 < 16; d4++) {
        float4 qv = *(const float4*)&Qrow[d4*4];
        #pragma unroll
        for (int j = 0; j < 7; j++) {
            float4 kk = *(const float4*)&Ks[(t + j)*68 + d4*4];
            sc[j] += qv.x*kk.x + qv.y*kk.y + qv.z*kk.z + qv.w*kk.w;
        }
    }

    float mx = -1e30f;
    #pragma unroll
    for (int j = 0; j < 7; j++) {
        sc[j] *= 0.125f;
        if ((unsigned)(q - 3 + j) < SS) mx = fmaxf(mx, sc[j]);
    }
    float p[7], sum = 0.f;
    #pragma unroll
    for (int j = 0; j < 7; j++) {
        p[j] = ((unsigned)(q - 3 + j) < SS) ? expf(sc[j] - mx) : 0.f;
        sum += p[j];
    }
    float inv = 1.0f / sum;
    #pragma unroll
    for (int j = 0; j < 7; j++) p[j] *= inv;

    float* Orow = &attno[(size_t)(b*SS + q)*DD + h*64];
    for (int d4 = 0; d4 < 16; d4++) {
        float4 o = make_float4(0.f, 0.f, 0.f, 0.f);
        #pragma unroll
        for (int j = 0; j < 7; j++) {
            float4 vv = *(const float4*)&Vs[(t + j)*68 + d4*4];
            o.x += p[j]*vv.x; o.y += p[j]*vv.y; o.z += p[j]*vv.z; o.w += p[j]*vv.w;
        }
        *(float4*)&Orow[d4*4] = o;
    }

    float* prow = &probs[((size_t)(b*HH + h)*SS + q)*8];
    *(float4*)&prow[0] = make_float4(p[0], p[1], p[2], p[3]);
    *(float4*)&prow[4] = make_float4(p[4], p[5], p[6], 0.f);
}

// ---------------------------------------------------------------------------
// Scatter band probs into the zeroed attn output (runs after zero_fill joins).
__global__ __launch_bounds__(256)
void band_write(const float* __restrict__ probs, float* __restrict__ attn_out) {
    int idx = blockIdx.x * blockDim.x + threadIdx.x;   // over BB*HH*SS
    if (idx >= BB*HH*SS) return;
    int q = idx & (SS - 1);
    const float* prow = &probs[(size_t)idx * 8];
    float4 p03 = *(const float4*)&prow[0];
    float4 p46 = *(const float4*)&prow[4];
    float p[7] = {p03.x, p03.y, p03.z, p03.w, p46.x, p46.y, p46.z};
    float* arow = attn_out + (size_t)idx * SS;
    #pragma unroll
    for (int j = 0; j < 7; j++) {
        int k = q - 3 + j;
        if ((unsigned)k < SS) arow[k] = p[j];
    }
}

// ---------------------------------------------------------------------------
// LayerNorm over D=512 per row; 128 threads, float4 each
__global__ __launch_bounds__(128)
void ln2(const float* __restrict__ y0, const float* __restrict__ gw,
         const float* __restrict__ bt, float* __restrict__ out)
{
    const int m = blockIdx.x, t = threadIdx.x;
    float4 v = ((const float4*)(y0 + (size_t)m*DD))[t];
    float s  = v.x + v.y + v.z + v.w;
    float sq = v.x*v.x + v.y*v.y + v.z*v.z + v.w*v.w;
    #pragma unroll
    for (int o = 16; o; o >>= 1) {
        s  += __shfl_xor_sync(0xffffffffu, s,  o);
        sq += __shfl_xor_sync(0xffffffffu, sq, o);
    }
    __shared__ float ss[4], qq[4];
    int w = t >> 5;
    if ((t & 31) == 0) { ss[w] = s; qq[w] = sq; }
    __syncthreads();
    s  = ss[0] + ss[1] + ss[2] + ss[3];
    sq = qq[0] + qq[1] + qq[2] + qq[3];
    float mean = s * (1.0f/DD);
    float var  = sq * (1.0f/DD) - mean*mean;
    float rstd = rsqrtf(var + 1e-5f);
    float4 gg = ((const float4*)gw)[t];
    float4 bb = ((const float4*)bt)[t];
    float4 r;
    r.x = (v.x - mean)*rstd*gg.x + bb.x;
    r.y = (v.y - mean)*rstd*gg.y + bb.y;
    r.z = (v.z - mean)*rstd*gg.z + bb.z;
    r.w = (v.w - mean)*rstd*gg.w + bb.w;
    ((float4*)(out + (size_t)m*DD))[t] = r;
}

// ---------------------------------------------------------------------------
extern "C" void kernel_launch(void* const* d_in, const int* in_sizes, int n_in,
                              void* d_out, int out_size) {
    const float* x    = (const float*)d_in[0];
    const float* wq_w = (const float*)d_in[2];
    const float* wq_b = (const float*)d_in[3];
    const float* wk_w = (const float*)d_in[4];
    const float* wk_b = (const float*)d_in[5];
    const float* wv_w = (const float*)d_in[6];
    const float* wv_b = (const float*)d_in[7];
    const float* wo_w = (const float*)d_in[8];
    const float* wo_b = (const float*)d_in[9];
    const float* ln_g = (const float*)d_in[10];
    const float* ln_b = (const float*)d_in[11];
    const float* pe   = (const float*)d_in[12];

    float* y_out    = (float*)d_out;
    float* attn_out = (float*)d_out + YELEMS;

    static float *p_qkv, *p_attno, *p_y0, *p_probs;
    static cudaStream_t s2;
    static cudaEvent_t evF, evJ;
    static bool init = false;
    if (!init) {
        cudaGetSymbolAddress((void**)&p_qkv,   g_qkv);
        cudaGetSymbolAddress((void**)&p_attno, g_attno);
        cudaGetSymbolAddress((void**)&p_y0,    g_y0);
        cudaGetSymbolAddress((void**)&p_probs, g_probs);
        cudaStreamCreateWithFlags(&s2, cudaStreamNonBlocking);
        cudaEventCreateWithFlags(&evF, cudaEventDisableTiming);
        cudaEventCreateWithFlags(&evJ, cudaEventDisableTiming);
        cudaFuncSetAttribute(attn2, cudaFuncAttributeMaxDynamicSharedMemorySize, ATTN_SMEM);
        init = true;
    }

    // fork: zero the 268MB attn output on a side stream (custom streaming kernel)
    cudaEventRecord(evF, 0);
    cudaStreamWaitEvent(s2, evF, 0);
    zero_fill<<<2368, 256, 0, s2>>>((float4*)attn_out, ATTN_ELEMS/4);
    cudaEventRecord(evJ, s2);

    // main chain (overlaps zero_fill entirely):
    // QKV projection (fused x+pe, 3-ptr weight select)
    gemm_bf16x3<<<dim3(NQKV/128, MM/128), 256>>>(x, pe, wq_w, wk_w, wv_w,
                                                 wq_b, wk_b, wv_b,
                                                 nullptr, p_qkv, NQKV);

    // banded attention -> attno + band probs scratch (no attn_out dep)
    attn2<<<dim3(SS/128, HH, BB), 128, ATTN_SMEM>>>(p_qkv, p_attno, p_probs);

    // O projection + residual
    gemm_bf16x3<<<dim3(DD/128, MM/128), 256>>>(p_attno, nullptr, wo_w, wo_w, wo_w,
                                               wo_b, wo_b, wo_b,
                                               x, p_y0, DD);

    // LayerNorm
    ln2<<<MM, 128>>>(p_y0, ln_g, ln_b, y_out);

    // join zero_fill, then scatter the band values
    cudaStreamWaitEvent(0, evJ, 0);
    band_write<<<(BB*HH*SS + 255)/256, 256>>>(p_probs, attn_out);
}

// round 8
// speedup vs baseline: 1.0003x; 1.0003x over previous
#include <cuda_runtime.h>
#include <cuda_bf16.h>
#include <cstdint>

#define BB   2
#define SS   2048
#define DD   512
#define HH   8
#define MM   (BB*SS)        // 4096
#define NQKV 1536
#define KK   512
#define YELEMS ((size_t)MM*DD)
#define ATTN_ELEMS ((size_t)BB*HH*SS*SS)
#define ATTN_SMEM (134*68*2*4)   // K + V tiles, rows padded to 68 floats

// Scratch (static device globals — no allocation)
__device__ float g_qkv[(size_t)MM*NQKV];      // Q|K|V packed per row
__device__ float g_attno[MM*DD];              // attention output (pre O-proj)
__device__ float g_y0[MM*DD];                 // residual + O-proj (pre-LN)
__device__ float g_probs[(size_t)BB*HH*SS*8]; // band softmax probs (padded to 8)

// ---------------------------------------------------------------------------
// pack float2 -> (hi bf16x2, lo bf16x2); element .x in low 16 bits
__device__ __forceinline__ void packhl(float2 v, uint32_t& h, uint32_t& l) {
    __nv_bfloat162 hb = __floats2bfloat162_rn(v.x, v.y);
    h = *reinterpret_cast<uint32_t*>(&hb);
    float hx = __bfloat162float(hb.x), hy = __bfloat162float(hb.y);
    __nv_bfloat162 lb = __floats2bfloat162_rn(v.x - hx, v.y - hy);
    l = *reinterpret_cast<uint32_t*>(&lb);
}

__device__ __forceinline__ void mma16(float* c, const uint32_t* a, const uint32_t* b) {
    asm volatile(
      "mma.sync.aligned.m16n8k16.row.col.f32.bf16.bf16.f32 "
      "{%0,%1,%2,%3},{%4,%5,%6,%7},{%8,%9},{%0,%1,%2,%3};"
      : "+f"(c[0]), "+f"(c[1]), "+f"(c[2]), "+f"(c[3])
      : "r"(a[0]), "r"(a[1]), "r"(a[2]), "r"(a[3]), "r"(b[0]), "r"(b[1]));
}

// ---------------------------------------------------------------------------
// Streaming zero-fill of the big attn output. Modest grid so it co-schedules
// with the compute chain instead of monopolizing SMs.
__global__ __launch_bounds__(256)
void zero_fill(float4* __restrict__ p, size_t n4) {
    size_t i = (size_t)blockIdx.x * blockDim.x + threadIdx.x;
    size_t stride = (size_t)gridDim.x * blockDim.x;
    const float4 z = make_float4(0.f, 0.f, 0.f, 0.f);
    for (; i < n4; i += stride) __stcs(&p[i], z);
}

// ---------------------------------------------------------------------------
// C[m,n] = sum_k A'[m,k]*W[n,k] + bias[n] (+ res[m,n]),  A' = A (+ pe row)
// bf16x3 split GEMM. Block tile 64x64, BK=32, 128 threads (4 warps),
// warp tile 32(M)x32(N). Per-lane frag smem layout (conflict-free LDS.128).
__global__ __launch_bounds__(128, 5)
void gemm_bf16x3(const float* __restrict__ A, const float* __restrict__ pe,
                 const float* __restrict__ W0, const float* __restrict__ W1, const float* __restrict__ W2,
                 const float* __restrict__ bi0, const float* __restrict__ bi1, const float* __restrict__ bi2,
                 const float* __restrict__ res, float* __restrict__ C, int ldc)
{
    __shared__ uint4 AsH[256], AsL[256];      // 8 frags x 32 lanes
    __shared__ uint2 BsH[512], BsL[512];      // 16 frags x 32 lanes

    const int t = threadIdx.x, lane = t & 31, w = t >> 5;   // w: 0..3
    const int g = lane >> 2, tg = lane & 3;
    const int bm = blockIdx.y * 64, bn = blockIdx.x * 64;
    const int seg = bn >> 9;
    const float* W  = (seg == 0) ? W0 : (seg == 1) ? W1 : W2;
    const float* bi = (seg == 0) ? bi0 : (seg == 1) ? bi1 : bi2;
    const int bnl = bn & 511;

    // store-phase slot coordinates: A frags 8 (mt4 x kt2), B frags 16 (nt8 x kt2)
    int a_r0[2], a_c0[2];
    #pragma unroll
    for (int s = 0; s < 2; s++) {
        int fa = w + 4*s;
        a_r0[s] = bm + (fa >> 1)*16 + g;
        a_c0[s] = (fa & 1)*16 + tg*2;
    }
    int b_n0[4], b_c0[4];
    #pragma unroll
    for (int s = 0; s < 4; s++) {
        int fb = w + 4*s;
        b_n0[s] = bnl + (fb >> 1)*8 + g;
        b_c0[s] = (fb & 1)*16 + tg*2;
    }

    float2 pa[2][4], pb[4][2];

    auto ldA = [&](int k0) {
        #pragma unroll
        for (int s = 0; s < 2; s++) {
            const float* p = A + (size_t)a_r0[s]*KK + a_c0[s] + k0;
            pa[s][0] = *(const float2*)p;
            pa[s][1] = *(const float2*)(p + 8*KK);
            pa[s][2] = *(const float2*)(p + 8);
            pa[s][3] = *(const float2*)(p + 8*KK + 8);
            if (pe) {
                const float* q0p = pe + (size_t)(a_r0[s] & (SS-1))*KK + a_c0[s] + k0;
                const float* q1p = pe + (size_t)((a_r0[s]+8) & (SS-1))*KK + a_c0[s] + k0;
                float2 e;
                e = *(const float2*)q0p;      pa[s][0].x += e.x; pa[s][0].y += e.y;
                e = *(const float2*)q1p;      pa[s][1].x += e.x; pa[s][1].y += e.y;
                e = *(const float2*)(q0p+8);  pa[s][2].x += e.x; pa[s][2].y += e.y;
                e = *(const float2*)(q1p+8);  pa[s][3].x += e.x; pa[s][3].y += e.y;
            }
        }
        #pragma unroll
        for (int s = 0; s < 4; s++) {
            const float* p = W + (size_t)b_n0[s]*KK + b_c0[s] + k0;
            pb[s][0] = *(const float2*)p;
            pb[s][1] = *(const float2*)(p + 8);
        }
    };

    auto stS = [&]() {
        #pragma unroll
        for (int s = 0; s < 2; s++) {
            uint4 hv, lv;
            packhl(pa[s][0], hv.x, lv.x);
            packhl(pa[s][1], hv.y, lv.y);
            packhl(pa[s][2], hv.z, lv.z);
            packhl(pa[s][3], hv.w, lv.w);
            AsH[(w + 4*s)*32 + lane] = hv;
            AsL[(w + 4*s)*32 + lane] = lv;
        }
        #pragma unroll
        for (int s = 0; s < 4; s++) {
            uint2 hv, lv;
            packhl(pb[s][0], hv.x, lv.x);
            packhl(pb[s][1], hv.y, lv.y);
            BsH[(w + 4*s)*32 + lane] = hv;
            BsL[(w + 4*s)*32 + lane] = lv;
        }
    };

    float acc[2][4][4] = {};
    const int wmt = (w & 1)*2, wnt = (w >> 1)*4;

    ldA(0);
    for (int k0 = 0; k0 < KK; k0 += 32) {
        stS();
        __syncthreads();
        if (k0 + 32 < KK) ldA(k0 + 32);

        #pragma unroll
        for (int kt = 0; kt < 2; kt++) {
            uint4 ah[2], al[2];
            uint2 bh[4], bl[4];
            #pragma unroll
            for (int m = 0; m < 2; m++) ah[m] = AsH[((wmt+m)*2 + kt)*32 + lane];
            #pragma unroll
            for (int n = 0; n < 4; n++) bh[n] = BsH[((wnt+n)*2 + kt)*32 + lane];
            #pragma unroll
            for (int m = 0; m < 2; m++)
                #pragma unroll
                for (int n = 0; n < 4; n++)
                    mma16(acc[m][n], (const uint32_t*)&ah[m], (const uint32_t*)&bh[n]);
            #pragma unroll
            for (int n = 0; n < 4; n++) bl[n] = BsL[((wnt+n)*2 + kt)*32 + lane];
            #pragma unroll
            for (int m = 0; m < 2; m++)
                #pragma unroll
                for (int n = 0; n < 4; n++)
                    mma16(acc[m][n], (const uint32_t*)&ah[m], (const uint32_t*)&bl[n]);
            #pragma unroll
            for (int m = 0; m < 2; m++) al[m] = AsL[((wmt+m)*2 + kt)*32 + lane];
            #pragma unroll
            for (int m = 0; m < 2; m++)
                #pragma unroll
                for (int n = 0; n < 4; n++)
                    mma16(acc[m][n], (const uint32_t*)&al[m], (const uint32_t*)&bh[n]);
        }
        __syncthreads();
    }

    #pragma unroll
    for (int m = 0; m < 2; m++) {
        const int gm = bm + (wmt + m)*16 + g;
        #pragma unroll
        for (int n = 0; n < 4; n++) {
            const int gn = bn + (wnt + n)*8 + tg*2;
            const int gl = gn & 511;
            float c0 = acc[m][n][0] + bi[gl];
            float c1 = acc[m][n][1] + bi[gl + 1];
            float c2 = acc[m][n][2] + bi[gl];
            float c3 = acc[m][n][3] + bi[gl + 1];
            if (res) {
                c0 += res[(size_t)gm*ldc + gn];
                c1 += res[(size_t)gm*ldc + gn + 1];
                c2 += res[(size_t)(gm+8)*ldc + gn];
                c3 += res[(size_t)(gm+8)*ldc + gn + 1];
            }
            *(float2*)&C[(size_t)gm*ldc + gn]     = make_float2(c0, c1);
            *(float2*)&C[(size_t)(gm+8)*ldc + gn] = make_float2(c2, c3);
        }
    }
}

// ---------------------------------------------------------------------------
// Banded attention: block = 128 q's of one (b,h). WIN=7, half=3.
__global__ __launch_bounds__(128)
void attn2(const float* __restrict__ qkv, float* __restrict__ attno,
           float* __restrict__ probs)
{
    extern __shared__ float sh[];
    float* Ks = sh;               // [134][68]
    float* Vs = sh + 134*68;      // [134][68]

    const int t  = threadIdx.x;
    const int q0 = blockIdx.x * 128;
    const int h  = blockIdx.y;
    const int b  = blockIdx.z;

    for (int i = t; i < 134*16; i += 128) {
        int r = i >> 4, d4 = i & 15;
        int row = q0 - 3 + r;
        float4 kv = make_float4(0.f, 0.f, 0.f, 0.f);
        float4 vv = kv;
        if ((unsigned)row < SS) {
            size_t base = (size_t)(b*SS + row)*NQKV + h*64 + d4*4;
            kv = *(const float4*)&qkv[base + 512];
            vv = *(const float4*)&qkv[base + 1024];
        }
        *(float4*)&Ks[r*68 + d4*4] = kv;
        *(float4*)&Vs[r*68 + d4*4] = vv;
    }
    __syncthreads();

    const int q = q0 + t;
    float sc[7] = {0.f,0.f,0.f,0.f,0.f,0.f,0.f};
    const float* Qrow = &qkv[(size_t)(b*SS + q)*NQKV + h*64];

    for (int d4 = 0; d4 < 16; d4++) {
        float4 qv = *(const float4*)&Qrow[d4*4];
        #pragma unroll
        for (int j = 0; j < 7; j++) {
            float4 kk = *(const float4*)&Ks[(t + j)*68 + d4*4];
            sc[j] += qv.x*kk.x + qv.y*kk.y + qv.z*kk.z + qv.w*kk.w;
        }
    }

    float mx = -1e30f;
    #pragma unroll
    for (int j = 0; j < 7; j++) {
        sc[j] *= 0.125f;
        if ((unsigned)(q - 3 + j) < SS) mx = fmaxf(mx, sc[j]);
    }
    float p[7], sum = 0.f;
    #pragma unroll
    for (int j = 0; j < 7; j++) {
        p[j] = ((unsigned)(q - 3 + j) < SS) ? expf(sc[j] - mx) : 0.f;
        sum += p[j];
    }
    float inv = 1.0f / sum;
    #pragma unroll
    for (int j = 0; j < 7; j++) p[j] *= inv;

    float* Orow = &attno[(size_t)(b*SS + q)*DD + h*64];
    for (int d4 = 0; d4 < 16; d4++) {
        float4 o = make_float4(0.f, 0.f, 0.f, 0.f);
        #pragma unroll
        for (int j = 0; j < 7; j++) {
            float4 vv = *(const float4*)&Vs[(t + j)*68 + d4*4];
            o.x += p[j]*vv.x; o.y += p[j]*vv.y; o.z += p[j]*vv.z; o.w += p[j]*vv.w;
        }
        *(float4*)&Orow[d4*4] = o;
    }

    float* prow = &probs[((size_t)(b*HH + h)*SS + q)*8];
    *(float4*)&prow[0] = make_float4(p[0], p[1], p[2], p[3]);
    *(float4*)&prow[4] = make_float4(p[4], p[5], p[6], 0.f);
}

// ---------------------------------------------------------------------------
// Scatter band probs into the zeroed attn output (runs after zero_fill joins).
__global__ __launch_bounds__(256)
void band_write(const float* __restrict__ probs, float* __restrict__ attn_out) {
    int idx = blockIdx.x * blockDim.x + threadIdx.x;   // over BB*HH*SS
    if (idx >= BB*HH*SS) return;
    int q = idx & (SS - 1);
    const float* prow = &probs[(size_t)idx * 8];
    float4 p03 = *(const float4*)&prow[0];
    float4 p46 = *(const float4*)&prow[4];
    float p[7] = {p03.x, p03.y, p03.z, p03.w, p46.x, p46.y, p46.z};
    float* arow = attn_out + (size_t)idx * SS;
    #pragma unroll
    for (int j = 0; j < 7; j++) {
        int k = q - 3 + j;
        if ((unsigned)k < SS) arow[k] = p[j];
    }
}

// ---------------------------------------------------------------------------
// LayerNorm over D=512 per row; 128 threads, float4 each
__global__ __launch_bounds__(128)
void ln2(const float* __restrict__ y0, const float* __restrict__ gw,
         const float* __restrict__ bt, float* __restrict__ out)
{
    const int m = blockIdx.x, t = threadIdx.x;
    float4 v = ((const float4*)(y0 + (size_t)m*DD))[t];
    float s  = v.x + v.y + v.z + v.w;
    float sq = v.x*v.x + v.y*v.y + v.z*v.z + v.w*v.w;
    #pragma unroll
    for (int o = 16; o; o >>= 1) {
        s  += __shfl_xor_sync(0xffffffffu, s,  o);
        sq += __shfl_xor_sync(0xffffffffu, sq, o);
    }
    __shared__ float ss[4], qq[4];
    int w = t >> 5;
    if ((t & 31) == 0) { ss[w] = s; qq[w] = sq; }
    __syncthreads();
    s  = ss[0] + ss[1] + ss[2] + ss[3];
    sq = qq[0] + qq[1] + qq[2] + qq[3];
    float mean = s * (1.0f/DD);
    float var  = sq * (1.0f/DD) - mean*mean;
    float rstd = rsqrtf(var + 1e-5f);
    float4 gg = ((const float4*)gw)[t];
    float4 bb = ((const float4*)bt)[t];
    float4 r;
    r.x = (v.x - mean)*rstd*gg.x + bb.x;
    r.y = (v.y - mean)*rstd*gg.y + bb.y;
    r.z = (v.z - mean)*rstd*gg.z + bb.z;
    r.w = (v.w - mean)*rstd*gg.w + bb.w;
    ((float4*)(out + (size_t)m*DD))[t] = r;
}

// ---------------------------------------------------------------------------
extern "C" void kernel_launch(void* const* d_in, const int* in_sizes, int n_in,
                              void* d_out, int out_size) {
    const float* x    = (const float*)d_in[0];
    const float* wq_w = (const float*)d_in[2];
    const float* wq_b = (const float*)d_in[3];
    const float* wk_w = (const float*)d_in[4];
    const float* wk_b = (const float*)d_in[5];
    const float* wv_w = (const float*)d_in[6];
    const float* wv_b = (const float*)d_in[7];
    const float* wo_w = (const float*)d_in[8];
    const float* wo_b = (const float*)d_in[9];
    const float* ln_g = (const float*)d_in[10];
    const float* ln_b = (const float*)d_in[11];
    const float* pe   = (const float*)d_in[12];

    float* y_out    = (float*)d_out;
    float* attn_out = (float*)d_out + YELEMS;

    static float *p_qkv, *p_attno, *p_y0, *p_probs;
    static cudaStream_t s2;
    static cudaEvent_t evF, evJ;
    static bool init = false;
    if (!init) {
        cudaGetSymbolAddress((void**)&p_qkv,   g_qkv);
        cudaGetSymbolAddress((void**)&p_attno, g_attno);
        cudaGetSymbolAddress((void**)&p_y0,    g_y0);
        cudaGetSymbolAddress((void**)&p_probs, g_probs);
        cudaStreamCreateWithFlags(&s2, cudaStreamNonBlocking);
        cudaEventCreateWithFlags(&evF, cudaEventDisableTiming);
        cudaEventCreateWithFlags(&evJ, cudaEventDisableTiming);
        cudaFuncSetAttribute(attn2, cudaFuncAttributeMaxDynamicSharedMemorySize, ATTN_SMEM);
        init = true;
    }

    // fork: zero the 268MB attn output on a side stream (modest grid so it
    // co-schedules with the compute chain)
    cudaEventRecord(evF, 0);
    cudaStreamWaitEvent(s2, evF, 0);
    zero_fill<<<592, 256, 0, s2>>>((float4*)attn_out, ATTN_ELEMS/4);
    cudaEventRecord(evJ, s2);

    // main chain (overlaps zero_fill):
    // QKV projection (fused x+pe, 3-ptr weight select): 24x64 = 1536 CTAs
    gemm_bf16x3<<<dim3(NQKV/64, MM/64), 128>>>(x, pe, wq_w, wk_w, wv_w,
                                               wq_b, wk_b, wv_b,
                                               nullptr, p_qkv, NQKV);

    // banded attention -> attno + band probs scratch (no attn_out dep)
    attn2<<<dim3(SS/128, HH, BB), 128, ATTN_SMEM>>>(p_qkv, p_attno, p_probs);

    // O projection + residual: 8x64 = 512 CTAs
    gemm_bf16x3<<<dim3(DD/64, MM/64), 128>>>(p_attno, nullptr, wo_w, wo_w, wo_w,
                                             wo_b, wo_b, wo_b,
                                             x, p_y0, DD);

    // LayerNorm
    ln2<<<MM, 128>>>(p_y0, ln_g, ln_b, y_out);

    // join zero_fill, then scatter the band values
    cudaStreamWaitEvent(0, evJ, 0);
    band_write<<<(BB*HH*SS + 255)/256, 256>>>(p_probs, attn_out);
}

// round 9
// speedup vs baseline: 1.4245x; 1.4241x over previous
#include <cuda_runtime.h>
#include <cuda_bf16.h>
#include <cstdint>

#define BB   2
#define SS   2048
#define DD   512
#define HH   8
#define MM   (BB*SS)        // 4096
#define NQKV 1536
#define KK   512
#define YELEMS ((size_t)MM*DD)
#define ATTN_ELEMS ((size_t)BB*HH*SS*SS)
#define ATTN_SMEM (134*68*2*4)

// Frag-packed buffers: A frags = (MM/16)*(KK/16) = 8192, lane uint4 (16B)
// B frags = (2048/8)*(KK/16) = 8192, lane uint2 (8B)
__device__ uint4 g_ah[8192*32], g_al[8192*32];   // x+pe hi/lo, frag-packed
__device__ uint2 g_bh[8192*32], g_bl[8192*32];   // [wq;wk;wv;wo] hi/lo, frag-packed
__device__ uint4 g_oh[8192*32], g_ol[8192*32];   // attn output hi/lo, frag-packed
__device__ float g_qkv[(size_t)MM*NQKV];
__device__ float g_y0[MM*DD];
__device__ float g_probs[(size_t)BB*HH*SS*8];

// ---------------------------------------------------------------------------
__device__ __forceinline__ void packhl(float2 v, uint32_t& h, uint32_t& l) {
    __nv_bfloat162 hb = __floats2bfloat162_rn(v.x, v.y);
    h = *reinterpret_cast<uint32_t*>(&hb);
    float hx = __bfloat162float(hb.x), hy = __bfloat162float(hb.y);
    __nv_bfloat162 lb = __floats2bfloat162_rn(v.x - hx, v.y - hy);
    l = *reinterpret_cast<uint32_t*>(&lb);
}
__device__ __forceinline__ void mma16(float* c, const uint32_t* a, const uint32_t* b) {
    asm volatile(
      "mma.sync.aligned.m16n8k16.row.col.f32.bf16.bf16.f32 "
      "{%0,%1,%2,%3},{%4,%5,%6,%7},{%8,%9},{%0,%1,%2,%3};"
      : "+f"(c[0]), "+f"(c[1]), "+f"(c[2]), "+f"(c[3])
      : "r"(a[0]), "r"(a[1]), "r"(a[2]), "r"(a[3]), "r"(b[0]), "r"(b[1]));
}

// ---------------------------------------------------------------------------
// prep: x+pe -> frag-packed bf16 hi/lo. One thread per (frag, lane).
__global__ __launch_bounds__(256)
void prep_xp(const float* __restrict__ x, const float* __restrict__ pe) {
    int gid = blockIdx.x * 256 + threadIdx.x;   // 8192*32
    if (gid >= 8192*32) return;
    int lane = gid & 31, fa = gid >> 5;
    int kblk = fa & 31, mblk = fa >> 5;
    int g = lane >> 2, tg = lane & 3;
    int r0 = mblk*16 + g, c0 = kblk*16 + tg*2;
    int s0 = r0 & (SS-1), s1 = (r0+8) & (SS-1);
    float2 v0 = *(const float2*)(x + (size_t)r0*KK + c0);
    float2 v1 = *(const float2*)(x + (size_t)(r0+8)*KK + c0);
    float2 v2 = *(const float2*)(x + (size_t)r0*KK + c0 + 8);
    float2 v3 = *(const float2*)(x + (size_t)(r0+8)*KK + c0 + 8);
    float2 e;
    e = *(const float2*)(pe + (size_t)s0*KK + c0);     v0.x += e.x; v0.y += e.y;
    e = *(const float2*)(pe + (size_t)s1*KK + c0);     v1.x += e.x; v1.y += e.y;
    e = *(const float2*)(pe + (size_t)s0*KK + c0 + 8); v2.x += e.x; v2.y += e.y;
    e = *(const float2*)(pe + (size_t)s1*KK + c0 + 8); v3.x += e.x; v3.y += e.y;
    uint4 hv, lv;
    packhl(v0, hv.x, lv.x); packhl(v1, hv.y, lv.y);
    packhl(v2, hv.z, lv.z); packhl(v3, hv.w, lv.w);
    g_ah[gid] = hv; g_al[gid] = lv;
}

// prep: [wq;wk;wv;wo] -> frag-packed bf16 hi/lo
__global__ __launch_bounds__(256)
void prep_w(const float* __restrict__ wq, const float* __restrict__ wk,
            const float* __restrict__ wv, const float* __restrict__ wo) {
    int gid = blockIdx.x * 256 + threadIdx.x;   // 8192*32
    if (gid >= 8192*32) return;
    int lane = gid & 31, fb = gid >> 5;
    int kblk = fb & 31, nblk = fb >> 5;
    int n = nblk*8 + (lane >> 2);
    int c0 = kblk*16 + (lane & 3)*2;
    const float* row = (n < 512)  ? wq + (size_t)n*KK
                     : (n < 1024) ? wk + (size_t)(n-512)*KK
                     : (n < 1536) ? wv + (size_t)(n-1024)*KK
                                  : wo + (size_t)(n-1536)*KK;
    float2 u0 = *(const float2*)(row + c0);
    float2 u1 = *(const float2*)(row + c0 + 8);
    uint2 hv, lv;
    packhl(u0, hv.x, lv.x); packhl(u1, hv.y, lv.y);
    g_bh[gid] = hv; g_bl[gid] = lv;
}

// ---------------------------------------------------------------------------
// bf16x3 GEMM from frag-packed inputs. M-tile = MF*16, N-tile 128, BK=32.
// 256 threads (8 warps), warp tile (MF*4)x64.
template<int MF>
__global__ __launch_bounds__(256, 2)
void gemm_fp(const uint4* __restrict__ Ah, const uint4* __restrict__ Al,
             const uint4* __restrict__ Bh4, const uint4* __restrict__ Bl4,
             int nblk_base,
             const float* __restrict__ bi0, const float* __restrict__ bi1,
             const float* __restrict__ bi2,
             const float* __restrict__ res, float* __restrict__ C, int ldc)
{
    __shared__ uint4 AsH[MF*64], AsL[MF*64];   // MF*2 frags x 32 lanes
    __shared__ uint4 BsH4[512], BsL4[512];     // 32 frags x 16 uint4

    const int t = threadIdx.x, lane = t & 31, w = t >> 5;
    const int g = lane >> 2, tg = lane & 3;
    const int mblk0 = blockIdx.y * MF;
    const int bn = blockIdx.x * 128;
    const int nblk0 = nblk_base + blockIdx.x * 16;
    const int seg = bn >> 9;
    const float* bi = (seg == 0) ? bi0 : (seg == 1) ? bi1 : bi2;
    constexpr int MPW = MF/4;
    const int wmt = (w & 3)*MPW, wnt = (w >> 2)*8;

    float acc[MPW][8][4] = {};

    for (int kb = 0; kb < 32; kb += 2) {
        #pragma unroll
        for (int i = 0; i < MF/4; i++) {
            int s = t + 256*i;
            int sfr = s >> 5, ln = s & 31;
            int mt = sfr >> 1, kt = sfr & 1;
            size_t fa = ((size_t)(mblk0 + mt)*32 + kb + kt)*32 + ln;
            AsH[s] = Ah[fa];
            AsL[s] = Al[fa];
        }
        #pragma unroll
        for (int i = 0; i < 2; i++) {
            int s = t + 256*i;
            int sfr = s >> 4, lp = s & 15;
            int nt = sfr >> 1, kt = sfr & 1;
            size_t fb = ((size_t)(nblk0 + nt)*32 + kb + kt)*16 + lp;
            BsH4[s] = Bh4[fb];
            BsL4[s] = Bl4[fb];
        }
        __syncthreads();
        const uint2* BsH = (const uint2*)BsH4;
        const uint2* BsL = (const uint2*)BsL4;
        #pragma unroll
        for (int kt = 0; kt < 2; kt++) {
            uint4 ah[MPW], al[MPW];
            uint2 bh[8], bl[8];
            #pragma unroll
            for (int m = 0; m < MPW; m++) ah[m] = AsH[((wmt+m)*2 + kt)*32 + lane];
            #pragma unroll
            for (int n = 0; n < 8; n++) bh[n] = BsH[((wnt+n)*2 + kt)*32 + lane];
            #pragma unroll
            for (int m = 0; m < MPW; m++)
                #pragma unroll
                for (int n = 0; n < 8; n++)
                    mma16(acc[m][n], (const uint32_t*)&ah[m], (const uint32_t*)&bh[n]);
            #pragma unroll
            for (int n = 0; n < 8; n++) bl[n] = BsL[((wnt+n)*2 + kt)*32 + lane];
            #pragma unroll
            for (int m = 0; m < MPW; m++)
                #pragma unroll
                for (int n = 0; n < 8; n++)
                    mma16(acc[m][n], (const uint32_t*)&ah[m], (const uint32_t*)&bl[n]);
            #pragma unroll
            for (int m = 0; m < MPW; m++) al[m] = AsL[((wmt+m)*2 + kt)*32 + lane];
            #pragma unroll
            for (int m = 0; m < MPW; m++)
                #pragma unroll
                for (int n = 0; n < 8; n++)
                    mma16(acc[m][n], (const uint32_t*)&al[m], (const uint32_t*)&bh[n]);
        }
        __syncthreads();
    }

    #pragma unroll
    for (int m = 0; m < MPW; m++) {
        const int gm = mblk0*16 + (wmt + m)*16 + g;
        #pragma unroll
        for (int n = 0; n < 8; n++) {
            const int gn = bn + (wnt + n)*8 + tg*2;
            const int gl = gn & 511;
            float c0 = acc[m][n][0] + bi[gl];
            float c1 = acc[m][n][1] + bi[gl + 1];
            float c2 = acc[m][n][2] + bi[gl];
            float c3 = acc[m][n][3] + bi[gl + 1];
            if (res) {
                c0 += res[(size_t)gm*ldc + gn];
                c1 += res[(size_t)gm*ldc + gn + 1];
                c2 += res[(size_t)(gm+8)*ldc + gn];
                c3 += res[(size_t)(gm+8)*ldc + gn + 1];
            }
            *(float2*)&C[(size_t)gm*ldc + gn]     = make_float2(c0, c1);
            *(float2*)&C[(size_t)(gm+8)*ldc + gn] = make_float2(c2, c3);
        }
    }
}

// ---------------------------------------------------------------------------
// frag-packed scatter store of one float2 at (row m, even col c)
__device__ __forceinline__ void st_frag(uint32_t* dH, uint32_t* dL,
                                        int m, int c, float2 v) {
    size_t fa = ((size_t)(m >> 4))*32 + (c >> 4);
    int mr = m & 15, kc = c & 15;
    int lane = (mr & 7)*4 + ((kc & 7) >> 1);
    int comp = ((mr >> 3) & 1) | ((kc >> 3) << 1);
    uint32_t h, l; packhl(v, h, l);
    size_t off = (fa*32 + lane)*4 + comp;
    dH[off] = h; dL[off] = l;
}

// Banded attention: block = 128 q's of one (b,h). Output frag-packed bf16 hi/lo.
__global__ __launch_bounds__(128)
void attn2(const float* __restrict__ qkv, float* __restrict__ probs)
{
    extern __shared__ float sh[];
    float* Ks = sh;               // [134][68]
    float* Vs = sh + 134*68;

    const int t  = threadIdx.x;
    const int q0 = blockIdx.x * 128;
    const int h  = blockIdx.y;
    const int b  = blockIdx.z;

    for (int i = t; i < 134*16; i += 128) {
        int r = i >> 4, d4 = i & 15;
        int row = q0 - 3 + r;
        float4 kv = make_float4(0.f,0.f,0.f,0.f), vv = kv;
        if ((unsigned)row < SS) {
            size_t base = (size_t)(b*SS + row)*NQKV + h*64 + d4*4;
            kv = *(const float4*)&qkv[base + 512];
            vv = *(const float4*)&qkv[base + 1024];
        }
        *(float4*)&Ks[r*68 + d4*4] = kv;
        *(float4*)&Vs[r*68 + d4*4] = vv;
    }
    __syncthreads();

    const int q = q0 + t;
    float sc[7] = {0.f,0.f,0.f,0.f,0.f,0.f,0.f};
    const float* Qrow = &qkv[(size_t)(b*SS + q)*NQKV + h*64];
    for (int d4 = 0; d4 < 16; d4++) {
        float4 qv = *(const float4*)&Qrow[d4*4];
        #pragma unroll
        for (int j = 0; j < 7; j++) {
            float4 kk = *(const float4*)&Ks[(t + j)*68 + d4*4];
            sc[j] += qv.x*kk.x + qv.y*kk.y + qv.z*kk.z + qv.w*kk.w;
        }
    }
    float mx = -1e30f;
    #pragma unroll
    for (int j = 0; j < 7; j++) {
        sc[j] *= 0.125f;
        if ((unsigned)(q - 3 + j) < SS) mx = fmaxf(mx, sc[j]);
    }
    float p[7], sum = 0.f;
    #pragma unroll
    for (int j = 0; j < 7; j++) {
        p[j] = ((unsigned)(q - 3 + j) < SS) ? expf(sc[j] - mx) : 0.f;
        sum += p[j];
    }
    float inv = 1.0f / sum;
    #pragma unroll
    for (int j = 0; j < 7; j++) p[j] *= inv;

    uint32_t* dH = (uint32_t*)g_oh;
    uint32_t* dL = (uint32_t*)g_ol;
    const int m = b*SS + q;
    for (int d4 = 0; d4 < 16; d4++) {
        float4 o = make_float4(0.f,0.f,0.f,0.f);
        #pragma unroll
        for (int j = 0; j < 7; j++) {
            float4 vv = *(const float4*)&Vs[(t + j)*68 + d4*4];
            o.x += p[j]*vv.x; o.y += p[j]*vv.y; o.z += p[j]*vv.z; o.w += p[j]*vv.w;
        }
        int c = h*64 + d4*4;
        st_frag(dH, dL, m, c,     make_float2(o.x, o.y));
        st_frag(dH, dL, m, c + 2, make_float2(o.z, o.w));
    }

    float* prow = &probs[((size_t)(b*HH + h)*SS + q)*8];
    *(float4*)&prow[0] = make_float4(p[0], p[1], p[2], p[3]);
    *(float4*)&prow[4] = make_float4(p[4], p[5], p[6], 0.f);
}

// ---------------------------------------------------------------------------
__global__ __launch_bounds__(256)
void band_write(const float* __restrict__ probs, float* __restrict__ attn_out) {
    int idx = blockIdx.x * blockDim.x + threadIdx.x;
    if (idx >= BB*HH*SS) return;
    int q = idx & (SS - 1);
    const float* prow = &probs[(size_t)idx * 8];
    float4 p03 = *(const float4*)&prow[0];
    float4 p46 = *(const float4*)&prow[4];
    float p[7] = {p03.x, p03.y, p03.z, p03.w, p46.x, p46.y, p46.z};
    float* arow = attn_out + (size_t)idx * SS;
    #pragma unroll
    for (int j = 0; j < 7; j++) {
        int k = q - 3 + j;
        if ((unsigned)k < SS) arow[k] = p[j];
    }
}

// ---------------------------------------------------------------------------
__global__ __launch_bounds__(128)
void ln2(const float* __restrict__ y0, const float* __restrict__ gw,
         const float* __restrict__ bt, float* __restrict__ out)
{
    const int m = blockIdx.x, t = threadIdx.x;
    float4 v = ((const float4*)(y0 + (size_t)m*DD))[t];
    float s  = v.x + v.y + v.z + v.w;
    float sq = v.x*v.x + v.y*v.y + v.z*v.z + v.w*v.w;
    #pragma unroll
    for (int o = 16; o; o >>= 1) {
        s  += __shfl_xor_sync(0xffffffffu, s,  o);
        sq += __shfl_xor_sync(0xffffffffu, sq, o);
    }
    __shared__ float ss[4], qq[4];
    int w = t >> 5;
    if ((t & 31) == 0) { ss[w] = s; qq[w] = sq; }
    __syncthreads();
    s  = ss[0] + ss[1] + ss[2] + ss[3];
    sq = qq[0] + qq[1] + qq[2] + qq[3];
    float mean = s * (1.0f/DD);
    float var  = sq * (1.0f/DD) - mean*mean;
    float rstd = rsqrtf(var + 1e-5f);
    float4 gg = ((const float4*)gw)[t];
    float4 bb = ((const float4*)bt)[t];
    float4 r;
    r.x = (v.x - mean)*rstd*gg.x + bb.x;
    r.y = (v.y - mean)*rstd*gg.y + bb.y;
    r.z = (v.z - mean)*rstd*gg.z + bb.z;
    r.w = (v.w - mean)*rstd*gg.w + bb.w;
    ((float4*)(out + (size_t)m*DD))[t] = r;
}

// ---------------------------------------------------------------------------
extern "C" void kernel_launch(void* const* d_in, const int* in_sizes, int n_in,
                              void* d_out, int out_size) {
    const float* x    = (const float*)d_in[0];
    const float* wq_w = (const float*)d_in[2];
    const float* wq_b = (const float*)d_in[3];
    const float* wk_w = (const float*)d_in[4];
    const float* wk_b = (const float*)d_in[5];
    const float* wv_w = (const float*)d_in[6];
    const float* wv_b = (const float*)d_in[7];
    const float* wo_w = (const float*)d_in[8];
    const float* wo_b = (const float*)d_in[9];
    const float* ln_g = (const float*)d_in[10];
    const float* ln_b = (const float*)d_in[11];
    const float* pe   = (const float*)d_in[12];

    float* y_out    = (float*)d_out;
    float* attn_out = (float*)d_out + YELEMS;

    static uint4 *p_ah, *p_al, *p_oh, *p_ol;
    static uint2 *p_bh, *p_bl;
    static float *p_qkv, *p_y0, *p_probs;
    static cudaStream_t s2;
    static cudaEvent_t evF, evJ;
    static bool init = false;
    if (!init) {
        cudaGetSymbolAddress((void**)&p_ah, g_ah);
        cudaGetSymbolAddress((void**)&p_al, g_al);
        cudaGetSymbolAddress((void**)&p_bh, g_bh);
        cudaGetSymbolAddress((void**)&p_bl, g_bl);
        cudaGetSymbolAddress((void**)&p_oh, g_oh);
        cudaGetSymbolAddress((void**)&p_ol, g_ol);
        cudaGetSymbolAddress((void**)&p_qkv,   g_qkv);
        cudaGetSymbolAddress((void**)&p_y0,    g_y0);
        cudaGetSymbolAddress((void**)&p_probs, g_probs);
        cudaStreamCreateWithFlags(&s2, cudaStreamNonBlocking);
        cudaEventCreateWithFlags(&evF, cudaEventDisableTiming);
        cudaEventCreateWithFlags(&evJ, cudaEventDisableTiming);
        cudaFuncSetAttribute(attn2, cudaFuncAttributeMaxDynamicSharedMemorySize, ATTN_SMEM);
        init = true;
    }

    // fork: zero 268MB attn output via driver memset (overlaps the whole chain)
    cudaEventRecord(evF, 0);
    cudaStreamWaitEvent(s2, evF, 0);
    cudaMemsetAsync(attn_out, 0, ATTN_ELEMS * sizeof(float), s2);
    cudaEventRecord(evJ, s2);

    // prep: convert to frag-packed bf16 hi/lo
    prep_w <<<8192*32/256, 256>>>(wq_w, wk_w, wv_w, wo_w);
    prep_xp<<<8192*32/256, 256>>>(x, pe);

    // QKV projection: [4096,512] x [1536,512]^T
    gemm_fp<8><<<dim3(NQKV/128, MM/128), 256>>>(p_ah, p_al,
        (const uint4*)p_bh, (const uint4*)p_bl, 0,
        wq_b, wk_b, wv_b, nullptr, p_qkv, NQKV);

    // banded attention -> frag-packed oh/ol + band probs
    attn2<<<dim3(SS/128, HH, BB), 128, ATTN_SMEM>>>(p_qkv, p_probs);

    // O projection + residual (M-tile 64 -> 256 CTAs)
    gemm_fp<4><<<dim3(DD/128, MM/64), 256>>>(p_oh, p_ol,
        (const uint4*)p_bh, (const uint4*)p_bl, 192,
        wo_b, wo_b, wo_b, x, p_y0, DD);

    // LayerNorm
    ln2<<<MM, 128>>>(p_y0, ln_g, ln_b, y_out);

    // join memset, then scatter band values
    cudaStreamWaitEvent(0, evJ, 0);
    band_write<<<(BB*HH*SS + 255)/256, 256>>>(p_probs, attn_out);
}

// round 10
// speedup vs baseline: 1.4347x; 1.0072x over previous
#include <cuda_runtime.h>
#include <cuda_bf16.h>
#include <cstdint>

#define BB   2
#define SS   2048
#define DD   512
#define HH   8
#define MM   (BB*SS)        // 4096
#define NQKV 1536
#define KK   512
#define YELEMS ((size_t)MM*DD)
#define ATTN_ELEMS ((size_t)BB*HH*SS*SS)
// K/V tiles + partial-score buffer (2 halves x 128 q x 9 pad)
#define ATTN_SMEM ((134*68*2 + 2*128*9)*4)

// Frag-packed buffers: A frags = (MM/16)*(KK/16) = 8192, lane uint4 (16B)
// B frags = (2048/8)*(KK/16) = 8192, lane uint2 (8B)
__device__ uint4 g_ah[8192*32], g_al[8192*32];   // x+pe hi/lo, frag-packed
__device__ uint2 g_bh[8192*32], g_bl[8192*32];   // [wq;wk;wv;wo] hi/lo, frag-packed
__device__ uint4 g_oh[8192*32], g_ol[8192*32];   // attn output hi/lo, frag-packed
__device__ float g_qkv[(size_t)MM*NQKV];
__device__ float g_y0[MM*DD];
__device__ float g_probs[(size_t)BB*HH*SS*8];

// ---------------------------------------------------------------------------
__device__ __forceinline__ void packhl(float2 v, uint32_t& h, uint32_t& l) {
    __nv_bfloat162 hb = __floats2bfloat162_rn(v.x, v.y);
    h = *reinterpret_cast<uint32_t*>(&hb);
    float hx = __bfloat162float(hb.x), hy = __bfloat162float(hb.y);
    __nv_bfloat162 lb = __floats2bfloat162_rn(v.x - hx, v.y - hy);
    l = *reinterpret_cast<uint32_t*>(&lb);
}
__device__ __forceinline__ void mma16(float* c, const uint32_t* a, const uint32_t* b) {
    asm volatile(
      "mma.sync.aligned.m16n8k16.row.col.f32.bf16.bf16.f32 "
      "{%0,%1,%2,%3},{%4,%5,%6,%7},{%8,%9},{%0,%1,%2,%3};"
      : "+f"(c[0]), "+f"(c[1]), "+f"(c[2]), "+f"(c[3])
      : "r"(a[0]), "r"(a[1]), "r"(a[2]), "r"(a[3]), "r"(b[0]), "r"(b[1]));
}

// ---------------------------------------------------------------------------
// Non-persistent streaming zero-fill: each CTA writes 256*32 float4 = 128KB
// then exits, so CTAs interleave with the compute chain on the other stream.
__global__ __launch_bounds__(256)
void zero_fill(float4* __restrict__ p) {
    const float4 z = make_float4(0.f, 0.f, 0.f, 0.f);
    size_t base = (size_t)blockIdx.x * (256*32) + threadIdx.x;
    #pragma unroll
    for (int i = 0; i < 32; i++) __stcs(&p[base + (size_t)i*256], z);
}

// ---------------------------------------------------------------------------
// prep: x+pe -> frag-packed bf16 hi/lo. One thread per (frag, lane).
__global__ __launch_bounds__(256)
void prep_xp(const float* __restrict__ x, const float* __restrict__ pe) {
    int gid = blockIdx.x * 256 + threadIdx.x;   // 8192*32
    if (gid >= 8192*32) return;
    int lane = gid & 31, fa = gid >> 5;
    int kblk = fa & 31, mblk = fa >> 5;
    int g = lane >> 2, tg = lane & 3;
    int r0 = mblk*16 + g, c0 = kblk*16 + tg*2;
    int s0 = r0 & (SS-1), s1 = (r0+8) & (SS-1);
    float2 v0 = *(const float2*)(x + (size_t)r0*KK + c0);
    float2 v1 = *(const float2*)(x + (size_t)(r0+8)*KK + c0);
    float2 v2 = *(const float2*)(x + (size_t)r0*KK + c0 + 8);
    float2 v3 = *(const float2*)(x + (size_t)(r0+8)*KK + c0 + 8);
    float2 e;
    e = *(const float2*)(pe + (size_t)s0*KK + c0);     v0.x += e.x; v0.y += e.y;
    e = *(const float2*)(pe + (size_t)s1*KK + c0);     v1.x += e.x; v1.y += e.y;
    e = *(const float2*)(pe + (size_t)s0*KK + c0 + 8); v2.x += e.x; v2.y += e.y;
    e = *(const float2*)(pe + (size_t)s1*KK + c0 + 8); v3.x += e.x; v3.y += e.y;
    uint4 hv, lv;
    packhl(v0, hv.x, lv.x); packhl(v1, hv.y, lv.y);
    packhl(v2, hv.z, lv.z); packhl(v3, hv.w, lv.w);
    g_ah[gid] = hv; g_al[gid] = lv;
}

// prep: [wq;wk;wv;wo] -> frag-packed bf16 hi/lo
__global__ __launch_bounds__(256)
void prep_w(const float* __restrict__ wq, const float* __restrict__ wk,
            const float* __restrict__ wv, const float* __restrict__ wo) {
    int gid = blockIdx.x * 256 + threadIdx.x;   // 8192*32
    if (gid >= 8192*32) return;
    int lane = gid & 31, fb = gid >> 5;
    int kblk = fb & 31, nblk = fb >> 5;
    int n = nblk*8 + (lane >> 2);
    int c0 = kblk*16 + (lane & 3)*2;
    const float* row = (n < 512)  ? wq + (size_t)n*KK
                     : (n < 1024) ? wk + (size_t)(n-512)*KK
                     : (n < 1536) ? wv + (size_t)(n-1024)*KK
                                  : wo + (size_t)(n-1536)*KK;
    float2 u0 = *(const float2*)(row + c0);
    float2 u1 = *(const float2*)(row + c0 + 8);
    uint2 hv, lv;
    packhl(u0, hv.x, lv.x); packhl(u1, hv.y, lv.y);
    g_bh[gid] = hv; g_bl[gid] = lv;
}

// ---------------------------------------------------------------------------
// bf16x3 GEMM from frag-packed inputs. M-tile = MF*16, N-tile 128, BK=32.
// 256 threads (8 warps), warp tile (MF*4)x64.
template<int MF>
__global__ __launch_bounds__(256, 2)
void gemm_fp(const uint4* __restrict__ Ah, const uint4* __restrict__ Al,
             const uint4* __restrict__ Bh4, const uint4* __restrict__ Bl4,
             int nblk_base,
             const float* __restrict__ bi0, const float* __restrict__ bi1,
             const float* __restrict__ bi2,
             const float* __restrict__ res, float* __restrict__ C, int ldc)
{
    __shared__ uint4 AsH[MF*64], AsL[MF*64];   // MF*2 frags x 32 lanes
    __shared__ uint4 BsH4[512], BsL4[512];     // 32 frags x 16 uint4

    const int t = threadIdx.x, lane = t & 31, w = t >> 5;
    const int g = lane >> 2, tg = lane & 3;
    const int mblk0 = blockIdx.y * MF;
    const int bn = blockIdx.x * 128;
    const int nblk0 = nblk_base + blockIdx.x * 16;
    const int seg = bn >> 9;
    const float* bi = (seg == 0) ? bi0 : (seg == 1) ? bi1 : bi2;
    constexpr int MPW = MF/4;
    const int wmt = (w & 3)*MPW, wnt = (w >> 2)*8;

    float acc[MPW][8][4] = {};

    for (int kb = 0; kb < 32; kb += 2) {
        #pragma unroll
        for (int i = 0; i < MF/4; i++) {
            int s = t + 256*i;
            int sfr = s >> 5, ln = s & 31;
            int mt = sfr >> 1, kt = sfr & 1;
            size_t fa = ((size_t)(mblk0 + mt)*32 + kb + kt)*32 + ln;
            AsH[s] = Ah[fa];
            AsL[s] = Al[fa];
        }
        #pragma unroll
        for (int i = 0; i < 2; i++) {
            int s = t + 256*i;
            int sfr = s >> 4, lp = s & 15;
            int nt = sfr >> 1, kt = sfr & 1;
            size_t fb = ((size_t)(nblk0 + nt)*32 + kb + kt)*16 + lp;
            BsH4[s] = Bh4[fb];
            BsL4[s] = Bl4[fb];
        }
        __syncthreads();
        const uint2* BsH = (const uint2*)BsH4;
        const uint2* BsL = (const uint2*)BsL4;
        #pragma unroll
        for (int kt = 0; kt < 2; kt++) {
            uint4 ah[MPW], al[MPW];
            uint2 bh[8], bl[8];
            #pragma unroll
            for (int m = 0; m < MPW; m++) ah[m] = AsH[((wmt+m)*2 + kt)*32 + lane];
            #pragma unroll
            for (int n = 0; n < 8; n++) bh[n] = BsH[((wnt+n)*2 + kt)*32 + lane];
            #pragma unroll
            for (int m = 0; m < MPW; m++)
                #pragma unroll
                for (int n = 0; n < 8; n++)
                    mma16(acc[m][n], (const uint32_t*)&ah[m], (const uint32_t*)&bh[n]);
            #pragma unroll
            for (int n = 0; n < 8; n++) bl[n] = BsL[((wnt+n)*2 + kt)*32 + lane];
            #pragma unroll
            for (int m = 0; m < MPW; m++)
                #pragma unroll
                for (int n = 0; n < 8; n++)
                    mma16(acc[m][n], (const uint32_t*)&ah[m], (const uint32_t*)&bl[n]);
            #pragma unroll
            for (int m = 0; m < MPW; m++) al[m] = AsL[((wmt+m)*2 + kt)*32 + lane];
            #pragma unroll
            for (int m = 0; m < MPW; m++)
                #pragma unroll
                for (int n = 0; n < 8; n++)
                    mma16(acc[m][n], (const uint32_t*)&al[m], (const uint32_t*)&bh[n]);
        }
        __syncthreads();
    }

    #pragma unroll
    for (int m = 0; m < MPW; m++) {
        const int gm = mblk0*16 + (wmt + m)*16 + g;
        #pragma unroll
        for (int n = 0; n < 8; n++) {
            const int gn = bn + (wnt + n)*8 + tg*2;
            const int gl = gn & 511;
            float c0 = acc[m][n][0] + bi[gl];
            float c1 = acc[m][n][1] + bi[gl + 1];
            float c2 = acc[m][n][2] + bi[gl];
            float c3 = acc[m][n][3] + bi[gl + 1];
            if (res) {
                c0 += res[(size_t)gm*ldc + gn];
                c1 += res[(size_t)gm*ldc + gn + 1];
                c2 += res[(size_t)(gm+8)*ldc + gn];
                c3 += res[(size_t)(gm+8)*ldc + gn + 1];
            }
            *(float2*)&C[(size_t)gm*ldc + gn]     = make_float2(c0, c1);
            *(float2*)&C[(size_t)(gm+8)*ldc + gn] = make_float2(c2, c3);
        }
    }
}

// ---------------------------------------------------------------------------
// frag-packed scatter store of one float2 at (row m, even col c)
__device__ __forceinline__ void st_frag(uint32_t* dH, uint32_t* dL,
                                        int m, int c, float2 v) {
    size_t fa = ((size_t)(m >> 4))*32 + (c >> 4);
    int mr = m & 15, kc = c & 15;
    int lane = (mr & 7)*4 + ((kc & 7) >> 1);
    int comp = ((mr >> 3) & 1) | ((kc >> 3) << 1);
    uint32_t h, l; packhl(v, h, l);
    size_t off = (fa*32 + lane)*4 + comp;
    dH[off] = h; dL[off] = l;
}

// Banded attention, split-d: block = 128 q's of one (b,h), 256 threads.
// Halves (t>>7) each cover 8 of the 16 d4-chunks; partial scores summed in smem.
__global__ __launch_bounds__(256)
void attn3(const float* __restrict__ qkv, float* __restrict__ probs)
{
    extern __shared__ float sh[];
    float* Ks = sh;                    // [134][68]
    float* Vs = sh + 134*68;           // [134][68]
    float* Pp = sh + 2*134*68;         // [2][128][9] partial scores

    const int t  = threadIdx.x;
    const int tq = t & 127;
    const int half = t >> 7;
    const int q0 = blockIdx.x * 128;
    const int h  = blockIdx.y;
    const int b  = blockIdx.z;

    for (int i = t; i < 134*16; i += 256) {
        int r = i >> 4, d4 = i & 15;
        int row = q0 - 3 + r;
        float4 kv = make_float4(0.f,0.f,0.f,0.f), vv = kv;
        if ((unsigned)row < SS) {
            size_t base = (size_t)(b*SS + row)*NQKV + h*64 + d4*4;
            kv = *(const float4*)&qkv[base + 512];
            vv = *(const float4*)&qkv[base + 1024];
        }
        *(float4*)&Ks[r*68 + d4*4] = kv;
        *(float4*)&Vs[r*68 + d4*4] = vv;
    }
    __syncthreads();

    const int q = q0 + tq;
    const int dbase = half*32;         // this half's 32 dims (8 d4 chunks)
    float sc[7] = {0.f,0.f,0.f,0.f,0.f,0.f,0.f};
    const float* Qrow = &qkv[(size_t)(b*SS + q)*NQKV + h*64 + dbase];
    #pragma unroll
    for (int d4 = 0; d4 < 8; d4++) {
        float4 qv = *(const float4*)&Qrow[d4*4];
        #pragma unroll
        for (int j = 0; j < 7; j++) {
            float4 kk = *(const float4*)&Ks[(tq + j)*68 + dbase + d4*4];
            sc[j] += qv.x*kk.x + qv.y*kk.y + qv.z*kk.z + qv.w*kk.w;
        }
    }
    float* prow_s = &Pp[(half*128 + tq)*9];
    #pragma unroll
    for (int j = 0; j < 7; j++) prow_s[j] = sc[j];
    __syncthreads();
    #pragma unroll
    for (int j = 0; j < 7; j++)
        sc[j] = Pp[tq*9 + j] + Pp[(128 + tq)*9 + j];

    float mx = -1e30f;
    #pragma unroll
    for (int j = 0; j < 7; j++) {
        sc[j] *= 0.125f;
        if ((unsigned)(q - 3 + j) < SS) mx = fmaxf(mx, sc[j]);
    }
    float p[7], sum = 0.f;
    #pragma unroll
    for (int j = 0; j < 7; j++) {
        p[j] = ((unsigned)(q - 3 + j) < SS) ? expf(sc[j] - mx) : 0.f;
        sum += p[j];
    }
    float inv = 1.0f / sum;
    #pragma unroll
    for (int j = 0; j < 7; j++) p[j] *= inv;

    uint32_t* dH = (uint32_t*)g_oh;
    uint32_t* dL = (uint32_t*)g_ol;
    const int m = b*SS + q;
    #pragma unroll
    for (int d4 = 0; d4 < 8; d4++) {
        float4 o = make_float4(0.f,0.f,0.f,0.f);
        #pragma unroll
        for (int j = 0; j < 7; j++) {
            float4 vv = *(const float4*)&Vs[(tq + j)*68 + dbase + d4*4];
            o.x += p[j]*vv.x; o.y += p[j]*vv.y; o.z += p[j]*vv.z; o.w += p[j]*vv.w;
        }
        int c = h*64 + dbase + d4*4;
        st_frag(dH, dL, m, c,     make_float2(o.x, o.y));
        st_frag(dH, dL, m, c + 2, make_float2(o.z, o.w));
    }

    if (half == 0) {
        float* prow = &probs[((size_t)(b*HH + h)*SS + q)*8];
        *(float4*)&prow[0] = make_float4(p[0], p[1], p[2], p[3]);
        *(float4*)&prow[4] = make_float4(p[4], p[5], p[6], 0.f);
    }
}

// ---------------------------------------------------------------------------
__global__ __launch_bounds__(256)
void band_write(const float* __restrict__ probs, float* __restrict__ attn_out) {
    int idx = blockIdx.x * blockDim.x + threadIdx.x;
    if (idx >= BB*HH*SS) return;
    int q = idx & (SS - 1);
    const float* prow = &probs[(size_t)idx * 8];
    float4 p03 = *(const float4*)&prow[0];
    float4 p46 = *(const float4*)&prow[4];
    float p[7] = {p03.x, p03.y, p03.z, p03.w, p46.x, p46.y, p46.z};
    float* arow = attn_out + (size_t)idx * SS;
    #pragma unroll
    for (int j = 0; j < 7; j++) {
        int k = q - 3 + j;
        if ((unsigned)k < SS) arow[k] = p[j];
    }
}

// ---------------------------------------------------------------------------
__global__ __launch_bounds__(128)
void ln2(const float* __restrict__ y0, const float* __restrict__ gw,
         const float* __restrict__ bt, float* __restrict__ out)
{
    const int m = blockIdx.x, t = threadIdx.x;
    float4 v = ((const float4*)(y0 + (size_t)m*DD))[t];
    float s  = v.x + v.y + v.z + v.w;
    float sq = v.x*v.x + v.y*v.y + v.z*v.z + v.w*v.w;
    #pragma unroll
    for (int o = 16; o; o >>= 1) {
        s  += __shfl_xor_sync(0xffffffffu, s,  o);
        sq += __shfl_xor_sync(0xffffffffu, sq, o);
    }
    __shared__ float ss[4], qq[4];
    int w = t >> 5;
    if ((t & 31) == 0) { ss[w] = s; qq[w] = sq; }
    __syncthreads();
    s  = ss[0] + ss[1] + ss[2] + ss[3];
    sq = qq[0] + qq[1] + qq[2] + qq[3];
    float mean = s * (1.0f/DD);
    float var  = sq * (1.0f/DD) - mean*mean;
    float rstd = rsqrtf(var + 1e-5f);
    float4 gg = ((const float4*)gw)[t];
    float4 bb = ((const float4*)bt)[t];
    float4 r;
    r.x = (v.x - mean)*rstd*gg.x + bb.x;
    r.y = (v.y - mean)*rstd*gg.y + bb.y;
    r.z = (v.z - mean)*rstd*gg.z + bb.z;
    r.w = (v.w - mean)*rstd*gg.w + bb.w;
    ((float4*)(out + (size_t)m*DD))[t] = r;
}

// ---------------------------------------------------------------------------
extern "C" void kernel_launch(void* const* d_in, const int* in_sizes, int n_in,
                              void* d_out, int out_size) {
    const float* x    = (const float*)d_in[0];
    const float* wq_w = (const float*)d_in[2];
    const float* wq_b = (const float*)d_in[3];
    const float* wk_w = (const float*)d_in[4];
    const float* wk_b = (const float*)d_in[5];
    const float* wv_w = (const float*)d_in[6];
    const float* wv_b = (const float*)d_in[7];
    const float* wo_w = (const float*)d_in[8];
    const float* wo_b = (const float*)d_in[9];
    const float* ln_g = (const float*)d_in[10];
    const float* ln_b = (const float*)d_in[11];
    const float* pe   = (const float*)d_in[12];

    float* y_out    = (float*)d_out;
    float* attn_out = (float*)d_out + YELEMS;

    static uint4 *p_ah, *p_al, *p_oh, *p_ol;
    static uint2 *p_bh, *p_bl;
    static float *p_qkv, *p_y0, *p_probs;
    static cudaStream_t s2;
    static cudaEvent_t evF, evJ;
    static bool init = false;
    if (!init) {
        cudaGetSymbolAddress((void**)&p_ah, g_ah);
        cudaGetSymbolAddress((void**)&p_al, g_al);
        cudaGetSymbolAddress((void**)&p_bh, g_bh);
        cudaGetSymbolAddress((void**)&p_bl, g_bl);
        cudaGetSymbolAddress((void**)&p_oh, g_oh);
        cudaGetSymbolAddress((void**)&p_ol, g_ol);
        cudaGetSymbolAddress((void**)&p_qkv,   g_qkv);
        cudaGetSymbolAddress((void**)&p_y0,    g_y0);
        cudaGetSymbolAddress((void**)&p_probs, g_probs);
        cudaStreamCreateWithFlags(&s2, cudaStreamNonBlocking);
        cudaEventCreateWithFlags(&evF, cudaEventDisableTiming);
        cudaEventCreateWithFlags(&evJ, cudaEventDisableTiming);
        cudaFuncSetAttribute(attn3, cudaFuncAttributeMaxDynamicSharedMemorySize, ATTN_SMEM);
        init = true;
    }

    // fork: zero the 268MB attn output with short-lived streaming CTAs
    // (ATTN_ELEMS/4 float4s, 8192 per CTA -> 2048 CTAs)
    cudaEventRecord(evF, 0);
    cudaStreamWaitEvent(s2, evF, 0);
    zero_fill<<<2048, 256, 0, s2>>>((float4*)attn_out);
    cudaEventRecord(evJ, s2);

    // prep: convert to frag-packed bf16 hi/lo
    prep_w <<<8192*32/256, 256>>>(wq_w, wk_w, wv_w, wo_w);
    prep_xp<<<8192*32/256, 256>>>(x, pe);

    // QKV projection: [4096,512] x [1536,512]^T
    gemm_fp<8><<<dim3(NQKV/128, MM/128), 256>>>(p_ah, p_al,
        (const uint4*)p_bh, (const uint4*)p_bl, 0,
        wq_b, wk_b, wv_b, nullptr, p_qkv, NQKV);

    // banded attention -> frag-packed oh/ol + band probs
    attn3<<<dim3(SS/128, HH, BB), 256, ATTN_SMEM>>>(p_qkv, p_probs);

    // O projection + residual (M-tile 64 -> 256 CTAs)
    gemm_fp<4><<<dim3(DD/128, MM/64), 256>>>(p_oh, p_ol,
        (const uint4*)p_bh, (const uint4*)p_bl, 192,
        wo_b, wo_b, wo_b, x, p_y0, DD);

    // LayerNorm
    ln2<<<MM, 128>>>(p_y0, ln_g, ln_b, y_out);

    // join zero_fill, then scatter band values
    cudaStreamWaitEvent(0, evJ, 0);
    band_write<<<(BB*HH*SS + 255)/256, 256>>>(p_probs, attn_out);
}

// round 11
// speedup vs baseline: 1.4400x; 1.0037x over previous
#include <cuda_runtime.h>
#include <cuda_bf16.h>
#include <cstdint>

#define BB   2
#define SS   2048
#define DD   512
#define HH   8
#define MM   (BB*SS)        // 4096
#define NQKV 1536
#define KK   512
#define YELEMS ((size_t)MM*DD)
#define ATTN_ELEMS ((size_t)BB*HH*SS*SS)
// K/V tiles + partial-score buffer (2 halves x 128 q x 9 pad)
#define ATTN_SMEM ((134*68*2 + 2*128*9)*4)

// Frag-packed buffers: A frags = (MM/16)*(KK/16) = 8192, lane uint4 (16B)
// B frags = (2048/8)*(KK/16) = 8192, lane uint2 (8B)
__device__ uint4 g_ah[8192*32], g_al[8192*32];   // x+pe hi/lo, frag-packed
__device__ uint2 g_bh[8192*32], g_bl[8192*32];   // [wq;wk;wv;wo] hi/lo, frag-packed
__device__ uint4 g_oh[8192*32], g_ol[8192*32];   // attn output hi/lo, frag-packed
__device__ float g_qkv[(size_t)MM*NQKV];
__device__ float g_y0[MM*DD];
__device__ float g_probs[(size_t)BB*HH*SS*8];

// ---------------------------------------------------------------------------
__device__ __forceinline__ void packhl(float2 v, uint32_t& h, uint32_t& l) {
    __nv_bfloat162 hb = __floats2bfloat162_rn(v.x, v.y);
    h = *reinterpret_cast<uint32_t*>(&hb);
    float hx = __bfloat162float(hb.x), hy = __bfloat162float(hb.y);
    __nv_bfloat162 lb = __floats2bfloat162_rn(v.x - hx, v.y - hy);
    l = *reinterpret_cast<uint32_t*>(&lb);
}
__device__ __forceinline__ void mma16(float* c, const uint32_t* a, const uint32_t* b) {
    asm volatile(
      "mma.sync.aligned.m16n8k16.row.col.f32.bf16.bf16.f32 "
      "{%0,%1,%2,%3},{%4,%5,%6,%7},{%8,%9},{%0,%1,%2,%3};"
      : "+f"(c[0]), "+f"(c[1]), "+f"(c[2]), "+f"(c[3])
      : "r"(a[0]), "r"(a[1]), "r"(a[2]), "r"(a[3]), "r"(b[0]), "r"(b[1]));
}

// ---------------------------------------------------------------------------
// Non-persistent streaming zero-fill: each CTA writes 256*32 float4 = 128KB
// then exits, so CTAs interleave with the compute chain on the other stream.
__global__ __launch_bounds__(256)
void zero_fill(float4* __restrict__ p) {
    const float4 z = make_float4(0.f, 0.f, 0.f, 0.f);
    size_t base = (size_t)blockIdx.x * (256*32) + threadIdx.x;
    #pragma unroll
    for (int i = 0; i < 32; i++) __stcs(&p[base + (size_t)i*256], z);
}

// ---------------------------------------------------------------------------
// prep: x+pe -> frag-packed bf16 hi/lo. One thread per (frag, lane).
__global__ __launch_bounds__(256)
void prep_xp(const float* __restrict__ x, const float* __restrict__ pe) {
    int gid = blockIdx.x * 256 + threadIdx.x;   // 8192*32
    if (gid >= 8192*32) return;
    int lane = gid & 31, fa = gid >> 5;
    int kblk = fa & 31, mblk = fa >> 5;
    int g = lane >> 2, tg = lane & 3;
    int r0 = mblk*16 + g, c0 = kblk*16 + tg*2;
    int s0 = r0 & (SS-1), s1 = (r0+8) & (SS-1);
    float2 v0 = *(const float2*)(x + (size_t)r0*KK + c0);
    float2 v1 = *(const float2*)(x + (size_t)(r0+8)*KK + c0);
    float2 v2 = *(const float2*)(x + (size_t)r0*KK + c0 + 8);
    float2 v3 = *(const float2*)(x + (size_t)(r0+8)*KK + c0 + 8);
    float2 e;
    e = *(const float2*)(pe + (size_t)s0*KK + c0);     v0.x += e.x; v0.y += e.y;
    e = *(const float2*)(pe + (size_t)s1*KK + c0);     v1.x += e.x; v1.y += e.y;
    e = *(const float2*)(pe + (size_t)s0*KK + c0 + 8); v2.x += e.x; v2.y += e.y;
    e = *(const float2*)(pe + (size_t)s1*KK + c0 + 8); v3.x += e.x; v3.y += e.y;
    uint4 hv, lv;
    packhl(v0, hv.x, lv.x); packhl(v1, hv.y, lv.y);
    packhl(v2, hv.z, lv.z); packhl(v3, hv.w, lv.w);
    g_ah[gid] = hv; g_al[gid] = lv;
}

// prep: [wq;wk;wv;wo] -> frag-packed bf16 hi/lo
__global__ __launch_bounds__(256)
void prep_w(const float* __restrict__ wq, const float* __restrict__ wk,
            const float* __restrict__ wv, const float* __restrict__ wo) {
    int gid = blockIdx.x * 256 + threadIdx.x;   // 8192*32
    if (gid >= 8192*32) return;
    int lane = gid & 31, fb = gid >> 5;
    int kblk = fb & 31, nblk = fb >> 5;
    int n = nblk*8 + (lane >> 2);
    int c0 = kblk*16 + (lane & 3)*2;
    const float* row = (n < 512)  ? wq + (size_t)n*KK
                     : (n < 1024) ? wk + (size_t)(n-512)*KK
                     : (n < 1536) ? wv + (size_t)(n-1024)*KK
                                  : wo + (size_t)(n-1536)*KK;
    float2 u0 = *(const float2*)(row + c0);
    float2 u1 = *(const float2*)(row + c0 + 8);
    uint2 hv, lv;
    packhl(u0, hv.x, lv.x); packhl(u1, hv.y, lv.y);
    g_bh[gid] = hv; g_bl[gid] = lv;
}

// ---------------------------------------------------------------------------
// bf16x3 GEMM from frag-packed inputs. M-tile = MF*16, N-tile 128, BK=32.
// 256 threads (8 warps), warp tile (MF*4)x64.
template<int MF>
__global__ __launch_bounds__(256, 2)
void gemm_fp(const uint4* __restrict__ Ah, const uint4* __restrict__ Al,
             const uint4* __restrict__ Bh4, const uint4* __restrict__ Bl4,
             int nblk_base,
             const float* __restrict__ bi0, const float* __restrict__ bi1,
             const float* __restrict__ bi2,
             const float* __restrict__ res, float* __restrict__ C, int ldc)
{
    __shared__ uint4 AsH[MF*64], AsL[MF*64];   // MF*2 frags x 32 lanes
    __shared__ uint4 BsH4[512], BsL4[512];     // 32 frags x 16 uint4

    const int t = threadIdx.x, lane = t & 31, w = t >> 5;
    const int g = lane >> 2, tg = lane & 3;
    const int mblk0 = blockIdx.y * MF;
    const int bn = blockIdx.x * 128;
    const int nblk0 = nblk_base + blockIdx.x * 16;
    const int seg = bn >> 9;
    const float* bi = (seg == 0) ? bi0 : (seg == 1) ? bi1 : bi2;
    constexpr int MPW = MF/4;
    const int wmt = (w & 3)*MPW, wnt = (w >> 2)*8;

    float acc[MPW][8][4] = {};

    for (int kb = 0; kb < 32; kb += 2) {
        #pragma unroll
        for (int i = 0; i < MF/4; i++) {
            int s = t + 256*i;
            int sfr = s >> 5, ln = s & 31;
            int mt = sfr >> 1, kt = sfr & 1;
            size_t fa = ((size_t)(mblk0 + mt)*32 + kb + kt)*32 + ln;
            AsH[s] = Ah[fa];
            AsL[s] = Al[fa];
        }
        #pragma unroll
        for (int i = 0; i < 2; i++) {
            int s = t + 256*i;
            int sfr = s >> 4, lp = s & 15;
            int nt = sfr >> 1, kt = sfr & 1;
            size_t fb = ((size_t)(nblk0 + nt)*32 + kb + kt)*16 + lp;
            BsH4[s] = Bh4[fb];
            BsL4[s] = Bl4[fb];
        }
        __syncthreads();
        const uint2* BsH = (const uint2*)BsH4;
        const uint2* BsL = (const uint2*)BsL4;
        #pragma unroll
        for (int kt = 0; kt < 2; kt++) {
            uint4 ah[MPW], al[MPW];
            uint2 bh[8], bl[8];
            #pragma unroll
            for (int m = 0; m < MPW; m++) ah[m] = AsH[((wmt+m)*2 + kt)*32 + lane];
            #pragma unroll
            for (int n = 0; n < 8; n++) bh[n] = BsH[((wnt+n)*2 + kt)*32 + lane];
            #pragma unroll
            for (int m = 0; m < MPW; m++)
                #pragma unroll
                for (int n = 0; n < 8; n++)
                    mma16(acc[m][n], (const uint32_t*)&ah[m], (const uint32_t*)&bh[n]);
            #pragma unroll
            for (int n = 0; n < 8; n++) bl[n] = BsL[((wnt+n)*2 + kt)*32 + lane];
            #pragma unroll
            for (int m = 0; m < MPW; m++)
                #pragma unroll
                for (int n = 0; n < 8; n++)
                    mma16(acc[m][n], (const uint32_t*)&ah[m], (const uint32_t*)&bl[n]);
            #pragma unroll
            for (int m = 0; m < MPW; m++) al[m] = AsL[((wmt+m)*2 + kt)*32 + lane];
            #pragma unroll
            for (int m = 0; m < MPW; m++)
                #pragma unroll
                for (int n = 0; n < 8; n++)
                    mma16(acc[m][n], (const uint32_t*)&al[m], (const uint32_t*)&bh[n]);
        }
        __syncthreads();
    }

    #pragma unroll
    for (int m = 0; m < MPW; m++) {
        const int gm = mblk0*16 + (wmt + m)*16 + g;
        #pragma unroll
        for (int n = 0; n < 8; n++) {
            const int gn = bn + (wnt + n)*8 + tg*2;
            const int gl = gn & 511;
            float c0 = acc[m][n][0] + bi[gl];
            float c1 = acc[m][n][1] + bi[gl + 1];
            float c2 = acc[m][n][2] + bi[gl];
            float c3 = acc[m][n][3] + bi[gl + 1];
            if (res) {
                c0 += res[(size_t)gm*ldc + gn];
                c1 += res[(size_t)gm*ldc + gn + 1];
                c2 += res[(size_t)(gm+8)*ldc + gn];
                c3 += res[(size_t)(gm+8)*ldc + gn + 1];
            }
            *(float2*)&C[(size_t)gm*ldc + gn]     = make_float2(c0, c1);
            *(float2*)&C[(size_t)(gm+8)*ldc + gn] = make_float2(c2, c3);
        }
    }
}

// ---------------------------------------------------------------------------
// frag-packed scatter store of one float2 at (row m, even col c)
__device__ __forceinline__ void st_frag(uint32_t* dH, uint32_t* dL,
                                        int m, int c, float2 v) {
    size_t fa = ((size_t)(m >> 4))*32 + (c >> 4);
    int mr = m & 15, kc = c & 15;
    int lane = (mr & 7)*4 + ((kc & 7) >> 1);
    int comp = ((mr >> 3) & 1) | ((kc >> 3) << 1);
    uint32_t h, l; packhl(v, h, l);
    size_t off = (fa*32 + lane)*4 + comp;
    dH[off] = h; dL[off] = l;
}

// Banded attention, split-d: block = 128 q's of one (b,h), 256 threads.
// Halves (t>>7) each cover 8 of the 16 d4-chunks; partial scores summed in smem.
__global__ __launch_bounds__(256)
void attn3(const float* __restrict__ qkv, float* __restrict__ probs)
{
    extern __shared__ float sh[];
    float* Ks = sh;                    // [134][68]
    float* Vs = sh + 134*68;           // [134][68]
    float* Pp = sh + 2*134*68;         // [2][128][9] partial scores

    const int t  = threadIdx.x;
    const int tq = t & 127;
    const int half = t >> 7;
    const int q0 = blockIdx.x * 128;
    const int h  = blockIdx.y;
    const int b  = blockIdx.z;

    for (int i = t; i < 134*16; i += 256) {
        int r = i >> 4, d4 = i & 15;
        int row = q0 - 3 + r;
        float4 kv = make_float4(0.f,0.f,0.f,0.f), vv = kv;
        if ((unsigned)row < SS) {
            size_t base = (size_t)(b*SS + row)*NQKV + h*64 + d4*4;
            kv = *(const float4*)&qkv[base + 512];
            vv = *(const float4*)&qkv[base + 1024];
        }
        *(float4*)&Ks[r*68 + d4*4] = kv;
        *(float4*)&Vs[r*68 + d4*4] = vv;
    }
    __syncthreads();

    const int q = q0 + tq;
    const int dbase = half*32;         // this half's 32 dims (8 d4 chunks)
    float sc[7] = {0.f,0.f,0.f,0.f,0.f,0.f,0.f};
    const float* Qrow = &qkv[(size_t)(b*SS + q)*NQKV + h*64 + dbase];
    #pragma unroll
    for (int d4 = 0; d4 < 8; d4++) {
        float4 qv = *(const float4*)&Qrow[d4*4];
        #pragma unroll
        for (int j = 0; j < 7; j++) {
            float4 kk = *(const float4*)&Ks[(tq + j)*68 + dbase + d4*4];
            sc[j] += qv.x*kk.x + qv.y*kk.y + qv.z*kk.z + qv.w*kk.w;
        }
    }
    float* prow_s = &Pp[(half*128 + tq)*9];
    #pragma unroll
    for (int j = 0; j < 7; j++) prow_s[j] = sc[j];
    __syncthreads();
    #pragma unroll
    for (int j = 0; j < 7; j++)
        sc[j] = Pp[tq*9 + j] + Pp[(128 + tq)*9 + j];

    float mx = -1e30f;
    #pragma unroll
    for (int j = 0; j < 7; j++) {
        sc[j] *= 0.125f;
        if ((unsigned)(q - 3 + j) < SS) mx = fmaxf(mx, sc[j]);
    }
    float p[7], sum = 0.f;
    #pragma unroll
    for (int j = 0; j < 7; j++) {
        p[j] = ((unsigned)(q - 3 + j) < SS) ? expf(sc[j] - mx) : 0.f;
        sum += p[j];
    }
    float inv = 1.0f / sum;
    #pragma unroll
    for (int j = 0; j < 7; j++) p[j] *= inv;

    uint32_t* dH = (uint32_t*)g_oh;
    uint32_t* dL = (uint32_t*)g_ol;
    const int m = b*SS + q;
    #pragma unroll
    for (int d4 = 0; d4 < 8; d4++) {
        float4 o = make_float4(0.f,0.f,0.f,0.f);
        #pragma unroll
        for (int j = 0; j < 7; j++) {
            float4 vv = *(const float4*)&Vs[(tq + j)*68 + dbase + d4*4];
            o.x += p[j]*vv.x; o.y += p[j]*vv.y; o.z += p[j]*vv.z; o.w += p[j]*vv.w;
        }
        int c = h*64 + dbase + d4*4;
        st_frag(dH, dL, m, c,     make_float2(o.x, o.y));
        st_frag(dH, dL, m, c + 2, make_float2(o.z, o.w));
    }

    if (half == 0) {
        float* prow = &probs[((size_t)(b*HH + h)*SS + q)*8];
        *(float4*)&prow[0] = make_float4(p[0], p[1], p[2], p[3]);
        *(float4*)&prow[4] = make_float4(p[4], p[5], p[6], 0.f);
    }
}

// ---------------------------------------------------------------------------
__global__ __launch_bounds__(256)
void band_write(const float* __restrict__ probs, float* __restrict__ attn_out) {
    int idx = blockIdx.x * blockDim.x + threadIdx.x;
    if (idx >= BB*HH*SS) return;
    int q = idx & (SS - 1);
    const float* prow = &probs[(size_t)idx * 8];
    float4 p03 = *(const float4*)&prow[0];
    float4 p46 = *(const float4*)&prow[4];
    float p[7] = {p03.x, p03.y, p03.z, p03.w, p46.x, p46.y, p46.z};
    float* arow = attn_out + (size_t)idx * SS;
    #pragma unroll
    for (int j = 0; j < 7; j++) {
        int k = q - 3 + j;
        if ((unsigned)k < SS) arow[k] = p[j];
    }
}

// ---------------------------------------------------------------------------
__global__ __launch_bounds__(128)
void ln2(const float* __restrict__ y0, const float* __restrict__ gw,
         const float* __restrict__ bt, float* __restrict__ out)
{
    const int m = blockIdx.x, t = threadIdx.x;
    float4 v = ((const float4*)(y0 + (size_t)m*DD))[t];
    float s  = v.x + v.y + v.z + v.w;
    float sq = v.x*v.x + v.y*v.y + v.z*v.z + v.w*v.w;
    #pragma unroll
    for (int o = 16; o; o >>= 1) {
        s  += __shfl_xor_sync(0xffffffffu, s,  o);
        sq += __shfl_xor_sync(0xffffffffu, sq, o);
    }
    __shared__ float ss[4], qq[4];
    int w = t >> 5;
    if ((t & 31) == 0) { ss[w] = s; qq[w] = sq; }
    __syncthreads();
    s  = ss[0] + ss[1] + ss[2] + ss[3];
    sq = qq[0] + qq[1] + qq[2] + qq[3];
    float mean = s * (1.0f/DD);
    float var  = sq * (1.0f/DD) - mean*mean;
    float rstd = rsqrtf(var + 1e-5f);
    float4 gg = ((const float4*)gw)[t];
    float4 bb = ((const float4*)bt)[t];
    float4 r;
    r.x = (v.x - mean)*rstd*gg.x + bb.x;
    r.y = (v.y - mean)*rstd*gg.y + bb.y;
    r.z = (v.z - mean)*rstd*gg.z + bb.z;
    r.w = (v.w - mean)*rstd*gg.w + bb.w;
    ((float4*)(out + (size_t)m*DD))[t] = r;
}

// ---------------------------------------------------------------------------
extern "C" void kernel_launch(void* const* d_in, const int* in_sizes, int n_in,
                              void* d_out, int out_size) {
    const float* x    = (const float*)d_in[0];
    const float* wq_w = (const float*)d_in[2];
    const float* wq_b = (const float*)d_in[3];
    const float* wk_w = (const float*)d_in[4];
    const float* wk_b = (const float*)d_in[5];
    const float* wv_w = (const float*)d_in[6];
    const float* wv_b = (const float*)d_in[7];
    const float* wo_w = (const float*)d_in[8];
    const float* wo_b = (const float*)d_in[9];
    const float* ln_g = (const float*)d_in[10];
    const float* ln_b = (const float*)d_in[11];
    const float* pe   = (const float*)d_in[12];

    float* y_out    = (float*)d_out;
    float* attn_out = (float*)d_out + YELEMS;

    static uint4 *p_ah, *p_al, *p_oh, *p_ol;
    static uint2 *p_bh, *p_bl;
    static float *p_qkv, *p_y0, *p_probs;
    static cudaStream_t s2;
    static cudaEvent_t evF, evJ;
    static bool init = false;
    if (!init) {
        cudaGetSymbolAddress((void**)&p_ah, g_ah);
        cudaGetSymbolAddress((void**)&p_al, g_al);
        cudaGetSymbolAddress((void**)&p_bh, g_bh);
        cudaGetSymbolAddress((void**)&p_bl, g_bl);
        cudaGetSymbolAddress((void**)&p_oh, g_oh);
        cudaGetSymbolAddress((void**)&p_ol, g_ol);
        cudaGetSymbolAddress((void**)&p_qkv,   g_qkv);
        cudaGetSymbolAddress((void**)&p_y0,    g_y0);
        cudaGetSymbolAddress((void**)&p_probs, g_probs);
        cudaStreamCreateWithFlags(&s2, cudaStreamNonBlocking);
        cudaEventCreateWithFlags(&evF, cudaEventDisableTiming);
        cudaEventCreateWithFlags(&evJ, cudaEventDisableTiming);
        cudaFuncSetAttribute(attn3, cudaFuncAttributeMaxDynamicSharedMemorySize, ATTN_SMEM);
        init = true;
    }

    // fork: zero the 268MB attn output with short-lived streaming CTAs
    // (ATTN_ELEMS/4 float4s, 8192 per CTA -> 2048 CTAs)
    cudaEventRecord(evF, 0);
    cudaStreamWaitEvent(s2, evF, 0);
    zero_fill<<<2048, 256, 0, s2>>>((float4*)attn_out);
    cudaEventRecord(evJ, s2);

    // prep: convert to frag-packed bf16 hi/lo
    prep_w <<<8192*32/256, 256>>>(wq_w, wk_w, wv_w, wo_w);
    prep_xp<<<8192*32/256, 256>>>(x, pe);

    // QKV projection: [4096,512] x [1536,512]^T
    gemm_fp<8><<<dim3(NQKV/128, MM/128), 256>>>(p_ah, p_al,
        (const uint4*)p_bh, (const uint4*)p_bl, 0,
        wq_b, wk_b, wv_b, nullptr, p_qkv, NQKV);

    // banded attention -> frag-packed oh/ol + band probs
    attn3<<<dim3(SS/128, HH, BB), 256, ATTN_SMEM>>>(p_qkv, p_probs);

    // O projection + residual (M-tile 64 -> 256 CTAs)
    gemm_fp<4><<<dim3(DD/128, MM/64), 256>>>(p_oh, p_ol,
        (const uint4*)p_bh, (const uint4*)p_bl, 192,
        wo_b, wo_b, wo_b, x, p_y0, DD);

    // LayerNorm
    ln2<<<MM, 128>>>(p_y0, ln_g, ln_b, y_out);

    // join zero_fill, then scatter band values
    cudaStreamWaitEvent(0, evJ, 0);
    band_write<<<(BB*HH*SS + 255)/256, 256>>>(p_probs, attn_out);
}

// round 12
// speedup vs baseline: 1.6007x; 1.1116x over previous
#include <cuda_runtime.h>
#include <cuda_bf16.h>
#include <cstdint>

#define BB   2
#define SS   2048
#define DD   512
#define HH   8
#define MM   (BB*SS)        // 4096
#define NQKV 1536
#define KK   512
#define YELEMS ((size_t)MM*DD)
#define ATTN_ELEMS ((size_t)BB*HH*SS*SS)
// K/V tiles + partial-score buffer (2 halves x 128 q x 9 pad)
#define ATTN_SMEM ((134*68*2 + 2*128*9)*4)

// Frag-packed buffers
__device__ uint4 g_ah[8192*32], g_al[8192*32];   // x+pe hi/lo, frag-packed
__device__ uint2 g_bh[8192*32], g_bl[8192*32];   // [wq;wk;wv;wo] hi/lo, frag-packed
__device__ uint4 g_oh[8192*32], g_ol[8192*32];   // attn output hi/lo, frag-packed
__device__ float g_qkv[(size_t)MM*NQKV];
__device__ float g_y0[MM*DD];
__device__ float g_probs[(size_t)BB*HH*SS*8];

// ---------------------------------------------------------------------------
__device__ __forceinline__ void packhl(float2 v, uint32_t& h, uint32_t& l) {
    __nv_bfloat162 hb = __floats2bfloat162_rn(v.x, v.y);
    h = *reinterpret_cast<uint32_t*>(&hb);
    float hx = __bfloat162float(hb.x), hy = __bfloat162float(hb.y);
    __nv_bfloat162 lb = __floats2bfloat162_rn(v.x - hx, v.y - hy);
    l = *reinterpret_cast<uint32_t*>(&lb);
}
__device__ __forceinline__ void mma16(float* c, const uint32_t* a, const uint32_t* b) {
    asm volatile(
      "mma.sync.aligned.m16n8k16.row.col.f32.bf16.bf16.f32 "
      "{%0,%1,%2,%3},{%4,%5,%6,%7},{%8,%9},{%0,%1,%2,%3};"
      : "+f"(c[0]), "+f"(c[1]), "+f"(c[2]), "+f"(c[3])
      : "r"(a[0]), "r"(a[1]), "r"(a[2]), "r"(a[3]), "r"(b[0]), "r"(b[1]));
}
__device__ __forceinline__ uint32_t smem_u32(const void* p) {
    uint32_t a;
    asm("{ .reg .u64 t; cvta.to.shared.u64 t, %1; cvt.u32.u64 %0, t; }" : "=r"(a) : "l"(p));
    return a;
}
__device__ __forceinline__ void cp16(uint32_t dst, const void* src) {
    asm volatile("cp.async.cg.shared.global [%0], [%1], 16;" :: "r"(dst), "l"(src));
}

// ---------------------------------------------------------------------------
// Non-persistent streaming zero-fill (128KB per CTA, then exit).
__global__ __launch_bounds__(256)
void zero_fill(float4* __restrict__ p) {
    const float4 z = make_float4(0.f, 0.f, 0.f, 0.f);
    size_t base = (size_t)blockIdx.x * (256*32) + threadIdx.x;
    #pragma unroll
    for (int i = 0; i < 32; i++) __stcs(&p[base + (size_t)i*256], z);
}

// ---------------------------------------------------------------------------
// prep: x+pe -> frag-packed bf16 hi/lo
__global__ __launch_bounds__(256)
void prep_xp(const float* __restrict__ x, const float* __restrict__ pe) {
    int gid = blockIdx.x * 256 + threadIdx.x;   // 8192*32
    if (gid >= 8192*32) return;
    int lane = gid & 31, fa = gid >> 5;
    int kblk = fa & 31, mblk = fa >> 5;
    int g = lane >> 2, tg = lane & 3;
    int r0 = mblk*16 + g, c0 = kblk*16 + tg*2;
    int s0 = r0 & (SS-1), s1 = (r0+8) & (SS-1);
    float2 v0 = *(const float2*)(x + (size_t)r0*KK + c0);
    float2 v1 = *(const float2*)(x + (size_t)(r0+8)*KK + c0);
    float2 v2 = *(const float2*)(x + (size_t)r0*KK + c0 + 8);
    float2 v3 = *(const float2*)(x + (size_t)(r0+8)*KK + c0 + 8);
    float2 e;
    e = *(const float2*)(pe + (size_t)s0*KK + c0);     v0.x += e.x; v0.y += e.y;
    e = *(const float2*)(pe + (size_t)s1*KK + c0);     v1.x += e.x; v1.y += e.y;
    e = *(const float2*)(pe + (size_t)s0*KK + c0 + 8); v2.x += e.x; v2.y += e.y;
    e = *(const float2*)(pe + (size_t)s1*KK + c0 + 8); v3.x += e.x; v3.y += e.y;
    uint4 hv, lv;
    packhl(v0, hv.x, lv.x); packhl(v1, hv.y, lv.y);
    packhl(v2, hv.z, lv.z); packhl(v3, hv.w, lv.w);
    g_ah[gid] = hv; g_al[gid] = lv;
}

// prep: [wq;wk;wv;wo] -> frag-packed bf16 hi/lo
__global__ __launch_bounds__(256)
void prep_w(const float* __restrict__ wq, const float* __restrict__ wk,
            const float* __restrict__ wv, const float* __restrict__ wo) {
    int gid = blockIdx.x * 256 + threadIdx.x;   // 8192*32
    if (gid >= 8192*32) return;
    int lane = gid & 31, fb = gid >> 5;
    int kblk = fb & 31, nblk = fb >> 5;
    int n = nblk*8 + (lane >> 2);
    int c0 = kblk*16 + (lane & 3)*2;
    const float* row = (n < 512)  ? wq + (size_t)n*KK
                     : (n < 1024) ? wk + (size_t)(n-512)*KK
                     : (n < 1536) ? wv + (size_t)(n-1024)*KK
                                  : wo + (size_t)(n-1536)*KK;
    float2 u0 = *(const float2*)(row + c0);
    float2 u1 = *(const float2*)(row + c0 + 8);
    uint2 hv, lv;
    packhl(u0, hv.x, lv.x); packhl(u1, hv.y, lv.y);
    g_bh[gid] = hv; g_bl[gid] = lv;
}

// ---------------------------------------------------------------------------
// bf16x3 GEMM, frag-packed inputs, cp.async double-buffered pipeline.
// M-tile = MF*16, N-tile 128, BK=32. 256 threads (8 warps), warp (MF*4)x64.
// Stage layout (bytes): [AH: MF*1024][AL: MF*1024][BH: 8192][BL: 8192]
template<int MF>
__global__ __launch_bounds__(256, 2)
void gemm_cp(const uint4* __restrict__ Ah, const uint4* __restrict__ Al,
             const uint4* __restrict__ Bh4, const uint4* __restrict__ Bl4,
             int nblk_base,
             const float* __restrict__ bi0, const float* __restrict__ bi1,
             const float* __restrict__ bi2,
             const float* __restrict__ res, float* __restrict__ C, int ldc)
{
    extern __shared__ __align__(16) char smem[];
    constexpr int A_BYTES = MF*64*16;          // MF*1024
    constexpr int STAGE   = 2*A_BYTES + 16384;
    const uint32_t sb = smem_u32(smem);

    const int t = threadIdx.x, lane = t & 31, w = t >> 5;
    const int g = lane >> 2, tg = lane & 3;
    const int mblk0 = blockIdx.y * MF;
    const int bn = blockIdx.x * 128;
    const int nblk0 = nblk_base + blockIdx.x * 16;
    const int seg = bn >> 9;
    const float* bi = (seg == 0) ? bi0 : (seg == 1) ? bi1 : bi2;
    constexpr int MPW = MF/4;
    const int wmt = (w & 3)*MPW, wnt = (w >> 2)*8;

    float acc[MPW][8][4] = {};

    auto issue = [&](int kb, int buf) {
        const uint32_t st = sb + buf*STAGE;
        #pragma unroll
        for (int i = 0; i < MF/4; i++) {
            int s = t + 256*i;
            int sfr = s >> 5, ln = s & 31;
            int mt = sfr >> 1, kt = sfr & 1;
            size_t fa = ((size_t)(mblk0 + mt)*32 + kb + kt)*32 + ln;
            cp16(st + s*16,           Ah + fa);
            cp16(st + A_BYTES + s*16, Al + fa);
        }
        #pragma unroll
        for (int i = 0; i < 2; i++) {
            int s = t + 256*i;
            int sfr = s >> 4, lp = s & 15;
            int nt = sfr >> 1, kt = sfr & 1;
            size_t fb = ((size_t)(nblk0 + nt)*32 + kb + kt)*16 + lp;
            cp16(st + 2*A_BYTES + s*16,        Bh4 + fb);
            cp16(st + 2*A_BYTES + 8192 + s*16, Bl4 + fb);
        }
        asm volatile("cp.async.commit_group;");
    };

    issue(0, 0);
    for (int s = 0; s < 16; s++) {
        if (s + 1 < 16) {
            issue((s + 1)*2, (s + 1) & 1);
            asm volatile("cp.async.wait_group 1;");
        } else {
            asm volatile("cp.async.wait_group 0;");
        }
        __syncthreads();

        const char* stg = smem + (s & 1)*STAGE;
        const uint4* AsH = (const uint4*)stg;
        const uint4* AsL = (const uint4*)(stg + A_BYTES);
        const uint2* BsH = (const uint2*)(stg + 2*A_BYTES);
        const uint2* BsL = (const uint2*)(stg + 2*A_BYTES + 8192);

        #pragma unroll
        for (int kt = 0; kt < 2; kt++) {
            uint4 ah[MPW], al[MPW];
            uint2 bh[8], bl[8];
            #pragma unroll
            for (int m = 0; m < MPW; m++) ah[m] = AsH[((wmt+m)*2 + kt)*32 + lane];
            #pragma unroll
            for (int n = 0; n < 8; n++) bh[n] = BsH[((wnt+n)*2 + kt)*32 + lane];
            #pragma unroll
            for (int m = 0; m < MPW; m++)
                #pragma unroll
                for (int n = 0; n < 8; n++)
                    mma16(acc[m][n], (const uint32_t*)&ah[m], (const uint32_t*)&bh[n]);
            #pragma unroll
            for (int n = 0; n < 8; n++) bl[n] = BsL[((wnt+n)*2 + kt)*32 + lane];
            #pragma unroll
            for (int m = 0; m < MPW; m++)
                #pragma unroll
                for (int n = 0; n < 8; n++)
                    mma16(acc[m][n], (const uint32_t*)&ah[m], (const uint32_t*)&bl[n]);
            #pragma unroll
            for (int m = 0; m < MPW; m++) al[m] = AsL[((wmt+m)*2 + kt)*32 + lane];
            #pragma unroll
            for (int m = 0; m < MPW; m++)
                #pragma unroll
                for (int n = 0; n < 8; n++)
                    mma16(acc[m][n], (const uint32_t*)&al[m], (const uint32_t*)&bh[n]);
        }
        __syncthreads();
    }

    #pragma unroll
    for (int m = 0; m < MPW; m++) {
        const int gm = mblk0*16 + (wmt + m)*16 + g;
        #pragma unroll
        for (int n = 0; n < 8; n++) {
            const int gn = bn + (wnt + n)*8 + tg*2;
            const int gl = gn & 511;
            float c0 = acc[m][n][0] + bi[gl];
            float c1 = acc[m][n][1] + bi[gl + 1];
            float c2 = acc[m][n][2] + bi[gl];
            float c3 = acc[m][n][3] + bi[gl + 1];
            if (res) {
                c0 += res[(size_t)gm*ldc + gn];
                c1 += res[(size_t)gm*ldc + gn + 1];
                c2 += res[(size_t)(gm+8)*ldc + gn];
                c3 += res[(size_t)(gm+8)*ldc + gn + 1];
            }
            *(float2*)&C[(size_t)gm*ldc + gn]     = make_float2(c0, c1);
            *(float2*)&C[(size_t)(gm+8)*ldc + gn] = make_float2(c2, c3);
        }
    }
}

// ---------------------------------------------------------------------------
__device__ __forceinline__ void st_frag(uint32_t* dH, uint32_t* dL,
                                        int m, int c, float2 v) {
    size_t fa = ((size_t)(m >> 4))*32 + (c >> 4);
    int mr = m & 15, kc = c & 15;
    int lane = (mr & 7)*4 + ((kc & 7) >> 1);
    int comp = ((mr >> 3) & 1) | ((kc >> 3) << 1);
    uint32_t h, l; packhl(v, h, l);
    size_t off = (fa*32 + lane)*4 + comp;
    dH[off] = h; dL[off] = l;
}

// Banded attention, split-d, 256 threads per 128 q's of one (b,h).
__global__ __launch_bounds__(256)
void attn3(const float* __restrict__ qkv, float* __restrict__ probs)
{
    extern __shared__ float sh[];
    float* Ks = sh;                    // [134][68]
    float* Vs = sh + 134*68;           // [134][68]
    float* Pp = sh + 2*134*68;         // [2][128][9]

    const int t  = threadIdx.x;
    const int tq = t & 127;
    const int half = t >> 7;
    const int q0 = blockIdx.x * 128;
    const int h  = blockIdx.y;
    const int b  = blockIdx.z;

    for (int i = t; i < 134*16; i += 256) {
        int r = i >> 4, d4 = i & 15;
        int row = q0 - 3 + r;
        float4 kv = make_float4(0.f,0.f,0.f,0.f), vv = kv;
        if ((unsigned)row < SS) {
            size_t base = (size_t)(b*SS + row)*NQKV + h*64 + d4*4;
            kv = *(const float4*)&qkv[base + 512];
            vv = *(const float4*)&qkv[base + 1024];
        }
        *(float4*)&Ks[r*68 + d4*4] = kv;
        *(float4*)&Vs[r*68 + d4*4] = vv;
    }
    __syncthreads();

    const int q = q0 + tq;
    const int dbase = half*32;
    float sc[7] = {0.f,0.f,0.f,0.f,0.f,0.f,0.f};
    const float* Qrow = &qkv[(size_t)(b*SS + q)*NQKV + h*64 + dbase];
    #pragma unroll
    for (int d4 = 0; d4 < 8; d4++) {
        float4 qv = *(const float4*)&Qrow[d4*4];
        #pragma unroll
        for (int j = 0; j < 7; j++) {
            float4 kk = *(const float4*)&Ks[(tq + j)*68 + dbase + d4*4];
            sc[j] += qv.x*kk.x + qv.y*kk.y + qv.z*kk.z + qv.w*kk.w;
        }
    }
    float* prow_s = &Pp[(half*128 + tq)*9];
    #pragma unroll
    for (int j = 0; j < 7; j++) prow_s[j] = sc[j];
    __syncthreads();
    #pragma unroll
    for (int j = 0; j < 7; j++)
        sc[j] = Pp[tq*9 + j] + Pp[(128 + tq)*9 + j];

    float mx = -1e30f;
    #pragma unroll
    for (int j = 0; j < 7; j++) {
        sc[j] *= 0.125f;
        if ((unsigned)(q - 3 + j) < SS) mx = fmaxf(mx, sc[j]);
    }
    float p[7], sum = 0.f;
    #pragma unroll
    for (int j = 0; j < 7; j++) {
        p[j] = ((unsigned)(q - 3 + j) < SS) ? expf(sc[j] - mx) : 0.f;
        sum += p[j];
    }
    float inv = 1.0f / sum;
    #pragma unroll
    for (int j = 0; j < 7; j++) p[j] *= inv;

    uint32_t* dH = (uint32_t*)g_oh;
    uint32_t* dL = (uint32_t*)g_ol;
    const int m = b*SS + q;
    #pragma unroll
    for (int d4 = 0; d4 < 8; d4++) {
        float4 o = make_float4(0.f,0.f,0.f,0.f);
        #pragma unroll
        for (int j = 0; j < 7; j++) {
            float4 vv = *(const float4*)&Vs[(tq + j)*68 + dbase + d4*4];
            o.x += p[j]*vv.x; o.y += p[j]*vv.y; o.z += p[j]*vv.z; o.w += p[j]*vv.w;
        }
        int c = h*64 + dbase + d4*4;
        st_frag(dH, dL, m, c,     make_float2(o.x, o.y));
        st_frag(dH, dL, m, c + 2, make_float2(o.z, o.w));
    }

    if (half == 0) {
        float* prow = &probs[((size_t)(b*HH + h)*SS + q)*8];
        *(float4*)&prow[0] = make_float4(p[0], p[1], p[2], p[3]);
        *(float4*)&prow[4] = make_float4(p[4], p[5], p[6], 0.f);
    }
}

// ---------------------------------------------------------------------------
__global__ __launch_bounds__(256)
void band_write(const float* __restrict__ probs, float* __restrict__ attn_out) {
    int idx = blockIdx.x * blockDim.x + threadIdx.x;
    if (idx >= BB*HH*SS) return;
    int q = idx & (SS - 1);
    const float* prow = &probs[(size_t)idx * 8];
    float4 p03 = *(const float4*)&prow[0];
    float4 p46 = *(const float4*)&prow[4];
    float p[7] = {p03.x, p03.y, p03.z, p03.w, p46.x, p46.y, p46.z};
    float* arow = attn_out + (size_t)idx * SS;
    #pragma unroll
    for (int j = 0; j < 7; j++) {
        int k = q - 3 + j;
        if ((unsigned)k < SS) arow[k] = p[j];
    }
}

// ---------------------------------------------------------------------------
__global__ __launch_bounds__(128)
void ln2(const float* __restrict__ y0, const float* __restrict__ gw,
         const float* __restrict__ bt, float* __restrict__ out)
{
    const int m = blockIdx.x, t = threadIdx.x;
    float4 v = ((const float4*)(y0 + (size_t)m*DD))[t];
    float s  = v.x + v.y + v.z + v.w;
    float sq = v.x*v.x + v.y*v.y + v.z*v.z + v.w*v.w;
    #pragma unroll
    for (int o = 16; o; o >>= 1) {
        s  += __shfl_xor_sync(0xffffffffu, s,  o);
        sq += __shfl_xor_sync(0xffffffffu, sq, o);
    }
    __shared__ float ss[4], qq[4];
    int w = t >> 5;
    if ((t & 31) == 0) { ss[w] = s; qq[w] = sq; }
    __syncthreads();
    s  = ss[0] + ss[1] + ss[2] + ss[3];
    sq = qq[0] + qq[1] + qq[2] + qq[3];
    float mean = s * (1.0f/DD);
    float var  = sq * (1.0f/DD) - mean*mean;
    float rstd = rsqrtf(var + 1e-5f);
    float4 gg = ((const float4*)gw)[t];
    float4 bb = ((const float4*)bt)[t];
    float4 r;
    r.x = (v.x - mean)*rstd*gg.x + bb.x;
    r.y = (v.y - mean)*rstd*gg.y + bb.y;
    r.z = (v.z - mean)*rstd*gg.z + bb.z;
    r.w = (v.w - mean)*rstd*gg.w + bb.w;
    ((float4*)(out + (size_t)m*DD))[t] = r;
}

// ---------------------------------------------------------------------------
extern "C" void kernel_launch(void* const* d_in, const int* in_sizes, int n_in,
                              void* d_out, int out_size) {
    const float* x    = (const float*)d_in[0];
    const float* wq_w = (const float*)d_in[2];
    const float* wq_b = (const float*)d_in[3];
    const float* wk_w = (const float*)d_in[4];
    const float* wk_b = (const float*)d_in[5];
    const float* wv_w = (const float*)d_in[6];
    const float* wv_b = (const float*)d_in[7];
    const float* wo_w = (const float*)d_in[8];
    const float* wo_b = (const float*)d_in[9];
    const float* ln_g = (const float*)d_in[10];
    const float* ln_b = (const float*)d_in[11];
    const float* pe   = (const float*)d_in[12];

    float* y_out    = (float*)d_out;
    float* attn_out = (float*)d_out + YELEMS;

    static uint4 *p_ah, *p_al, *p_oh, *p_ol;
    static uint2 *p_bh, *p_bl;
    static float *p_qkv, *p_y0, *p_probs;
    static cudaStream_t s2;
    static cudaEvent_t evF, evJ;
    static bool init = false;
    if (!init) {
        cudaGetSymbolAddress((void**)&p_ah, g_ah);
        cudaGetSymbolAddress((void**)&p_al, g_al);
        cudaGetSymbolAddress((void**)&p_bh, g_bh);
        cudaGetSymbolAddress((void**)&p_bl, g_bl);
        cudaGetSymbolAddress((void**)&p_oh, g_oh);
        cudaGetSymbolAddress((void**)&p_ol, g_ol);
        cudaGetSymbolAddress((void**)&p_qkv,   g_qkv);
        cudaGetSymbolAddress((void**)&p_y0,    g_y0);
        cudaGetSymbolAddress((void**)&p_probs, g_probs);
        cudaStreamCreateWithFlags(&s2, cudaStreamNonBlocking);
        cudaEventCreateWithFlags(&evF, cudaEventDisableTiming);
        cudaEventCreateWithFlags(&evJ, cudaEventDisableTiming);
        cudaFuncSetAttribute(attn3, cudaFuncAttributeMaxDynamicSharedMemorySize, ATTN_SMEM);
        cudaFuncSetAttribute(gemm_cp<8>, cudaFuncAttributeMaxDynamicSharedMemorySize, 2*(2*8*1024 + 16384));
        cudaFuncSetAttribute(gemm_cp<4>, cudaFuncAttributeMaxDynamicSharedMemorySize, 2*(2*4*1024 + 16384));
        init = true;
    }

    // fork: zero the 268MB attn output with short-lived streaming CTAs
    cudaEventRecord(evF, 0);
    cudaStreamWaitEvent(s2, evF, 0);
    zero_fill<<<2048, 256, 0, s2>>>((float4*)attn_out);
    cudaEventRecord(evJ, s2);

    // prep: convert to frag-packed bf16 hi/lo
    prep_w <<<8192*32/256, 256>>>(wq_w, wk_w, wv_w, wo_w);
    prep_xp<<<8192*32/256, 256>>>(x, pe);

    // QKV projection: [4096,512] x [1536,512]^T
    gemm_cp<8><<<dim3(NQKV/128, MM/128), 256, 2*(2*8*1024 + 16384)>>>(
        p_ah, p_al, (const uint4*)p_bh, (const uint4*)p_bl, 0,
        wq_b, wk_b, wv_b, nullptr, p_qkv, NQKV);

    // banded attention -> frag-packed oh/ol + band probs
    attn3<<<dim3(SS/128, HH, BB), 256, ATTN_SMEM>>>(p_qkv, p_probs);

    // O projection + residual (M-tile 64 -> 256 CTAs)
    gemm_cp<4><<<dim3(DD/128, MM/64), 256, 2*(2*4*1024 + 16384)>>>(
        p_oh, p_ol, (const uint4*)p_bh, (const uint4*)p_bl, 192,
        wo_b, wo_b, wo_b, x, p_y0, DD);

    // LayerNorm
    ln2<<<MM, 128>>>(p_y0, ln_g, ln_b, y_out);

    // join zero_fill, then scatter band values
    cudaStreamWaitEvent(0, evJ, 0);
    band_write<<<(BB*HH*SS + 255)/256, 256>>>(p_probs, attn_out);
}

// round 13
// speedup vs baseline: 1.6080x; 1.0045x over previous
#include <cuda_runtime.h>
#include <cuda_bf16.h>
#include <cstdint>

#define BB   2
#define SS   2048
#define DD   512
#define HH   8
#define MM   (BB*SS)        // 4096
#define NQKV 1536
#define KK   512
#define YELEMS ((size_t)MM*DD)
#define ATTN_ELEMS ((size_t)BB*HH*SS*SS)
#define ATTN_SMEM ((134*68*2 + 2*128*9)*4)

// Frag-packed buffers
__device__ uint4 g_ah[8192*32], g_al[8192*32];   // x+pe hi/lo, frag-packed
__device__ uint2 g_bh[8192*32], g_bl[8192*32];   // [wq;wk;wv;wo] hi/lo, frag-packed
__device__ uint4 g_oh[8192*32], g_ol[8192*32];   // attn output hi/lo, frag-packed
__device__ float g_qkv[(size_t)MM*NQKV];
__device__ float g_y0[MM*DD];
__device__ float g_probs[(size_t)BB*HH*SS*8];

// ---------------------------------------------------------------------------
__device__ __forceinline__ void packhl(float2 v, uint32_t& h, uint32_t& l) {
    __nv_bfloat162 hb = __floats2bfloat162_rn(v.x, v.y);
    h = *reinterpret_cast<uint32_t*>(&hb);
    float hx = __bfloat162float(hb.x), hy = __bfloat162float(hb.y);
    __nv_bfloat162 lb = __floats2bfloat162_rn(v.x - hx, v.y - hy);
    l = *reinterpret_cast<uint32_t*>(&lb);
}
__device__ __forceinline__ void mma16(float* c, const uint32_t* a, const uint32_t* b) {
    asm volatile(
      "mma.sync.aligned.m16n8k16.row.col.f32.bf16.bf16.f32 "
      "{%0,%1,%2,%3},{%4,%5,%6,%7},{%8,%9},{%0,%1,%2,%3};"
      : "+f"(c[0]), "+f"(c[1]), "+f"(c[2]), "+f"(c[3])
      : "r"(a[0]), "r"(a[1]), "r"(a[2]), "r"(a[3]), "r"(b[0]), "r"(b[1]));
}
__device__ __forceinline__ uint32_t smem_u32(const void* p) {
    uint32_t a;
    asm("{ .reg .u64 t; cvta.to.shared.u64 t, %1; cvt.u32.u64 %0, t; }" : "=r"(a) : "l"(p));
    return a;
}
__device__ __forceinline__ void cp16(uint32_t dst, const void* src) {
    asm volatile("cp.async.cg.shared.global [%0], [%1], 16;" :: "r"(dst), "l"(src));
}

// ---------------------------------------------------------------------------
__global__ __launch_bounds__(256)
void zero_fill(float4* __restrict__ p) {
    const float4 z = make_float4(0.f, 0.f, 0.f, 0.f);
    size_t base = (size_t)blockIdx.x * (256*32) + threadIdx.x;
    #pragma unroll
    for (int i = 0; i < 32; i++) __stcs(&p[base + (size_t)i*256], z);
}

// ---------------------------------------------------------------------------
__global__ __launch_bounds__(256)
void prep_xp(const float* __restrict__ x, const float* __restrict__ pe) {
    int gid = blockIdx.x * 256 + threadIdx.x;   // 8192*32
    if (gid >= 8192*32) return;
    int lane = gid & 31, fa = gid >> 5;
    int kblk = fa & 31, mblk = fa >> 5;
    int g = lane >> 2, tg = lane & 3;
    int r0 = mblk*16 + g, c0 = kblk*16 + tg*2;
    int s0 = r0 & (SS-1), s1 = (r0+8) & (SS-1);
    float2 v0 = *(const float2*)(x + (size_t)r0*KK + c0);
    float2 v1 = *(const float2*)(x + (size_t)(r0+8)*KK + c0);
    float2 v2 = *(const float2*)(x + (size_t)r0*KK + c0 + 8);
    float2 v3 = *(const float2*)(x + (size_t)(r0+8)*KK + c0 + 8);
    float2 e;
    e = *(const float2*)(pe + (size_t)s0*KK + c0);     v0.x += e.x; v0.y += e.y;
    e = *(const float2*)(pe + (size_t)s1*KK + c0);     v1.x += e.x; v1.y += e.y;
    e = *(const float2*)(pe + (size_t)s0*KK + c0 + 8); v2.x += e.x; v2.y += e.y;
    e = *(const float2*)(pe + (size_t)s1*KK + c0 + 8); v3.x += e.x; v3.y += e.y;
    uint4 hv, lv;
    packhl(v0, hv.x, lv.x); packhl(v1, hv.y, lv.y);
    packhl(v2, hv.z, lv.z); packhl(v3, hv.w, lv.w);
    g_ah[gid] = hv; g_al[gid] = lv;
}

__global__ __launch_bounds__(256)
void prep_w(const float* __restrict__ wq, const float* __restrict__ wk,
            const float* __restrict__ wv, const float* __restrict__ wo) {
    int gid = blockIdx.x * 256 + threadIdx.x;   // 8192*32
    if (gid >= 8192*32) return;
    int lane = gid & 31, fb = gid >> 5;
    int kblk = fb & 31, nblk = fb >> 5;
    int n = nblk*8 + (lane >> 2);
    int c0 = kblk*16 + (lane & 3)*2;
    const float* row = (n < 512)  ? wq + (size_t)n*KK
                     : (n < 1024) ? wk + (size_t)(n-512)*KK
                     : (n < 1536) ? wv + (size_t)(n-1024)*KK
                                  : wo + (size_t)(n-1536)*KK;
    float2 u0 = *(const float2*)(row + c0);
    float2 u1 = *(const float2*)(row + c0 + 8);
    uint2 hv, lv;
    packhl(u0, hv.x, lv.x); packhl(u1, hv.y, lv.y);
    g_bh[gid] = hv; g_bl[gid] = lv;
}

// ---------------------------------------------------------------------------
// bf16x3 GEMM, frag-packed inputs, 3-stage cp.async pipeline, ONE sync/stage.
// M-tile = MF*16, N-tile 128, BK=32. 256 threads (8 warps), warp (MF*4)x64.
// Stage layout (bytes): [AH: MF*1024][AL: MF*1024][BH: 8192][BL: 8192]
template<int MF>
__global__ __launch_bounds__(256, 2)
void gemm_cp(const uint4* __restrict__ Ah, const uint4* __restrict__ Al,
             const uint4* __restrict__ Bh4, const uint4* __restrict__ Bl4,
             int nblk_base,
             const float* __restrict__ bi0, const float* __restrict__ bi1,
             const float* __restrict__ bi2,
             const float* __restrict__ res, float* __restrict__ C, int ldc)
{
    extern __shared__ __align__(16) char smem[];
    constexpr int A_BYTES = MF*64*16;          // MF*1024
    constexpr int STAGE   = 2*A_BYTES + 16384;
    const uint32_t sb = smem_u32(smem);

    const int t = threadIdx.x, lane = t & 31, w = t >> 5;
    const int g = lane >> 2, tg = lane & 3;
    const int mblk0 = blockIdx.y * MF;
    const int bn = blockIdx.x * 128;
    const int nblk0 = nblk_base + blockIdx.x * 16;
    const int seg = bn >> 9;
    const float* bi = (seg == 0) ? bi0 : (seg == 1) ? bi1 : bi2;
    constexpr int MPW = MF/4;
    const int wmt = (w & 3)*MPW, wnt = (w >> 2)*8;

    float acc[MPW][8][4] = {};

    // issue stage st (k-block pair 2*st) into buffer st%3
    auto issue = [&](int st) {
        const int kb = st*2;
        const uint32_t base = sb + (st % 3)*STAGE;
        #pragma unroll
        for (int i = 0; i < MF/4; i++) {
            int s = t + 256*i;
            int sfr = s >> 5, ln = s & 31;
            int mt = sfr >> 1, kt = sfr & 1;
            size_t fa = ((size_t)(mblk0 + mt)*32 + kb + kt)*32 + ln;
            cp16(base + s*16,           Ah + fa);
            cp16(base + A_BYTES + s*16, Al + fa);
        }
        #pragma unroll
        for (int i = 0; i < 2; i++) {
            int s = t + 256*i;
            int sfr = s >> 4, lp = s & 15;
            int nt = sfr >> 1, kt = sfr & 1;
            size_t fb = ((size_t)(nblk0 + nt)*32 + kb + kt)*16 + lp;
            cp16(base + 2*A_BYTES + s*16,        Bh4 + fb);
            cp16(base + 2*A_BYTES + 8192 + s*16, Bl4 + fb);
        }
        asm volatile("cp.async.commit_group;");
    };

    issue(0);
    issue(1);
    for (int s = 0; s < 16; s++) {
        if (s < 15) asm volatile("cp.async.wait_group 1;");
        else        asm volatile("cp.async.wait_group 0;");
        __syncthreads();

        const char* stg = smem + (s % 3)*STAGE;
        const uint4* AsH = (const uint4*)stg;
        const uint4* AsL = (const uint4*)(stg + A_BYTES);
        const uint2* BsH = (const uint2*)(stg + 2*A_BYTES);
        const uint2* BsL = (const uint2*)(stg + 2*A_BYTES + 8192);

        #pragma unroll
        for (int kt = 0; kt < 2; kt++) {
            uint4 ah[MPW], al[MPW];
            uint2 bh[8], bl[8];
            #pragma unroll
            for (int m = 0; m < MPW; m++) ah[m] = AsH[((wmt+m)*2 + kt)*32 + lane];
            #pragma unroll
            for (int n = 0; n < 8; n++) bh[n] = BsH[((wnt+n)*2 + kt)*32 + lane];
            #pragma unroll
            for (int m = 0; m < MPW; m++)
                #pragma unroll
                for (int n = 0; n < 8; n++)
                    mma16(acc[m][n], (const uint32_t*)&ah[m], (const uint32_t*)&bh[n]);
            #pragma unroll
            for (int n = 0; n < 8; n++) bl[n] = BsL[((wnt+n)*2 + kt)*32 + lane];
            #pragma unroll
            for (int m = 0; m < MPW; m++)
                #pragma unroll
                for (int n = 0; n < 8; n++)
                    mma16(acc[m][n], (const uint32_t*)&ah[m], (const uint32_t*)&bl[n]);
            #pragma unroll
            for (int m = 0; m < MPW; m++) al[m] = AsL[((wmt+m)*2 + kt)*32 + lane];
            #pragma unroll
            for (int m = 0; m < MPW; m++)
                #pragma unroll
                for (int n = 0; n < 8; n++)
                    mma16(acc[m][n], (const uint32_t*)&al[m], (const uint32_t*)&bh[n]);
        }

        // safe: buffer (s+2)%3 was last read by compute(s-1); all threads
        // passed this stage's __syncthreads() after finishing compute(s-1).
        if (s + 2 < 16) issue(s + 2);
    }

    #pragma unroll
    for (int m = 0; m < MPW; m++) {
        const int gm = mblk0*16 + (wmt + m)*16 + g;
        #pragma unroll
        for (int n = 0; n < 8; n++) {
            const int gn = bn + (wnt + n)*8 + tg*2;
            const int gl = gn & 511;
            float c0 = acc[m][n][0] + bi[gl];
            float c1 = acc[m][n][1] + bi[gl + 1];
            float c2 = acc[m][n][2] + bi[gl];
            float c3 = acc[m][n][3] + bi[gl + 1];
            if (res) {
                c0 += res[(size_t)gm*ldc + gn];
                c1 += res[(size_t)gm*ldc + gn + 1];
                c2 += res[(size_t)(gm+8)*ldc + gn];
                c3 += res[(size_t)(gm+8)*ldc + gn + 1];
            }
            *(float2*)&C[(size_t)gm*ldc + gn]     = make_float2(c0, c1);
            *(float2*)&C[(size_t)(gm+8)*ldc + gn] = make_float2(c2, c3);
        }
    }
}

// ---------------------------------------------------------------------------
__device__ __forceinline__ void st_frag(uint32_t* dH, uint32_t* dL,
                                        int m, int c, float2 v) {
    size_t fa = ((size_t)(m >> 4))*32 + (c >> 4);
    int mr = m & 15, kc = c & 15;
    int lane = (mr & 7)*4 + ((kc & 7) >> 1);
    int comp = ((mr >> 3) & 1) | ((kc >> 3) << 1);
    uint32_t h, l; packhl(v, h, l);
    size_t off = (fa*32 + lane)*4 + comp;
    dH[off] = h; dL[off] = l;
}

// Banded attention, split-d, 256 threads per 128 q's of one (b,h).
__global__ __launch_bounds__(256)
void attn3(const float* __restrict__ qkv, float* __restrict__ probs)
{
    extern __shared__ float sh[];
    float* Ks = sh;                    // [134][68]
    float* Vs = sh + 134*68;           // [134][68]
    float* Pp = sh + 2*134*68;         // [2][128][9]

    const int t  = threadIdx.x;
    const int tq = t & 127;
    const int half = t >> 7;
    const int q0 = blockIdx.x * 128;
    const int h  = blockIdx.y;
    const int b  = blockIdx.z;

    for (int i = t; i < 134*16; i += 256) {
        int r = i >> 4, d4 = i & 15;
        int row = q0 - 3 + r;
        float4 kv = make_float4(0.f,0.f,0.f,0.f), vv = kv;
        if ((unsigned)row < SS) {
            size_t base = (size_t)(b*SS + row)*NQKV + h*64 + d4*4;
            kv = *(const float4*)&qkv[base + 512];
            vv = *(const float4*)&qkv[base + 1024];
        }
        *(float4*)&Ks[r*68 + d4*4] = kv;
        *(float4*)&Vs[r*68 + d4*4] = vv;
    }
    __syncthreads();

    const int q = q0 + tq;
    const int dbase = half*32;
    float sc[7] = {0.f,0.f,0.f,0.f,0.f,0.f,0.f};
    const float* Qrow = &qkv[(size_t)(b*SS + q)*NQKV + h*64 + dbase];
    #pragma unroll
    for (int d4 = 0; d4 < 8; d4++) {
        float4 qv = *(const float4*)&Qrow[d4*4];
        #pragma unroll
        for (int j = 0; j < 7; j++) {
            float4 kk = *(const float4*)&Ks[(tq + j)*68 + dbase + d4*4];
            sc[j] += qv.x*kk.x + qv.y*kk.y + qv.z*kk.z + qv.w*kk.w;
        }
    }
    float* prow_s = &Pp[(half*128 + tq)*9];
    #pragma unroll
    for (int j = 0; j < 7; j++) prow_s[j] = sc[j];
    __syncthreads();
    #pragma unroll
    for (int j = 0; j < 7; j++)
        sc[j] = Pp[tq*9 + j] + Pp[(128 + tq)*9 + j];

    float mx = -1e30f;
    #pragma unroll
    for (int j = 0; j < 7; j++) {
        sc[j] *= 0.125f;
        if ((unsigned)(q - 3 + j) < SS) mx = fmaxf(mx, sc[j]);
    }
    float p[7], sum = 0.f;
    #pragma unroll
    for (int j = 0; j < 7; j++) {
        p[j] = ((unsigned)(q - 3 + j) < SS) ? expf(sc[j] - mx) : 0.f;
        sum += p[j];
    }
    float inv = 1.0f / sum;
    #pragma unroll
    for (int j = 0; j < 7; j++) p[j] *= inv;

    uint32_t* dH = (uint32_t*)g_oh;
    uint32_t* dL = (uint32_t*)g_ol;
    const int m = b*SS + q;
    #pragma unroll
    for (int d4 = 0; d4 < 8; d4++) {
        float4 o = make_float4(0.f,0.f,0.f,0.f);
        #pragma unroll
        for (int j = 0; j < 7; j++) {
            float4 vv = *(const float4*)&Vs[(tq + j)*68 + dbase + d4*4];
            o.x += p[j]*vv.x; o.y += p[j]*vv.y; o.z += p[j]*vv.z; o.w += p[j]*vv.w;
        }
        int c = h*64 + dbase + d4*4;
        st_frag(dH, dL, m, c,     make_float2(o.x, o.y));
        st_frag(dH, dL, m, c + 2, make_float2(o.z, o.w));
    }

    if (half == 0) {
        float* prow = &probs[((size_t)(b*HH + h)*SS + q)*8];
        *(float4*)&prow[0] = make_float4(p[0], p[1], p[2], p[3]);
        *(float4*)&prow[4] = make_float4(p[4], p[5], p[6], 0.f);
    }
}

// ---------------------------------------------------------------------------
__global__ __launch_bounds__(256)
void band_write(const float* __restrict__ probs, float* __restrict__ attn_out) {
    int idx = blockIdx.x * blockDim.x + threadIdx.x;
    if (idx >= BB*HH*SS) return;
    int q = idx & (SS - 1);
    const float* prow = &probs[(size_t)idx * 8];
    float4 p03 = *(const float4*)&prow[0];
    float4 p46 = *(const float4*)&prow[4];
    float p[7] = {p03.x, p03.y, p03.z, p03.w, p46.x, p46.y, p46.z};
    float* arow = attn_out + (size_t)idx * SS;
    #pragma unroll
    for (int j = 0; j < 7; j++) {
        int k = q - 3 + j;
        if ((unsigned)k < SS) arow[k] = p[j];
    }
}

// ---------------------------------------------------------------------------
__global__ __launch_bounds__(128)
void ln2(const float* __restrict__ y0, const float* __restrict__ gw,
         const float* __restrict__ bt, float* __restrict__ out)
{
    const int m = blockIdx.x, t = threadIdx.x;
    float4 v = ((const float4*)(y0 + (size_t)m*DD))[t];
    float s  = v.x + v.y + v.z + v.w;
    float sq = v.x*v.x + v.y*v.y + v.z*v.z + v.w*v.w;
    #pragma unroll
    for (int o = 16; o; o >>= 1) {
        s  += __shfl_xor_sync(0xffffffffu, s,  o);
        sq += __shfl_xor_sync(0xffffffffu, sq, o);
    }
    __shared__ float ss[4], qq[4];
    int w = t >> 5;
    if ((t & 31) == 0) { ss[w] = s; qq[w] = sq; }
    __syncthreads();
    s  = ss[0] + ss[1] + ss[2] + ss[3];
    sq = qq[0] + qq[1] + qq[2] + qq[3];
    float mean = s * (1.0f/DD);
    float var  = sq * (1.0f/DD) - mean*mean;
    float rstd = rsqrtf(var + 1e-5f);
    float4 gg = ((const float4*)gw)[t];
    float4 bb = ((const float4*)bt)[t];
    float4 r;
    r.x = (v.x - mean)*rstd*gg.x + bb.x;
    r.y = (v.y - mean)*rstd*gg.y + bb.y;
    r.z = (v.z - mean)*rstd*gg.z + bb.z;
    r.w = (v.w - mean)*rstd*gg.w + bb.w;
    ((float4*)(out + (size_t)m*DD))[t] = r;
}

// ---------------------------------------------------------------------------
extern "C" void kernel_launch(void* const* d_in, const int* in_sizes, int n_in,
                              void* d_out, int out_size) {
    const float* x    = (const float*)d_in[0];
    const float* wq_w = (const float*)d_in[2];
    const float* wq_b = (const float*)d_in[3];
    const float* wk_w = (const float*)d_in[4];
    const float* wk_b = (const float*)d_in[5];
    const float* wv_w = (const float*)d_in[6];
    const float* wv_b = (const float*)d_in[7];
    const float* wo_w = (const float*)d_in[8];
    const float* wo_b = (const float*)d_in[9];
    const float* ln_g = (const float*)d_in[10];
    const float* ln_b = (const float*)d_in[11];
    const float* pe   = (const float*)d_in[12];

    float* y_out    = (float*)d_out;
    float* attn_out = (float*)d_out + YELEMS;

    static uint4 *p_ah, *p_al, *p_oh, *p_ol;
    static uint2 *p_bh, *p_bl;
    static float *p_qkv, *p_y0, *p_probs;
    static cudaStream_t s2;
    static cudaEvent_t evF, evJ;
    static bool init = false;
    if (!init) {
        cudaGetSymbolAddress((void**)&p_ah, g_ah);
        cudaGetSymbolAddress((void**)&p_al, g_al);
        cudaGetSymbolAddress((void**)&p_bh, g_bh);
        cudaGetSymbolAddress((void**)&p_bl, g_bl);
        cudaGetSymbolAddress((void**)&p_oh, g_oh);
        cudaGetSymbolAddress((void**)&p_ol, g_ol);
        cudaGetSymbolAddress((void**)&p_qkv,   g_qkv);
        cudaGetSymbolAddress((void**)&p_y0,    g_y0);
        cudaGetSymbolAddress((void**)&p_probs, g_probs);
        cudaStreamCreateWithFlags(&s2, cudaStreamNonBlocking);
        cudaEventCreateWithFlags(&evF, cudaEventDisableTiming);
        cudaEventCreateWithFlags(&evJ, cudaEventDisableTiming);
        cudaFuncSetAttribute(attn3, cudaFuncAttributeMaxDynamicSharedMemorySize, ATTN_SMEM);
        cudaFuncSetAttribute(gemm_cp<8>, cudaFuncAttributeMaxDynamicSharedMemorySize, 3*(2*8*1024 + 16384));
        cudaFuncSetAttribute(gemm_cp<4>, cudaFuncAttributeMaxDynamicSharedMemorySize, 3*(2*4*1024 + 16384));
        init = true;
    }

    // fork: zero the 268MB attn output with short-lived streaming CTAs
    cudaEventRecord(evF, 0);
    cudaStreamWaitEvent(s2, evF, 0);
    zero_fill<<<2048, 256, 0, s2>>>((float4*)attn_out);
    cudaEventRecord(evJ, s2);

    // prep: convert to frag-packed bf16 hi/lo
    prep_w <<<8192*32/256, 256>>>(wq_w, wk_w, wv_w, wo_w);
    prep_xp<<<8192*32/256, 256>>>(x, pe);

    // QKV projection: [4096,512] x [1536,512]^T
    gemm_cp<8><<<dim3(NQKV/128, MM/128), 256, 3*(2*8*1024 + 16384)>>>(
        p_ah, p_al, (const uint4*)p_bh, (const uint4*)p_bl, 0,
        wq_b, wk_b, wv_b, nullptr, p_qkv, NQKV);

    // banded attention -> frag-packed oh/ol + band probs
    attn3<<<dim3(SS/128, HH, BB), 256, ATTN_SMEM>>>(p_qkv, p_probs);

    // O projection + residual (M-tile 64 -> 256 CTAs)
    gemm_cp<4><<<dim3(DD/128, MM/64), 256, 3*(2*4*1024 + 16384)>>>(
        p_oh, p_ol, (const uint4*)p_bh, (const uint4*)p_bl, 192,
        wo_b, wo_b, wo_b, x, p_y0, DD);

    // LayerNorm
    ln2<<<MM, 128>>>(p_y0, ln_g, ln_b, y_out);

    // join zero_fill, then scatter band values
    cudaStreamWaitEvent(0, evJ, 0);
    band_write<<<(BB*HH*SS + 255)/256, 256>>>(p_probs, attn_out);
}

// round 14
// speedup vs baseline: 1.6692x; 1.0381x over previous
#include <cuda_runtime.h>
#include <cuda_bf16.h>
#include <cstdint>

#define BB   2
#define SS   2048
#define DD   512
#define HH   8
#define MM   (BB*SS)        // 4096
#define NQKV 1536
#define KK   512
#define YELEMS ((size_t)MM*DD)
#define ATTN_ELEMS ((size_t)BB*HH*SS*SS)
#define ATTN_SMEM ((134*68*2 + 2*128*9)*4)

// Frag-packed buffers
__device__ uint4 g_ah[8192*32], g_al[8192*32];   // x+pe hi/lo, frag-packed
__device__ uint2 g_bh[8192*32], g_bl[8192*32];   // [wq;wk;wv;wo] hi/lo, frag-packed
__device__ uint4 g_oh[8192*32], g_ol[8192*32];   // attn output hi/lo, frag-packed
__device__ float g_qkv[(size_t)MM*NQKV];
__device__ float g_y0[MM*DD];
__device__ float g_probs[(size_t)BB*HH*SS*8];

// ---------------------------------------------------------------------------
__device__ __forceinline__ void packhl(float2 v, uint32_t& h, uint32_t& l) {
    __nv_bfloat162 hb = __floats2bfloat162_rn(v.x, v.y);
    h = *reinterpret_cast<uint32_t*>(&hb);
    float hx = __bfloat162float(hb.x), hy = __bfloat162float(hb.y);
    __nv_bfloat162 lb = __floats2bfloat162_rn(v.x - hx, v.y - hy);
    l = *reinterpret_cast<uint32_t*>(&lb);
}
__device__ __forceinline__ void mma16(float* c, const uint32_t* a, const uint32_t* b) {
    asm volatile(
      "mma.sync.aligned.m16n8k16.row.col.f32.bf16.bf16.f32 "
      "{%0,%1,%2,%3},{%4,%5,%6,%7},{%8,%9},{%0,%1,%2,%3};"
      : "+f"(c[0]), "+f"(c[1]), "+f"(c[2]), "+f"(c[3])
      : "r"(a[0]), "r"(a[1]), "r"(a[2]), "r"(a[3]), "r"(b[0]), "r"(b[1]));
}
__device__ __forceinline__ uint32_t smem_u32(const void* p) {
    uint32_t a;
    asm("{ .reg .u64 t; cvta.to.shared.u64 t, %1; cvt.u32.u64 %0, t; }" : "=r"(a) : "l"(p));
    return a;
}
__device__ __forceinline__ void cp16(uint32_t dst, const void* src) {
    asm volatile("cp.async.cg.shared.global [%0], [%1], 16;" :: "r"(dst), "l"(src));
}

// ---------------------------------------------------------------------------
__global__ __launch_bounds__(256)
void zero_fill(float4* __restrict__ p) {
    const float4 z = make_float4(0.f, 0.f, 0.f, 0.f);
    size_t base = (size_t)blockIdx.x * (256*32) + threadIdx.x;
    #pragma unroll
    for (int i = 0; i < 32; i++) __stcs(&p[base + (size_t)i*256], z);
}

// ---------------------------------------------------------------------------
__global__ __launch_bounds__(256)
void prep_xp(const float* __restrict__ x, const float* __restrict__ pe) {
    int gid = blockIdx.x * 256 + threadIdx.x;   // 8192*32
    if (gid >= 8192*32) return;
    int lane = gid & 31, fa = gid >> 5;
    int kblk = fa & 31, mblk = fa >> 5;
    int g = lane >> 2, tg = lane & 3;
    int r0 = mblk*16 + g, c0 = kblk*16 + tg*2;
    int s0 = r0 & (SS-1), s1 = (r0+8) & (SS-1);
    float2 v0 = *(const float2*)(x + (size_t)r0*KK + c0);
    float2 v1 = *(const float2*)(x + (size_t)(r0+8)*KK + c0);
    float2 v2 = *(const float2*)(x + (size_t)r0*KK + c0 + 8);
    float2 v3 = *(const float2*)(x + (size_t)(r0+8)*KK + c0 + 8);
    float2 e;
    e = *(const float2*)(pe + (size_t)s0*KK + c0);     v0.x += e.x; v0.y += e.y;
    e = *(const float2*)(pe + (size_t)s1*KK + c0);     v1.x += e.x; v1.y += e.y;
    e = *(const float2*)(pe + (size_t)s0*KK + c0 + 8); v2.x += e.x; v2.y += e.y;
    e = *(const float2*)(pe + (size_t)s1*KK + c0 + 8); v3.x += e.x; v3.y += e.y;
    uint4 hv, lv;
    packhl(v0, hv.x, lv.x); packhl(v1, hv.y, lv.y);
    packhl(v2, hv.z, lv.z); packhl(v3, hv.w, lv.w);
    g_ah[gid] = hv; g_al[gid] = lv;
}

__global__ __launch_bounds__(256)
void prep_w(const float* __restrict__ wq, const float* __restrict__ wk,
            const float* __restrict__ wv, const float* __restrict__ wo) {
    int gid = blockIdx.x * 256 + threadIdx.x;   // 8192*32
    if (gid >= 8192*32) return;
    int lane = gid & 31, fb = gid >> 5;
    int kblk = fb & 31, nblk = fb >> 5;
    int n = nblk*8 + (lane >> 2);
    int c0 = kblk*16 + (lane & 3)*2;
    const float* row = (n < 512)  ? wq + (size_t)n*KK
                     : (n < 1024) ? wk + (size_t)(n-512)*KK
                     : (n < 1536) ? wv + (size_t)(n-1024)*KK
                                  : wo + (size_t)(n-1536)*KK;
    float2 u0 = *(const float2*)(row + c0);
    float2 u1 = *(const float2*)(row + c0 + 8);
    uint2 hv, lv;
    packhl(u0, hv.x, lv.x); packhl(u1, hv.y, lv.y);
    g_bh[gid] = hv; g_bl[gid] = lv;
}

// ---------------------------------------------------------------------------
// bf16x3 GEMM, frag-packed inputs, 3-stage cp.async pipeline, ONE sync/stage.
template<int MF>
__global__ __launch_bounds__(256, 2)
void gemm_cp(const uint4* __restrict__ Ah, const uint4* __restrict__ Al,
             const uint4* __restrict__ Bh4, const uint4* __restrict__ Bl4,
             int nblk_base,
             const float* __restrict__ bi0, const float* __restrict__ bi1,
             const float* __restrict__ bi2,
             const float* __restrict__ res, float* __restrict__ C, int ldc)
{
    extern __shared__ __align__(16) char smem[];
    constexpr int A_BYTES = MF*64*16;          // MF*1024
    constexpr int STAGE   = 2*A_BYTES + 16384;
    const uint32_t sb = smem_u32(smem);

    const int t = threadIdx.x, lane = t & 31, w = t >> 5;
    const int g = lane >> 2, tg = lane & 3;
    const int mblk0 = blockIdx.y * MF;
    const int bn = blockIdx.x * 128;
    const int nblk0 = nblk_base + blockIdx.x * 16;
    const int seg = bn >> 9;
    const float* bi = (seg == 0) ? bi0 : (seg == 1) ? bi1 : bi2;
    constexpr int MPW = MF/4;
    const int wmt = (w & 3)*MPW, wnt = (w >> 2)*8;

    float acc[MPW][8][4] = {};

    auto issue = [&](int st) {
        const int kb = st*2;
        const uint32_t base = sb + (st % 3)*STAGE;
        #pragma unroll
        for (int i = 0; i < MF/4; i++) {
            int s = t + 256*i;
            int sfr = s >> 5, ln = s & 31;
            int mt = sfr >> 1, kt = sfr & 1;
            size_t fa = ((size_t)(mblk0 + mt)*32 + kb + kt)*32 + ln;
            cp16(base + s*16,           Ah + fa);
            cp16(base + A_BYTES + s*16, Al + fa);
        }
        #pragma unroll
        for (int i = 0; i < 2; i++) {
            int s = t + 256*i;
            int sfr = s >> 4, lp = s & 15;
            int nt = sfr >> 1, kt = sfr & 1;
            size_t fb = ((size_t)(nblk0 + nt)*32 + kb + kt)*16 + lp;
            cp16(base + 2*A_BYTES + s*16,        Bh4 + fb);
            cp16(base + 2*A_BYTES + 8192 + s*16, Bl4 + fb);
        }
        asm volatile("cp.async.commit_group;");
    };

    issue(0);
    issue(1);
    for (int s = 0; s < 16; s++) {
        if (s < 15) asm volatile("cp.async.wait_group 1;");
        else        asm volatile("cp.async.wait_group 0;");
        __syncthreads();

        const char* stg = smem + (s % 3)*STAGE;
        const uint4* AsH = (const uint4*)stg;
        const uint4* AsL = (const uint4*)(stg + A_BYTES);
        const uint2* BsH = (const uint2*)(stg + 2*A_BYTES);
        const uint2* BsL = (const uint2*)(stg + 2*A_BYTES + 8192);

        #pragma unroll
        for (int kt = 0; kt < 2; kt++) {
            uint4 ah[MPW], al[MPW];
            uint2 bh[8], bl[8];
            #pragma unroll
            for (int m = 0; m < MPW; m++) ah[m] = AsH[((wmt+m)*2 + kt)*32 + lane];
            #pragma unroll
            for (int n = 0; n < 8; n++) bh[n] = BsH[((wnt+n)*2 + kt)*32 + lane];
            #pragma unroll
            for (int m = 0; m < MPW; m++)
                #pragma unroll
                for (int n = 0; n < 8; n++)
                    mma16(acc[m][n], (const uint32_t*)&ah[m], (const uint32_t*)&bh[n]);
            #pragma unroll
            for (int n = 0; n < 8; n++) bl[n] = BsL[((wnt+n)*2 + kt)*32 + lane];
            #pragma unroll
            for (int m = 0; m < MPW; m++)
                #pragma unroll
                for (int n = 0; n < 8; n++)
                    mma16(acc[m][n], (const uint32_t*)&ah[m], (const uint32_t*)&bl[n]);
            #pragma unroll
            for (int m = 0; m < MPW; m++) al[m] = AsL[((wmt+m)*2 + kt)*32 + lane];
            #pragma unroll
            for (int m = 0; m < MPW; m++)
                #pragma unroll
                for (int n = 0; n < 8; n++)
                    mma16(acc[m][n], (const uint32_t*)&al[m], (const uint32_t*)&bh[n]);
        }

        if (s + 2 < 16) issue(s + 2);
    }

    #pragma unroll
    for (int m = 0; m < MPW; m++) {
        const int gm = mblk0*16 + (wmt + m)*16 + g;
        #pragma unroll
        for (int n = 0; n < 8; n++) {
            const int gn = bn + (wnt + n)*8 + tg*2;
            const int gl = gn & 511;
            float c0 = acc[m][n][0] + bi[gl];
            float c1 = acc[m][n][1] + bi[gl + 1];
            float c2 = acc[m][n][2] + bi[gl];
            float c3 = acc[m][n][3] + bi[gl + 1];
            if (res) {
                c0 += res[(size_t)gm*ldc + gn];
                c1 += res[(size_t)gm*ldc + gn + 1];
                c2 += res[(size_t)(gm+8)*ldc + gn];
                c3 += res[(size_t)(gm+8)*ldc + gn + 1];
            }
            *(float2*)&C[(size_t)gm*ldc + gn]     = make_float2(c0, c1);
            *(float2*)&C[(size_t)(gm+8)*ldc + gn] = make_float2(c2, c3);
        }
    }
}

// ---------------------------------------------------------------------------
__device__ __forceinline__ void st_frag(uint32_t* dH, uint32_t* dL,
                                        int m, int c, float2 v) {
    size_t fa = ((size_t)(m >> 4))*32 + (c >> 4);
    int mr = m & 15, kc = c & 15;
    int lane = (mr & 7)*4 + ((kc & 7) >> 1);
    int comp = ((mr >> 3) & 1) | ((kc >> 3) << 1);
    uint32_t h, l; packhl(v, h, l);
    size_t off = (fa*32 + lane)*4 + comp;
    dH[off] = h; dL[off] = l;
}

// Banded attention, split-d, 256 threads per 128 q's of one (b,h).
__global__ __launch_bounds__(256)
void attn3(const float* __restrict__ qkv, float* __restrict__ probs)
{
    extern __shared__ float sh[];
    float* Ks = sh;                    // [134][68]
    float* Vs = sh + 134*68;           // [134][68]
    float* Pp = sh + 2*134*68;         // [2][128][9]

    const int t  = threadIdx.x;
    const int tq = t & 127;
    const int half = t >> 7;
    const int q0 = blockIdx.x * 128;
    const int h  = blockIdx.y;
    const int b  = blockIdx.z;

    for (int i = t; i < 134*16; i += 256) {
        int r = i >> 4, d4 = i & 15;
        int row = q0 - 3 + r;
        float4 kv = make_float4(0.f,0.f,0.f,0.f), vv = kv;
        if ((unsigned)row < SS) {
            size_t base = (size_t)(b*SS + row)*NQKV + h*64 + d4*4;
            kv = *(const float4*)&qkv[base + 512];
            vv = *(const float4*)&qkv[base + 1024];
        }
        *(float4*)&Ks[r*68 + d4*4] = kv;
        *(float4*)&Vs[r*68 + d4*4] = vv;
    }
    __syncthreads();

    const int q = q0 + tq;
    const int dbase = half*32;
    float sc[7] = {0.f,0.f,0.f,0.f,0.f,0.f,0.f};
    const float* Qrow = &qkv[(size_t)(b*SS + q)*NQKV + h*64 + dbase];
    #pragma unroll
    for (int d4 = 0; d4 < 8; d4++) {
        float4 qv = *(const float4*)&Qrow[d4*4];
        #pragma unroll
        for (int j = 0; j < 7; j++) {
            float4 kk = *(const float4*)&Ks[(tq + j)*68 + dbase + d4*4];
            sc[j] += qv.x*kk.x + qv.y*kk.y + qv.z*kk.z + qv.w*kk.w;
        }
    }
    float* prow_s = &Pp[(half*128 + tq)*9];
    #pragma unroll
    for (int j = 0; j < 7; j++) prow_s[j] = sc[j];
    __syncthreads();
    #pragma unroll
    for (int j = 0; j < 7; j++)
        sc[j] = Pp[tq*9 + j] + Pp[(128 + tq)*9 + j];

    float mx = -1e30f;
    #pragma unroll
    for (int j = 0; j < 7; j++) {
        sc[j] *= 0.125f;
        if ((unsigned)(q - 3 + j) < SS) mx = fmaxf(mx, sc[j]);
    }
    float p[7], sum = 0.f;
    #pragma unroll
    for (int j = 0; j < 7; j++) {
        p[j] = ((unsigned)(q - 3 + j) < SS) ? expf(sc[j] - mx) : 0.f;
        sum += p[j];
    }
    float inv = 1.0f / sum;
    #pragma unroll
    for (int j = 0; j < 7; j++) p[j] *= inv;

    uint32_t* dH = (uint32_t*)g_oh;
    uint32_t* dL = (uint32_t*)g_ol;
    const int m = b*SS + q;
    #pragma unroll
    for (int d4 = 0; d4 < 8; d4++) {
        float4 o = make_float4(0.f,0.f,0.f,0.f);
        #pragma unroll
        for (int j = 0; j < 7; j++) {
            float4 vv = *(const float4*)&Vs[(tq + j)*68 + dbase + d4*4];
            o.x += p[j]*vv.x; o.y += p[j]*vv.y; o.z += p[j]*vv.z; o.w += p[j]*vv.w;
        }
        int c = h*64 + dbase + d4*4;
        st_frag(dH, dL, m, c,     make_float2(o.x, o.y));
        st_frag(dH, dL, m, c + 2, make_float2(o.z, o.w));
    }

    if (half == 0) {
        float* prow = &probs[((size_t)(b*HH + h)*SS + q)*8];
        *(float4*)&prow[0] = make_float4(p[0], p[1], p[2], p[3]);
        *(float4*)&prow[4] = make_float4(p[4], p[5], p[6], 0.f);
    }
}

// ---------------------------------------------------------------------------
__global__ __launch_bounds__(256)
void band_write(const float* __restrict__ probs, float* __restrict__ attn_out) {
    int idx = blockIdx.x * blockDim.x + threadIdx.x;
    if (idx >= BB*HH*SS) return;
    int q = idx & (SS - 1);
    const float* prow = &probs[(size_t)idx * 8];
    float4 p03 = *(const float4*)&prow[0];
    float4 p46 = *(const float4*)&prow[4];
    float p[7] = {p03.x, p03.y, p03.z, p03.w, p46.x, p46.y, p46.z};
    float* arow = attn_out + (size_t)idx * SS;
    #pragma unroll
    for (int j = 0; j < 7; j++) {
        int k = q - 3 + j;
        if ((unsigned)k < SS) arow[k] = p[j];
    }
}

// ---------------------------------------------------------------------------
__global__ __launch_bounds__(128)
void ln2(const float* __restrict__ y0, const float* __restrict__ gw,
         const float* __restrict__ bt, float* __restrict__ out)
{
    const int m = blockIdx.x, t = threadIdx.x;
    float4 v = ((const float4*)(y0 + (size_t)m*DD))[t];
    float s  = v.x + v.y + v.z + v.w;
    float sq = v.x*v.x + v.y*v.y + v.z*v.z + v.w*v.w;
    #pragma unroll
    for (int o = 16; o; o >>= 1) {
        s  += __shfl_xor_sync(0xffffffffu, s,  o);
        sq += __shfl_xor_sync(0xffffffffu, sq, o);
    }
    __shared__ float ss[4], qq[4];
    int w = t >> 5;
    if ((t & 31) == 0) { ss[w] = s; qq[w] = sq; }
    __syncthreads();
    s  = ss[0] + ss[1] + ss[2] + ss[3];
    sq = qq[0] + qq[1] + qq[2] + qq[3];
    float mean = s * (1.0f/DD);
    float var  = sq * (1.0f/DD) - mean*mean;
    float rstd = rsqrtf(var + 1e-5f);
    float4 gg = ((const float4*)gw)[t];
    float4 bb = ((const float4*)bt)[t];
    float4 r;
    r.x = (v.x - mean)*rstd*gg.x + bb.x;
    r.y = (v.y - mean)*rstd*gg.y + bb.y;
    r.z = (v.z - mean)*rstd*gg.z + bb.z;
    r.w = (v.w - mean)*rstd*gg.w + bb.w;
    ((float4*)(out + (size_t)m*DD))[t] = r;
}

// ---------------------------------------------------------------------------
extern "C" void kernel_launch(void* const* d_in, const int* in_sizes, int n_in,
                              void* d_out, int out_size) {
    const float* x    = (const float*)d_in[0];
    const float* wq_w = (const float*)d_in[2];
    const float* wq_b = (const float*)d_in[3];
    const float* wk_w = (const float*)d_in[4];
    const float* wk_b = (const float*)d_in[5];
    const float* wv_w = (const float*)d_in[6];
    const float* wv_b = (const float*)d_in[7];
    const float* wo_w = (const float*)d_in[8];
    const float* wo_b = (const float*)d_in[9];
    const float* ln_g = (const float*)d_in[10];
    const float* ln_b = (const float*)d_in[11];
    const float* pe   = (const float*)d_in[12];

    float* y_out    = (float*)d_out;
    float* attn_out = (float*)d_out + YELEMS;

    static uint4 *p_ah, *p_al, *p_oh, *p_ol;
    static uint2 *p_bh, *p_bl;
    static float *p_qkv, *p_y0, *p_probs;
    static cudaStream_t s2;
    static cudaEvent_t evF, evZ, evA, evB;
    static bool init = false;
    if (!init) {
        cudaGetSymbolAddress((void**)&p_ah, g_ah);
        cudaGetSymbolAddress((void**)&p_al, g_al);
        cudaGetSymbolAddress((void**)&p_bh, g_bh);
        cudaGetSymbolAddress((void**)&p_bl, g_bl);
        cudaGetSymbolAddress((void**)&p_oh, g_oh);
        cudaGetSymbolAddress((void**)&p_ol, g_ol);
        cudaGetSymbolAddress((void**)&p_qkv,   g_qkv);
        cudaGetSymbolAddress((void**)&p_y0,    g_y0);
        cudaGetSymbolAddress((void**)&p_probs, g_probs);
        int prLo = 0, prHi = 0;
        cudaDeviceGetStreamPriorityRange(&prLo, &prHi);   // prLo = LEAST urgent
        cudaStreamCreateWithPriority(&s2, cudaStreamNonBlocking, prLo);
        cudaEventCreateWithFlags(&evF, cudaEventDisableTiming);
        cudaEventCreateWithFlags(&evZ, cudaEventDisableTiming);
        cudaEventCreateWithFlags(&evA, cudaEventDisableTiming);
        cudaEventCreateWithFlags(&evB, cudaEventDisableTiming);
        cudaFuncSetAttribute(attn3, cudaFuncAttributeMaxDynamicSharedMemorySize, ATTN_SMEM);
        cudaFuncSetAttribute(gemm_cp<8>, cudaFuncAttributeMaxDynamicSharedMemorySize, 3*(2*8*1024 + 16384));
        cudaFuncSetAttribute(gemm_cp<4>, cudaFuncAttributeMaxDynamicSharedMemorySize, 3*(2*4*1024 + 16384));
        init = true;
    }

    // fork: zero the 268MB attn output on a LOW-PRIORITY stream so the
    // compute chain's CTAs win SM slots and the write drains into gaps.
    cudaEventRecord(evF, 0);
    cudaStreamWaitEvent(s2, evF, 0);
    zero_fill<<<2048, 256, 0, s2>>>((float4*)attn_out);

    // main chain
    prep_w <<<8192*32/256, 256>>>(wq_w, wk_w, wv_w, wo_w);
    prep_xp<<<8192*32/256, 256>>>(x, pe);

    gemm_cp<8><<<dim3(NQKV/128, MM/128), 256, 3*(2*8*1024 + 16384)>>>(
        p_ah, p_al, (const uint4*)p_bh, (const uint4*)p_bl, 0,
        wq_b, wk_b, wv_b, nullptr, p_qkv, NQKV);

    attn3<<<dim3(SS/128, HH, BB), 256, ATTN_SMEM>>>(p_qkv, p_probs);
    cudaEventRecord(evA, 0);                       // probs ready

    // band_write on side stream: needs zero_fill done (program order on s2)
    // and probs ready (evA); overlaps gemm2 + ln2.
    cudaStreamWaitEvent(s2, evA, 0);
    band_write<<<(BB*HH*SS + 255)/256, 256, 0, s2>>>(p_probs, attn_out);
    cudaEventRecord(evB, s2);

    gemm_cp<4><<<dim3(DD/128, MM/64), 256, 3*(2*4*1024 + 16384)>>>(
        p_oh, p_ol, (const uint4*)p_bh, (const uint4*)p_bl, 192,
        wo_b, wo_b, wo_b, x, p_y0, DD);

    ln2<<<MM, 128>>>(p_y0, ln_g, ln_b, y_out);

    // join side stream before capture ends
    cudaStreamWaitEvent(0, evB, 0);
}

// round 15
// speedup vs baseline: 1.6924x; 1.0139x over previous
#include <cuda_runtime.h>
#include <cuda_bf16.h>
#include <cstdint>

#define BB   2
#define SS   2048
#define DD   512
#define HH   8
#define MM   (BB*SS)        // 4096
#define NQKV 1536
#define KK   512
#define YELEMS ((size_t)MM*DD)
#define ATTN_ELEMS ((size_t)BB*HH*SS*SS)
#define ATTN_SMEM ((134*68*2 + 2*128*9)*4)

// Frag-packed buffers
__device__ uint4 g_ah[8192*32], g_al[8192*32];   // x+pe hi/lo, frag-packed
__device__ uint4 g_bhl[8192*32];                 // [wq;wk;wv;wo] {h0,h1,l0,l1} per (frag,lane)
__device__ uint4 g_oh[8192*32], g_ol[8192*32];   // attn output hi/lo, frag-packed
__device__ float g_qkv[(size_t)MM*NQKV];
__device__ float g_y0[MM*DD];
__device__ float g_probs[(size_t)BB*HH*SS*8];

// ---------------------------------------------------------------------------
__device__ __forceinline__ void packhl(float2 v, uint32_t& h, uint32_t& l) {
    __nv_bfloat162 hb = __floats2bfloat162_rn(v.x, v.y);
    h = *reinterpret_cast<uint32_t*>(&hb);
    float hx = __bfloat162float(hb.x), hy = __bfloat162float(hb.y);
    __nv_bfloat162 lb = __floats2bfloat162_rn(v.x - hx, v.y - hy);
    l = *reinterpret_cast<uint32_t*>(&lb);
}
__device__ __forceinline__ void mma16(float* c, const uint32_t* a, uint32_t b0, uint32_t b1) {
    asm volatile(
      "mma.sync.aligned.m16n8k16.row.col.f32.bf16.bf16.f32 "
      "{%0,%1,%2,%3},{%4,%5,%6,%7},{%8,%9},{%0,%1,%2,%3};"
      : "+f"(c[0]), "+f"(c[1]), "+f"(c[2]), "+f"(c[3])
      : "r"(a[0]), "r"(a[1]), "r"(a[2]), "r"(a[3]), "r"(b0), "r"(b1));
}
__device__ __forceinline__ uint32_t smem_u32(const void* p) {
    uint32_t a;
    asm("{ .reg .u64 t; cvta.to.shared.u64 t, %1; cvt.u32.u64 %0, t; }" : "=r"(a) : "l"(p));
    return a;
}
__device__ __forceinline__ void cp16(uint32_t dst, const void* src) {
    asm volatile("cp.async.cg.shared.global [%0], [%1], 16;" :: "r"(dst), "l"(src));
}

// ---------------------------------------------------------------------------
__global__ __launch_bounds__(256)
void zero_fill(float4* __restrict__ p) {
    const float4 z = make_float4(0.f, 0.f, 0.f, 0.f);
    size_t base = (size_t)blockIdx.x * (256*32) + threadIdx.x;
    #pragma unroll
    for (int i = 0; i < 32; i++) __stcs(&p[base + (size_t)i*256], z);
}

// ---------------------------------------------------------------------------
__global__ __launch_bounds__(256)
void prep_xp(const float* __restrict__ x, const float* __restrict__ pe) {
    int gid = blockIdx.x * 256 + threadIdx.x;   // 8192*32
    if (gid >= 8192*32) return;
    int lane = gid & 31, fa = gid >> 5;
    int kblk = fa & 31, mblk = fa >> 5;
    int g = lane >> 2, tg = lane & 3;
    int r0 = mblk*16 + g, c0 = kblk*16 + tg*2;
    int s0 = r0 & (SS-1), s1 = (r0+8) & (SS-1);
    float2 v0 = *(const float2*)(x + (size_t)r0*KK + c0);
    float2 v1 = *(const float2*)(x + (size_t)(r0+8)*KK + c0);
    float2 v2 = *(const float2*)(x + (size_t)r0*KK + c0 + 8);
    float2 v3 = *(const float2*)(x + (size_t)(r0+8)*KK + c0 + 8);
    float2 e;
    e = *(const float2*)(pe + (size_t)s0*KK + c0);     v0.x += e.x; v0.y += e.y;
    e = *(const float2*)(pe + (size_t)s1*KK + c0);     v1.x += e.x; v1.y += e.y;
    e = *(const float2*)(pe + (size_t)s0*KK + c0 + 8); v2.x += e.x; v2.y += e.y;
    e = *(const float2*)(pe + (size_t)s1*KK + c0 + 8); v3.x += e.x; v3.y += e.y;
    uint4 hv, lv;
    packhl(v0, hv.x, lv.x); packhl(v1, hv.y, lv.y);
    packhl(v2, hv.z, lv.z); packhl(v3, hv.w, lv.w);
    g_ah[gid] = hv; g_al[gid] = lv;
}

// prep: weights -> {h0,h1,l0,l1} uint4 per (frag, lane)
__global__ __launch_bounds__(256)
void prep_w(const float* __restrict__ wq, const float* __restrict__ wk,
            const float* __restrict__ wv, const float* __restrict__ wo) {
    int gid = blockIdx.x * 256 + threadIdx.x;   // 8192*32
    if (gid >= 8192*32) return;
    int lane = gid & 31, fb = gid >> 5;
    int kblk = fb & 31, nblk = fb >> 5;
    int n = nblk*8 + (lane >> 2);
    int c0 = kblk*16 + (lane & 3)*2;
    const float* row = (n < 512)  ? wq + (size_t)n*KK
                     : (n < 1024) ? wk + (size_t)(n-512)*KK
                     : (n < 1536) ? wv + (size_t)(n-1024)*KK
                                  : wo + (size_t)(n-1536)*KK;
    float2 u0 = *(const float2*)(row + c0);
    float2 u1 = *(const float2*)(row + c0 + 8);
    uint4 o;
    packhl(u0, o.x, o.z); packhl(u1, o.y, o.w);   // {h0, h1, l0, l1}
    g_bhl[gid] = o;
}

// ---------------------------------------------------------------------------
// bf16x3 GEMM, frag-packed inputs, 3-stage cp.async pipeline, ONE sync/stage.
// B staged as uint4 {h0,h1,l0,l1} per (frag,lane): one LDS.128 feeds HH+HL.
// Stage layout: [AH: MF*1024][AL: MF*1024][BHL: 16384]
template<int MF>
__global__ __launch_bounds__(256, 2)
void gemm_cp(const uint4* __restrict__ Ah, const uint4* __restrict__ Al,
             const uint4* __restrict__ Bhl,
             int nblk_base,
             const float* __restrict__ bi0, const float* __restrict__ bi1,
             const float* __restrict__ bi2,
             const float* __restrict__ res, float* __restrict__ C, int ldc)
{
    extern __shared__ __align__(16) char smem[];
    constexpr int A_BYTES = MF*64*16;          // MF*1024
    constexpr int STAGE   = 2*A_BYTES + 16384;
    const uint32_t sb = smem_u32(smem);

    const int t = threadIdx.x, lane = t & 31, w = t >> 5;
    const int g = lane >> 2, tg = lane & 3;
    const int mblk0 = blockIdx.y * MF;
    const int bn = blockIdx.x * 128;
    const int nblk0 = nblk_base + blockIdx.x * 16;
    const int seg = bn >> 9;
    const float* bi = (seg == 0) ? bi0 : (seg == 1) ? bi1 : bi2;
    constexpr int MPW = MF/4;
    const int wmt = (w & 3)*MPW, wnt = (w >> 2)*8;

    float acc[MPW][8][4] = {};

    auto issue = [&](int st) {
        const int kb = st*2;
        const uint32_t base = sb + (st % 3)*STAGE;
        #pragma unroll
        for (int i = 0; i < MF/4; i++) {
            int s = t + 256*i;
            int sfr = s >> 5, ln = s & 31;
            int mt = sfr >> 1, kt = sfr & 1;
            size_t fa = ((size_t)(mblk0 + mt)*32 + kb + kt)*32 + ln;
            cp16(base + s*16,           Ah + fa);
            cp16(base + A_BYTES + s*16, Al + fa);
        }
        #pragma unroll
        for (int i = 0; i < 4; i++) {
            int s = t + 256*i;                     // 1024 uint4s
            int sfr = s >> 5, ln = s & 31;
            int nt = sfr >> 1, kt = sfr & 1;
            size_t fb = ((size_t)(nblk0 + nt)*32 + kb + kt)*32 + ln;
            cp16(base + 2*A_BYTES + s*16, Bhl + fb);
        }
        asm volatile("cp.async.commit_group;");
    };

    issue(0);
    issue(1);
    for (int s = 0; s < 16; s++) {
        if (s < 15) asm volatile("cp.async.wait_group 1;");
        else        asm volatile("cp.async.wait_group 0;");
        __syncthreads();

        const char* stg = smem + (s % 3)*STAGE;
        const uint4* AsH = (const uint4*)stg;
        const uint4* AsL = (const uint4*)(stg + A_BYTES);
        const uint4* Bs  = (const uint4*)(stg + 2*A_BYTES);

        #pragma unroll
        for (int kt = 0; kt < 2; kt++) {
            uint4 ah[MPW], al[MPW], bhl[8];
            #pragma unroll
            for (int m = 0; m < MPW; m++) ah[m] = AsH[((wmt+m)*2 + kt)*32 + lane];
            #pragma unroll
            for (int n = 0; n < 8; n++) bhl[n] = Bs[((wnt+n)*2 + kt)*32 + lane];
            #pragma unroll
            for (int m = 0; m < MPW; m++)
                #pragma unroll
                for (int n = 0; n < 8; n++)
                    mma16(acc[m][n], (const uint32_t*)&ah[m], bhl[n].x, bhl[n].y);
            #pragma unroll
            for (int m = 0; m < MPW; m++)
                #pragma unroll
                for (int n = 0; n < 8; n++)
                    mma16(acc[m][n], (const uint32_t*)&ah[m], bhl[n].z, bhl[n].w);
            #pragma unroll
            for (int m = 0; m < MPW; m++) al[m] = AsL[((wmt+m)*2 + kt)*32 + lane];
            #pragma unroll
            for (int m = 0; m < MPW; m++)
                #pragma unroll
                for (int n = 0; n < 8; n++)
                    mma16(acc[m][n], (const uint32_t*)&al[m], bhl[n].x, bhl[n].y);
        }

        if (s + 2 < 16) issue(s + 2);
    }

    #pragma unroll
    for (int m = 0; m < MPW; m++) {
        const int gm = mblk0*16 + (wmt + m)*16 + g;
        #pragma unroll
        for (int n = 0; n < 8; n++) {
            const int gn = bn + (wnt + n)*8 + tg*2;
            const int gl = gn & 511;
            float c0 = acc[m][n][0] + bi[gl];
            float c1 = acc[m][n][1] + bi[gl + 1];
            float c2 = acc[m][n][2] + bi[gl];
            float c3 = acc[m][n][3] + bi[gl + 1];
            if (res) {
                c0 += res[(size_t)gm*ldc + gn];
                c1 += res[(size_t)gm*ldc + gn + 1];
                c2 += res[(size_t)(gm+8)*ldc + gn];
                c3 += res[(size_t)(gm+8)*ldc + gn + 1];
            }
            *(float2*)&C[(size_t)gm*ldc + gn]     = make_float2(c0, c1);
            *(float2*)&C[(size_t)(gm+8)*ldc + gn] = make_float2(c2, c3);
        }
    }
}

// ---------------------------------------------------------------------------
__device__ __forceinline__ void st_frag(uint32_t* dH, uint32_t* dL,
                                        int m, int c, float2 v) {
    size_t fa = ((size_t)(m >> 4))*32 + (c >> 4);
    int mr = m & 15, kc = c & 15;
    int lane = (mr & 7)*4 + ((kc & 7) >> 1);
    int comp = ((mr >> 3) & 1) | ((kc >> 3) << 1);
    uint32_t h, l; packhl(v, h, l);
    size_t off = (fa*32 + lane)*4 + comp;
    dH[off] = h; dL[off] = l;
}

// Banded attention, split-d, 256 threads per 128 q's of one (b,h).
__global__ __launch_bounds__(256)
void attn3(const float* __restrict__ qkv, float* __restrict__ probs)
{
    extern __shared__ float sh[];
    float* Ks = sh;                    // [134][68]
    float* Vs = sh + 134*68;           // [134][68]
    float* Pp = sh + 2*134*68;         // [2][128][9]

    const int t  = threadIdx.x;
    const int tq = t & 127;
    const int half = t >> 7;
    const int q0 = blockIdx.x * 128;
    const int h  = blockIdx.y;
    const int b  = blockIdx.z;

    for (int i = t; i < 134*16; i += 256) {
        int r = i >> 4, d4 = i & 15;
        int row = q0 - 3 + r;
        float4 kv = make_float4(0.f,0.f,0.f,0.f), vv = kv;
        if ((unsigned)row < SS) {
            size_t base = (size_t)(b*SS + row)*NQKV + h*64 + d4*4;
            kv = *(const float4*)&qkv[base + 512];
            vv = *(const float4*)&qkv[base + 1024];
        }
        *(float4*)&Ks[r*68 + d4*4] = kv;
        *(float4*)&Vs[r*68 + d4*4] = vv;
    }
    __syncthreads();

    const int q = q0 + tq;
    const int dbase = half*32;
    float sc[7] = {0.f,0.f,0.f,0.f,0.f,0.f,0.f};
    const float* Qrow = &qkv[(size_t)(b*SS + q)*NQKV + h*64 + dbase];
    #pragma unroll
    for (int d4 = 0; d4 < 8; d4++) {
        float4 qv = *(const float4*)&Qrow[d4*4];
        #pragma unroll
        for (int j = 0; j < 7; j++) {
            float4 kk = *(const float4*)&Ks[(tq + j)*68 + dbase + d4*4];
            sc[j] += qv.x*kk.x + qv.y*kk.y + qv.z*kk.z + qv.w*kk.w;
        }
    }
    float* prow_s = &Pp[(half*128 + tq)*9];
    #pragma unroll
    for (int j = 0; j < 7; j++) prow_s[j] = sc[j];
    __syncthreads();
    #pragma unroll
    for (int j = 0; j < 7; j++)
        sc[j] = Pp[tq*9 + j] + Pp[(128 + tq)*9 + j];

    float mx = -1e30f;
    #pragma unroll
    for (int j = 0; j < 7; j++) {
        sc[j] *= 0.125f;
        if ((unsigned)(q - 3 + j) < SS) mx = fmaxf(mx, sc[j]);
    }
    float p[7], sum = 0.f;
    #pragma unroll
    for (int j = 0; j < 7; j++) {
        p[j] = ((unsigned)(q - 3 + j) < SS) ? expf(sc[j] - mx) : 0.f;
        sum += p[j];
    }
    float inv = 1.0f / sum;
    #pragma unroll
    for (int j = 0; j < 7; j++) p[j] *= inv;

    uint32_t* dH = (uint32_t*)g_oh;
    uint32_t* dL = (uint32_t*)g_ol;
    const int m = b*SS + q;
    #pragma unroll
    for (int d4 = 0; d4 < 8; d4++) {
        float4 o = make_float4(0.f,0.f,0.f,0.f);
        #pragma unroll
        for (int j = 0; j < 7; j++) {
            float4 vv = *(const float4*)&Vs[(tq + j)*68 + dbase + d4*4];
            o.x += p[j]*vv.x; o.y += p[j]*vv.y; o.z += p[j]*vv.z; o.w += p[j]*vv.w;
        }
        int c = h*64 + dbase + d4*4;
        st_frag(dH, dL, m, c,     make_float2(o.x, o.y));
        st_frag(dH, dL, m, c + 2, make_float2(o.z, o.w));
    }

    if (half == 0) {
        float* prow = &probs[((size_t)(b*HH + h)*SS + q)*8];
        *(float4*)&prow[0] = make_float4(p[0], p[1], p[2], p[3]);
        *(float4*)&prow[4] = make_float4(p[4], p[5], p[6], 0.f);
    }
}

// ---------------------------------------------------------------------------
__global__ __launch_bounds__(256)
void band_write(const float* __restrict__ probs, float* __restrict__ attn_out) {
    int idx = blockIdx.x * blockDim.x + threadIdx.x;
    if (idx >= BB*HH*SS) return;
    int q = idx & (SS - 1);
    const float* prow = &probs[(size_t)idx * 8];
    float4 p03 = *(const float4*)&prow[0];
    float4 p46 = *(const float4*)&prow[4];
    float p[7] = {p03.x, p03.y, p03.z, p03.w, p46.x, p46.y, p46.z};
    float* arow = attn_out + (size_t)idx * SS;
    #pragma unroll
    for (int j = 0; j < 7; j++) {
        int k = q - 3 + j;
        if ((unsigned)k < SS) arow[k] = p[j];
    }
}

// ---------------------------------------------------------------------------
__global__ __launch_bounds__(128)
void ln2(const float* __restrict__ y0, const float* __restrict__ gw,
         const float* __restrict__ bt, float* __restrict__ out)
{
    const int m = blockIdx.x, t = threadIdx.x;
    float4 v = ((const float4*)(y0 + (size_t)m*DD))[t];
    float s  = v.x + v.y + v.z + v.w;
    float sq = v.x*v.x + v.y*v.y + v.z*v.z + v.w*v.w;
    #pragma unroll
    for (int o = 16; o; o >>= 1) {
        s  += __shfl_xor_sync(0xffffffffu, s,  o);
        sq += __shfl_xor_sync(0xffffffffu, sq, o);
    }
    __shared__ float ss[4], qq[4];
    int w = t >> 5;
    if ((t & 31) == 0) { ss[w] = s; qq[w] = sq; }
    __syncthreads();
    s  = ss[0] + ss[1] + ss[2] + ss[3];
    sq = qq[0] + qq[1] + qq[2] + qq[3];
    float mean = s * (1.0f/DD);
    float var  = sq * (1.0f/DD) - mean*mean;
    float rstd = rsqrtf(var + 1e-5f);
    float4 gg = ((const float4*)gw)[t];
    float4 bb = ((const float4*)bt)[t];
    float4 r;
    r.x = (v.x - mean)*rstd*gg.x + bb.x;
    r.y = (v.y - mean)*rstd*gg.y + bb.y;
    r.z = (v.z - mean)*rstd*gg.z + bb.z;
    r.w = (v.w - mean)*rstd*gg.w + bb.w;
    ((float4*)(out + (size_t)m*DD))[t] = r;
}

// ---------------------------------------------------------------------------
extern "C" void kernel_launch(void* const* d_in, const int* in_sizes, int n_in,
                              void* d_out, int out_size) {
    const float* x    = (const float*)d_in[0];
    const float* wq_w = (const float*)d_in[2];
    const float* wq_b = (const float*)d_in[3];
    const float* wk_w = (const float*)d_in[4];
    const float* wk_b = (const float*)d_in[5];
    const float* wv_w = (const float*)d_in[6];
    const float* wv_b = (const float*)d_in[7];
    const float* wo_w = (const float*)d_in[8];
    const float* wo_b = (const float*)d_in[9];
    const float* ln_g = (const float*)d_in[10];
    const float* ln_b = (const float*)d_in[11];
    const float* pe   = (const float*)d_in[12];

    float* y_out    = (float*)d_out;
    float* attn_out = (float*)d_out + YELEMS;

    static uint4 *p_ah, *p_al, *p_bhl, *p_oh, *p_ol;
    static float *p_qkv, *p_y0, *p_probs;
    static cudaStream_t s2, s3;
    static cudaEvent_t evF, evW, evA, evB;
    static bool init = false;
    if (!init) {
        cudaGetSymbolAddress((void**)&p_ah,  g_ah);
        cudaGetSymbolAddress((void**)&p_al,  g_al);
        cudaGetSymbolAddress((void**)&p_bhl, g_bhl);
        cudaGetSymbolAddress((void**)&p_oh,  g_oh);
        cudaGetSymbolAddress((void**)&p_ol,  g_ol);
        cudaGetSymbolAddress((void**)&p_qkv,   g_qkv);
        cudaGetSymbolAddress((void**)&p_y0,    g_y0);
        cudaGetSymbolAddress((void**)&p_probs, g_probs);
        int prLo = 0, prHi = 0;
        cudaDeviceGetStreamPriorityRange(&prLo, &prHi);
        cudaStreamCreateWithPriority(&s2, cudaStreamNonBlocking, prLo);
        cudaStreamCreateWithFlags(&s3, cudaStreamNonBlocking);
        cudaEventCreateWithFlags(&evF, cudaEventDisableTiming);
        cudaEventCreateWithFlags(&evW, cudaEventDisableTiming);
        cudaEventCreateWithFlags(&evA, cudaEventDisableTiming);
        cudaEventCreateWithFlags(&evB, cudaEventDisableTiming);
        cudaFuncSetAttribute(attn3, cudaFuncAttributeMaxDynamicSharedMemorySize, ATTN_SMEM);
        cudaFuncSetAttribute(gemm_cp<8>, cudaFuncAttributeMaxDynamicSharedMemorySize, 3*(2*8*1024 + 16384));
        cudaFuncSetAttribute(gemm_cp<4>, cudaFuncAttributeMaxDynamicSharedMemorySize, 3*(2*4*1024 + 16384));
        init = true;
    }

    // fork: zero 268MB attn output on LOW-PRIORITY stream
    cudaEventRecord(evF, 0);
    cudaStreamWaitEvent(s2, evF, 0);
    zero_fill<<<2048, 256, 0, s2>>>((float4*)attn_out);

    // prep_w concurrent with prep_xp (independent)
    cudaStreamWaitEvent(s3, evF, 0);
    prep_w<<<8192*32/256, 256, 0, s3>>>(wq_w, wk_w, wv_w, wo_w);
    cudaEventRecord(evW, s3);

    prep_xp<<<8192*32/256, 256>>>(x, pe);
    cudaStreamWaitEvent(0, evW, 0);   // join prep_w before gemm1

    gemm_cp<8><<<dim3(NQKV/128, MM/128), 256, 3*(2*8*1024 + 16384)>>>(
        p_ah, p_al, p_bhl, 0,
        wq_b, wk_b, wv_b, nullptr, p_qkv, NQKV);

    attn3<<<dim3(SS/128, HH, BB), 256, ATTN_SMEM>>>(p_qkv, p_probs);
    cudaEventRecord(evA, 0);          // probs ready

    // band_write on side stream (after zero_fill by program order + probs)
    cudaStreamWaitEvent(s2, evA, 0);
    band_write<<<(BB*HH*SS + 255)/256, 256, 0, s2>>>(p_probs, attn_out);
    cudaEventRecord(evB, s2);

    gemm_cp<4><<<dim3(DD/128, MM/64), 256, 3*(2*4*1024 + 16384)>>>(
        p_oh, p_ol, p_bhl, 192,
        wo_b, wo_b, wo_b, x, p_y0, DD);

    ln2<<<MM, 128>>>(p_y0, ln_g, ln_b, y_out);

    cudaStreamWaitEvent(0, evB, 0);
}

// round 16
// speedup vs baseline: 1.8750x; 1.1079x over previous
#include <cuda_runtime.h>
#include <cuda_bf16.h>
#include <cstdint>

#define BB   2
#define SS   2048
#define DD   512
#define HH   8
#define MM   (BB*SS)        // 4096
#define NQKV 1536
#define KK   512
#define YELEMS ((size_t)MM*DD)
#define ATTN_ELEMS ((size_t)BB*HH*SS*SS)
#define ATTN_F4 (ATTN_ELEMS/4)          // 16,777,216 float4s
#define ATTN_SMEM ((134*68*2 + 2*128*9)*4)

// Frag-packed buffers
__device__ uint4 g_ah[8192*32], g_al[8192*32];   // x+pe hi/lo, frag-packed
__device__ uint2 g_bh[8192*32], g_bl[8192*32];   // [wq;wk;wv;wo] hi/lo, frag-packed
__device__ uint4 g_oh[8192*32], g_ol[8192*32];   // attn output hi/lo, frag-packed
__device__ float g_qkv[(size_t)MM*NQKV];
__device__ float g_y0[MM*DD];
__device__ float g_probs[(size_t)BB*HH*SS*8];

// ---------------------------------------------------------------------------
__device__ __forceinline__ void packhl(float2 v, uint32_t& h, uint32_t& l) {
    __nv_bfloat162 hb = __floats2bfloat162_rn(v.x, v.y);
    h = *reinterpret_cast<uint32_t*>(&hb);
    float hx = __bfloat162float(hb.x), hy = __bfloat162float(hb.y);
    __nv_bfloat162 lb = __floats2bfloat162_rn(v.x - hx, v.y - hy);
    l = *reinterpret_cast<uint32_t*>(&lb);
}
__device__ __forceinline__ void mma16(float* c, const uint32_t* a, const uint32_t* b) {
    asm volatile(
      "mma.sync.aligned.m16n8k16.row.col.f32.bf16.bf16.f32 "
      "{%0,%1,%2,%3},{%4,%5,%6,%7},{%8,%9},{%0,%1,%2,%3};"
      : "+f"(c[0]), "+f"(c[1]), "+f"(c[2]), "+f"(c[3])
      : "r"(a[0]), "r"(a[1]), "r"(a[2]), "r"(a[3]), "r"(b[0]), "r"(b[1]));
}
__device__ __forceinline__ uint32_t smem_u32(const void* p) {
    uint32_t a;
    asm("{ .reg .u64 t; cvta.to.shared.u64 t, %1; cvt.u32.u64 %0, t; }" : "=r"(a) : "l"(p));
    return a;
}
__device__ __forceinline__ void cp16(uint32_t dst, const void* src) {
    asm volatile("cp.async.cg.shared.global [%0], [%1], 16;" :: "r"(dst), "l"(src));
}

// ---------------------------------------------------------------------------
__global__ __launch_bounds__(256)
void prep_xp(const float* __restrict__ x, const float* __restrict__ pe) {
    int gid = blockIdx.x * 256 + threadIdx.x;   // 8192*32
    if (gid >= 8192*32) return;
    int lane = gid & 31, fa = gid >> 5;
    int kblk = fa & 31, mblk = fa >> 5;
    int g = lane >> 2, tg = lane & 3;
    int r0 = mblk*16 + g, c0 = kblk*16 + tg*2;
    int s0 = r0 & (SS-1), s1 = (r0+8) & (SS-1);
    float2 v0 = *(const float2*)(x + (size_t)r0*KK + c0);
    float2 v1 = *(const float2*)(x + (size_t)(r0+8)*KK + c0);
    float2 v2 = *(const float2*)(x + (size_t)r0*KK + c0 + 8);
    float2 v3 = *(const float2*)(x + (size_t)(r0+8)*KK + c0 + 8);
    float2 e;
    e = *(const float2*)(pe + (size_t)s0*KK + c0);     v0.x += e.x; v0.y += e.y;
    e = *(const float2*)(pe + (size_t)s1*KK + c0);     v1.x += e.x; v1.y += e.y;
    e = *(const float2*)(pe + (size_t)s0*KK + c0 + 8); v2.x += e.x; v2.y += e.y;
    e = *(const float2*)(pe + (size_t)s1*KK + c0 + 8); v3.x += e.x; v3.y += e.y;
    uint4 hv, lv;
    packhl(v0, hv.x, lv.x); packhl(v1, hv.y, lv.y);
    packhl(v2, hv.z, lv.z); packhl(v3, hv.w, lv.w);
    g_ah[gid] = hv; g_al[gid] = lv;
}

__global__ __launch_bounds__(256)
void prep_w(const float* __restrict__ wq, const float* __restrict__ wk,
            const float* __restrict__ wv, const float* __restrict__ wo) {
    int gid = blockIdx.x * 256 + threadIdx.x;   // 8192*32
    if (gid >= 8192*32) return;
    int lane = gid & 31, fb = gid >> 5;
    int kblk = fb & 31, nblk = fb >> 5;
    int n = nblk*8 + (lane >> 2);
    int c0 = kblk*16 + (lane & 3)*2;
    const float* row = (n < 512)  ? wq + (size_t)n*KK
                     : (n < 1024) ? wk + (size_t)(n-512)*KK
                     : (n < 1536) ? wv + (size_t)(n-1024)*KK
                                  : wo + (size_t)(n-1536)*KK;
    float2 u0 = *(const float2*)(row + c0);
    float2 u1 = *(const float2*)(row + c0 + 8);
    uint2 hv, lv;
    packhl(u0, hv.x, lv.x); packhl(u1, hv.y, lv.y);
    g_bh[gid] = hv; g_bl[gid] = lv;
}

// ---------------------------------------------------------------------------
// bf16x3 GEMM, frag-packed inputs, 3-stage cp.async pipeline, ONE sync/stage.
// When zbuf != nullptr (gemm1 only, 384 CTAs), each thread also streams ~171
// float4 zero-stores to zbuf, 11 per stage — hides the 268MB attn zero-write
// inside the GEMM's idle DRAM bandwidth (structural overlap).
template<int MF>
__global__ __launch_bounds__(256, 2)
void gemm_cp(const uint4* __restrict__ Ah, const uint4* __restrict__ Al,
             const uint4* __restrict__ Bh4, const uint4* __restrict__ Bl4,
             int nblk_base,
             const float* __restrict__ bi0, const float* __restrict__ bi1,
             const float* __restrict__ bi2,
             const float* __restrict__ res, float* __restrict__ C, int ldc,
             float4* __restrict__ zbuf)
{
    extern __shared__ __align__(16) char smem[];
    constexpr int A_BYTES = MF*64*16;          // MF*1024
    constexpr int STAGE   = 2*A_BYTES + 16384;
    const uint32_t sb = smem_u32(smem);

    const int t = threadIdx.x, lane = t & 31, w = t >> 5;
    const int g = lane >> 2, tg = lane & 3;
    const int mblk0 = blockIdx.y * MF;
    const int bn = blockIdx.x * 128;
    const int nblk0 = nblk_base + blockIdx.x * 16;
    const int seg = bn >> 9;
    const float* bi = (seg == 0) ? bi0 : (seg == 1) ? bi1 : bi2;
    constexpr int MPW = MF/4;
    const int wmt = (w & 3)*MPW, wnt = (w >> 2)*8;
    const unsigned gtid = (blockIdx.y * gridDim.x + blockIdx.x) * 256 + t;  // < 98304 for gemm1

    float acc[MPW][8][4] = {};

    auto issue = [&](int st) {
        const int kb = st*2;
        const uint32_t base = sb + (st % 3)*STAGE;
        #pragma unroll
        for (int i = 0; i < MF/4; i++) {
            int s = t + 256*i;
            int sfr = s >> 5, ln = s & 31;
            int mt = sfr >> 1, kt = sfr & 1;
            size_t fa = ((size_t)(mblk0 + mt)*32 + kb + kt)*32 + ln;
            cp16(base + s*16,           Ah + fa);
            cp16(base + A_BYTES + s*16, Al + fa);
        }
        #pragma unroll
        for (int i = 0; i < 2; i++) {
            int s = t + 256*i;
            int sfr = s >> 4, lp = s & 15;
            int nt = sfr >> 1, kt = sfr & 1;
            size_t fb = ((size_t)(nblk0 + nt)*32 + kb + kt)*16 + lp;
            cp16(base + 2*A_BYTES + s*16,        Bh4 + fb);
            cp16(base + 2*A_BYTES + 8192 + s*16, Bl4 + fb);
        }
        asm volatile("cp.async.commit_group;");
    };

    issue(0);
    issue(1);
    const float4 z4 = make_float4(0.f, 0.f, 0.f, 0.f);
    for (int s = 0; s < 16; s++) {
        if (s < 15) asm volatile("cp.async.wait_group 1;");
        else        asm volatile("cp.async.wait_group 0;");
        __syncthreads();

        // streamed zero-fill slice (fire-and-forget; overlaps this stage's mma)
        if (zbuf) {
            #pragma unroll
            for (int k = 0; k < 11; k++) {
                unsigned idx = (unsigned)s*11 + k;
                size_t off = (size_t)idx * 98304 + gtid;
                if (idx < 171 && off < ATTN_F4) __stcs(zbuf + off, z4);
            }
        }

        const char* stg = smem + (s % 3)*STAGE;
        const uint4* AsH = (const uint4*)stg;
        const uint4* AsL = (const uint4*)(stg + A_BYTES);
        const uint2* BsH = (const uint2*)(stg + 2*A_BYTES);
        const uint2* BsL = (const uint2*)(stg + 2*A_BYTES + 8192);

        #pragma unroll
        for (int kt = 0; kt < 2; kt++) {
            uint4 ah[MPW], al[MPW];
            uint2 bh[8], bl[8];
            #pragma unroll
            for (int m = 0; m < MPW; m++) ah[m] = AsH[((wmt+m)*2 + kt)*32 + lane];
            #pragma unroll
            for (int n = 0; n < 8; n++) bh[n] = BsH[((wnt+n)*2 + kt)*32 + lane];
            #pragma unroll
            for (int m = 0; m < MPW; m++)
                #pragma unroll
                for (int n = 0; n < 8; n++)
                    mma16(acc[m][n], (const uint32_t*)&ah[m], (const uint32_t*)&bh[n]);
            #pragma unroll
            for (int n = 0; n < 8; n++) bl[n] = BsL[((wnt+n)*2 + kt)*32 + lane];
            #pragma unroll
            for (int m = 0; m < MPW; m++)
                #pragma unroll
                for (int n = 0; n < 8; n++)
                    mma16(acc[m][n], (const uint32_t*)&ah[m], (const uint32_t*)&bl[n]);
            #pragma unroll
            for (int m = 0; m < MPW; m++) al[m] = AsL[((wmt+m)*2 + kt)*32 + lane];
            #pragma unroll
            for (int m = 0; m < MPW; m++)
                #pragma unroll
                for (int n = 0; n < 8; n++)
                    mma16(acc[m][n], (const uint32_t*)&al[m], (const uint32_t*)&bh[n]);
        }

        if (s + 2 < 16) issue(s + 2);
    }

    #pragma unroll
    for (int m = 0; m < MPW; m++) {
        const int gm = mblk0*16 + (wmt + m)*16 + g;
        #pragma unroll
        for (int n = 0; n < 8; n++) {
            const int gn = bn + (wnt + n)*8 + tg*2;
            const int gl = gn & 511;
            float c0 = acc[m][n][0] + bi[gl];
            float c1 = acc[m][n][1] + bi[gl + 1];
            float c2 = acc[m][n][2] + bi[gl];
            float c3 = acc[m][n][3] + bi[gl + 1];
            if (res) {
                c0 += res[(size_t)gm*ldc + gn];
                c1 += res[(size_t)gm*ldc + gn + 1];
                c2 += res[(size_t)(gm+8)*ldc + gn];
                c3 += res[(size_t)(gm+8)*ldc + gn + 1];
            }
            *(float2*)&C[(size_t)gm*ldc + gn]     = make_float2(c0, c1);
            *(float2*)&C[(size_t)(gm+8)*ldc + gn] = make_float2(c2, c3);
        }
    }
}

// ---------------------------------------------------------------------------
__device__ __forceinline__ void st_frag(uint32_t* dH, uint32_t* dL,
                                        int m, int c, float2 v) {
    size_t fa = ((size_t)(m >> 4))*32 + (c >> 4);
    int mr = m & 15, kc = c & 15;
    int lane = (mr & 7)*4 + ((kc & 7) >> 1);
    int comp = ((mr >> 3) & 1) | ((kc >> 3) << 1);
    uint32_t h, l; packhl(v, h, l);
    size_t off = (fa*32 + lane)*4 + comp;
    dH[off] = h; dL[off] = l;
}

// Banded attention, split-d, 256 threads per 128 q's of one (b,h).
__global__ __launch_bounds__(256)
void attn3(const float* __restrict__ qkv, float* __restrict__ probs)
{
    extern __shared__ float sh[];
    float* Ks = sh;                    // [134][68]
    float* Vs = sh + 134*68;           // [134][68]
    float* Pp = sh + 2*134*68;         // [2][128][9]

    const int t  = threadIdx.x;
    const int tq = t & 127;
    const int half = t >> 7;
    const int q0 = blockIdx.x * 128;
    const int h  = blockIdx.y;
    const int b  = blockIdx.z;

    for (int i = t; i < 134*16; i += 256) {
        int r = i >> 4, d4 = i & 15;
        int row = q0 - 3 + r;
        float4 kv = make_float4(0.f,0.f,0.f,0.f), vv = kv;
        if ((unsigned)row < SS) {
            size_t base = (size_t)(b*SS + row)*NQKV + h*64 + d4*4;
            kv = *(const float4*)&qkv[base + 512];
            vv = *(const float4*)&qkv[base + 1024];
        }
        *(float4*)&Ks[r*68 + d4*4] = kv;
        *(float4*)&Vs[r*68 + d4*4] = vv;
    }
    __syncthreads();

    const int q = q0 + tq;
    const int dbase = half*32;
    float sc[7] = {0.f,0.f,0.f,0.f,0.f,0.f,0.f};
    const float* Qrow = &qkv[(size_t)(b*SS + q)*NQKV + h*64 + dbase];
    #pragma unroll
    for (int d4 = 0; d4 < 8; d4++) {
        float4 qv = *(const float4*)&Qrow[d4*4];
        #pragma unroll
        for (int j = 0; j < 7; j++) {
            float4 kk = *(const float4*)&Ks[(tq + j)*68 + dbase + d4*4];
            sc[j] += qv.x*kk.x + qv.y*kk.y + qv.z*kk.z + qv.w*kk.w;
        }
    }
    float* prow_s = &Pp[(half*128 + tq)*9];
    #pragma unroll
    for (int j = 0; j < 7; j++) prow_s[j] = sc[j];
    __syncthreads();
    #pragma unroll
    for (int j = 0; j < 7; j++)
        sc[j] = Pp[tq*9 + j] + Pp[(128 + tq)*9 + j];

    float mx = -1e30f;
    #pragma unroll
    for (int j = 0; j < 7; j++) {
        sc[j] *= 0.125f;
        if ((unsigned)(q - 3 + j) < SS) mx = fmaxf(mx, sc[j]);
    }
    float p[7], sum = 0.f;
    #pragma unroll
    for (int j = 0; j < 7; j++) {
        p[j] = ((unsigned)(q - 3 + j) < SS) ? expf(sc[j] - mx) : 0.f;
        sum += p[j];
    }
    float inv = 1.0f / sum;
    #pragma unroll
    for (int j = 0; j < 7; j++) p[j] *= inv;

    uint32_t* dH = (uint32_t*)g_oh;
    uint32_t* dL = (uint32_t*)g_ol;
    const int m = b*SS + q;
    #pragma unroll
    for (int d4 = 0; d4 < 8; d4++) {
        float4 o = make_float4(0.f,0.f,0.f,0.f);
        #pragma unroll
        for (int j = 0; j < 7; j++) {
            float4 vv = *(const float4*)&Vs[(tq + j)*68 + dbase + d4*4];
            o.x += p[j]*vv.x; o.y += p[j]*vv.y; o.z += p[j]*vv.z; o.w += p[j]*vv.w;
        }
        int c = h*64 + dbase + d4*4;
        st_frag(dH, dL, m, c,     make_float2(o.x, o.y));
        st_frag(dH, dL, m, c + 2, make_float2(o.z, o.w));
    }

    if (half == 0) {
        float* prow = &probs[((size_t)(b*HH + h)*SS + q)*8];
        *(float4*)&prow[0] = make_float4(p[0], p[1], p[2], p[3]);
        *(float4*)&prow[4] = make_float4(p[4], p[5], p[6], 0.f);
    }
}

// ---------------------------------------------------------------------------
__global__ __launch_bounds__(256)
void band_write(const float* __restrict__ probs, float* __restrict__ attn_out) {
    int idx = blockIdx.x * blockDim.x + threadIdx.x;
    if (idx >= BB*HH*SS) return;
    int q = idx & (SS - 1);
    const float* prow = &probs[(size_t)idx * 8];
    float4 p03 = *(const float4*)&prow[0];
    float4 p46 = *(const float4*)&prow[4];
    float p[7] = {p03.x, p03.y, p03.z, p03.w, p46.x, p46.y, p46.z};
    float* arow = attn_out + (size_t)idx * SS;
    #pragma unroll
    for (int j = 0; j < 7; j++) {
        int k = q - 3 + j;
        if ((unsigned)k < SS) arow[k] = p[j];
    }
}

// ---------------------------------------------------------------------------
__global__ __launch_bounds__(128)
void ln2(const float* __restrict__ y0, const float* __restrict__ gw,
         const float* __restrict__ bt, float* __restrict__ out)
{
    const int m = blockIdx.x, t = threadIdx.x;
    float4 v = ((const float4*)(y0 + (size_t)m*DD))[t];
    float s  = v.x + v.y + v.z + v.w;
    float sq = v.x*v.x + v.y*v.y + v.z*v.z + v.w*v.w;
    #pragma unroll
    for (int o = 16; o; o >>= 1) {
        s  += __shfl_xor_sync(0xffffffffu, s,  o);
        sq += __shfl_xor_sync(0xffffffffu, sq, o);
    }
    __shared__ float ss[4], qq[4];
    int w = t >> 5;
    if ((t & 31) == 0) { ss[w] = s; qq[w] = sq; }
    __syncthreads();
    s  = ss[0] + ss[1] + ss[2] + ss[3];
    sq = qq[0] + qq[1] + qq[2] + qq[3];
    float mean = s * (1.0f/DD);
    float var  = sq * (1.0f/DD) - mean*mean;
    float rstd = rsqrtf(var + 1e-5f);
    float4 gg = ((const float4*)gw)[t];
    float4 bb = ((const float4*)bt)[t];
    float4 r;
    r.x = (v.x - mean)*rstd*gg.x + bb.x;
    r.y = (v.y - mean)*rstd*gg.y + bb.y;
    r.z = (v.z - mean)*rstd*gg.z + bb.z;
    r.w = (v.w - mean)*rstd*gg.w + bb.w;
    ((float4*)(out + (size_t)m*DD))[t] = r;
}

// ---------------------------------------------------------------------------
extern "C" void kernel_launch(void* const* d_in, const int* in_sizes, int n_in,
                              void* d_out, int out_size) {
    const float* x    = (const float*)d_in[0];
    const float* wq_w = (const float*)d_in[2];
    const float* wq_b = (const float*)d_in[3];
    const float* wk_w = (const float*)d_in[4];
    const float* wk_b = (const float*)d_in[5];
    const float* wv_w = (const float*)d_in[6];
    const float* wv_b = (const float*)d_in[7];
    const float* wo_w = (const float*)d_in[8];
    const float* wo_b = (const float*)d_in[9];
    const float* ln_g = (const float*)d_in[10];
    const float* ln_b = (const float*)d_in[11];
    const float* pe   = (const float*)d_in[12];

    float* y_out    = (float*)d_out;
    float* attn_out = (float*)d_out + YELEMS;

    static uint4 *p_ah, *p_al, *p_oh, *p_ol;
    static uint2 *p_bh, *p_bl;
    static float *p_qkv, *p_y0, *p_probs;
    static cudaStream_t s2, s3;
    static cudaEvent_t evF, evW, evA, evB;
    static bool init = false;
    if (!init) {
        cudaGetSymbolAddress((void**)&p_ah, g_ah);
        cudaGetSymbolAddress((void**)&p_al, g_al);
        cudaGetSymbolAddress((void**)&p_bh, g_bh);
        cudaGetSymbolAddress((void**)&p_bl, g_bl);
        cudaGetSymbolAddress((void**)&p_oh, g_oh);
        cudaGetSymbolAddress((void**)&p_ol, g_ol);
        cudaGetSymbolAddress((void**)&p_qkv,   g_qkv);
        cudaGetSymbolAddress((void**)&p_y0,    g_y0);
        cudaGetSymbolAddress((void**)&p_probs, g_probs);
        cudaStreamCreateWithFlags(&s2, cudaStreamNonBlocking);
        cudaStreamCreateWithFlags(&s3, cudaStreamNonBlocking);
        cudaEventCreateWithFlags(&evF, cudaEventDisableTiming);
        cudaEventCreateWithFlags(&evW, cudaEventDisableTiming);
        cudaEventCreateWithFlags(&evA, cudaEventDisableTiming);
        cudaEventCreateWithFlags(&evB, cudaEventDisableTiming);
        cudaFuncSetAttribute(attn3, cudaFuncAttributeMaxDynamicSharedMemorySize, ATTN_SMEM);
        cudaFuncSetAttribute(gemm_cp<8>, cudaFuncAttributeMaxDynamicSharedMemorySize, 3*(2*8*1024 + 16384));
        cudaFuncSetAttribute(gemm_cp<4>, cudaFuncAttributeMaxDynamicSharedMemorySize, 3*(2*4*1024 + 16384));
        init = true;
    }

    cudaEventRecord(evF, 0);

    // prep_w concurrent with prep_xp (independent)
    cudaStreamWaitEvent(s3, evF, 0);
    prep_w<<<8192*32/256, 256, 0, s3>>>(wq_w, wk_w, wv_w, wo_w);
    cudaEventRecord(evW, s3);

    prep_xp<<<8192*32/256, 256>>>(x, pe);
    cudaStreamWaitEvent(0, evW, 0);   // join prep_w before gemm1

    // QKV projection WITH fused streaming zero-fill of attn_out (268MB)
    gemm_cp<8><<<dim3(NQKV/128, MM/128), 256, 3*(2*8*1024 + 16384)>>>(
        p_ah, p_al, (const uint4*)p_bh, (const uint4*)p_bl, 0,
        wq_b, wk_b, wv_b, nullptr, p_qkv, NQKV, (float4*)attn_out);

    attn3<<<dim3(SS/128, HH, BB), 256, ATTN_SMEM>>>(p_qkv, p_probs);
    cudaEventRecord(evA, 0);          // probs ready (and zeros written, via gemm1)

    // band_write on side stream; overlaps gemm2 + ln2
    cudaStreamWaitEvent(s2, evA, 0);
    band_write<<<(BB*HH*SS + 255)/256, 256, 0, s2>>>(p_probs, attn_out);
    cudaEventRecord(evB, s2);

    gemm_cp<4><<<dim3(DD/128, MM/64), 256, 3*(2*4*1024 + 16384)>>>(
        p_oh, p_ol, (const uint4*)p_bh, (const uint4*)p_bl, 192,
        wo_b, wo_b, wo_b, x, p_y0, DD, nullptr);

    ln2<<<MM, 128>>>(p_y0, ln_g, ln_b, y_out);

    cudaStreamWaitEvent(0, evB, 0);
}

// round 17
// speedup vs baseline: 1.9231x; 1.0256x over previous
#include <cuda_runtime.h>
#include <cuda_bf16.h>
#include <cstdint>

#define BB   2
#define SS   2048
#define DD   512
#define HH   8
#define MM   (BB*SS)        // 4096
#define NQKV 1536
#define KK   512
#define YELEMS ((size_t)MM*DD)
#define ATTN_ELEMS ((size_t)BB*HH*SS*SS)
#define ATTN_F4 (ATTN_ELEMS/4)          // 16,777,216 float4s
#define ATTN_SMEM ((134*68*2 + 2*128*9)*4)

// zero-write partition (exact): gemm1 112*98304, attn3 56*65536, gemm2 32*65536
#define Z1_F4 11010048u
#define Z2_F4  3670016u
#define Z2_BASE 11010048u
#define Z3_BASE 14680064u

// Frag-packed buffers
__device__ uint4 g_ah[8192*32], g_al[8192*32];   // x+pe hi/lo, frag-packed
__device__ uint2 g_bh[8192*32], g_bl[8192*32];   // [wq;wk;wv;wo] hi/lo, frag-packed
__device__ uint4 g_oh[8192*32], g_ol[8192*32];   // attn output hi/lo, frag-packed
__device__ float g_qkv[(size_t)MM*NQKV];
__device__ float g_y0[MM*DD];
__device__ float g_probs[(size_t)BB*HH*SS*8];

// ---------------------------------------------------------------------------
__device__ __forceinline__ void packhl(float2 v, uint32_t& h, uint32_t& l) {
    __nv_bfloat162 hb = __floats2bfloat162_rn(v.x, v.y);
    h = *reinterpret_cast<uint32_t*>(&hb);
    float hx = __bfloat162float(hb.x), hy = __bfloat162float(hb.y);
    __nv_bfloat162 lb = __floats2bfloat162_rn(v.x - hx, v.y - hy);
    l = *reinterpret_cast<uint32_t*>(&lb);
}
__device__ __forceinline__ void mma16(float* c, const uint32_t* a, const uint32_t* b) {
    asm volatile(
      "mma.sync.aligned.m16n8k16.row.col.f32.bf16.bf16.f32 "
      "{%0,%1,%2,%3},{%4,%5,%6,%7},{%8,%9},{%0,%1,%2,%3};"
      : "+f"(c[0]), "+f"(c[1]), "+f"(c[2]), "+f"(c[3])
      : "r"(a[0]), "r"(a[1]), "r"(a[2]), "r"(a[3]), "r"(b[0]), "r"(b[1]));
}
__device__ __forceinline__ uint32_t smem_u32(const void* p) {
    uint32_t a;
    asm("{ .reg .u64 t; cvta.to.shared.u64 t, %1; cvt.u32.u64 %0, t; }" : "=r"(a) : "l"(p));
    return a;
}
__device__ __forceinline__ void cp16(uint32_t dst, const void* src) {
    asm volatile("cp.async.cg.shared.global [%0], [%1], 16;" :: "r"(dst), "l"(src));
}

// ---------------------------------------------------------------------------
__global__ __launch_bounds__(256)
void prep_xp(const float* __restrict__ x, const float* __restrict__ pe) {
    int gid = blockIdx.x * 256 + threadIdx.x;   // 8192*32
    if (gid >= 8192*32) return;
    int lane = gid & 31, fa = gid >> 5;
    int kblk = fa & 31, mblk = fa >> 5;
    int g = lane >> 2, tg = lane & 3;
    int r0 = mblk*16 + g, c0 = kblk*16 + tg*2;
    int s0 = r0 & (SS-1), s1 = (r0+8) & (SS-1);
    float2 v0 = *(const float2*)(x + (size_t)r0*KK + c0);
    float2 v1 = *(const float2*)(x + (size_t)(r0+8)*KK + c0);
    float2 v2 = *(const float2*)(x + (size_t)r0*KK + c0 + 8);
    float2 v3 = *(const float2*)(x + (size_t)(r0+8)*KK + c0 + 8);
    float2 e;
    e = *(const float2*)(pe + (size_t)s0*KK + c0);     v0.x += e.x; v0.y += e.y;
    e = *(const float2*)(pe + (size_t)s1*KK + c0);     v1.x += e.x; v1.y += e.y;
    e = *(const float2*)(pe + (size_t)s0*KK + c0 + 8); v2.x += e.x; v2.y += e.y;
    e = *(const float2*)(pe + (size_t)s1*KK + c0 + 8); v3.x += e.x; v3.y += e.y;
    uint4 hv, lv;
    packhl(v0, hv.x, lv.x); packhl(v1, hv.y, lv.y);
    packhl(v2, hv.z, lv.z); packhl(v3, hv.w, lv.w);
    g_ah[gid] = hv; g_al[gid] = lv;
}

__global__ __launch_bounds__(256)
void prep_w(const float* __restrict__ wq, const float* __restrict__ wk,
            const float* __restrict__ wv, const float* __restrict__ wo) {
    int gid = blockIdx.x * 256 + threadIdx.x;   // 8192*32
    if (gid >= 8192*32) return;
    int lane = gid & 31, fb = gid >> 5;
    int kblk = fb & 31, nblk = fb >> 5;
    int n = nblk*8 + (lane >> 2);
    int c0 = kblk*16 + (lane & 3)*2;
    const float* row = (n < 512)  ? wq + (size_t)n*KK
                     : (n < 1024) ? wk + (size_t)(n-512)*KK
                     : (n < 1536) ? wv + (size_t)(n-1024)*KK
                                  : wo + (size_t)(n-1536)*KK;
    float2 u0 = *(const float2*)(row + c0);
    float2 u1 = *(const float2*)(row + c0 + 8);
    uint2 hv, lv;
    packhl(u0, hv.x, lv.x); packhl(u1, hv.y, lv.y);
    g_bh[gid] = hv; g_bl[gid] = lv;
}

// ---------------------------------------------------------------------------
// bf16x3 GEMM, frag-packed inputs, 3-stage cp.async pipeline, ONE sync/stage.
// ZPS zero-slices per stage streamed into zbuf (load-balanced zero-fill).
template<int MF, int ZPS>
__global__ __launch_bounds__(256, 2)
void gemm_cp(const uint4* __restrict__ Ah, const uint4* __restrict__ Al,
             const uint4* __restrict__ Bh4, const uint4* __restrict__ Bl4,
             int nblk_base,
             const float* __restrict__ bi0, const float* __restrict__ bi1,
             const float* __restrict__ bi2,
             const float* __restrict__ res, float* __restrict__ C, int ldc,
             float4* __restrict__ zbuf, unsigned zstride)
{
    extern __shared__ __align__(16) char smem[];
    constexpr int A_BYTES = MF*64*16;          // MF*1024
    constexpr int STAGE   = 2*A_BYTES + 16384;
    const uint32_t sb = smem_u32(smem);

    const int t = threadIdx.x, lane = t & 31, w = t >> 5;
    const int g = lane >> 2, tg = lane & 3;
    const int mblk0 = blockIdx.y * MF;
    const int bn = blockIdx.x * 128;
    const int nblk0 = nblk_base + blockIdx.x * 16;
    const int seg = bn >> 9;
    const float* bi = (seg == 0) ? bi0 : (seg == 1) ? bi1 : bi2;
    constexpr int MPW = MF/4;
    const int wmt = (w & 3)*MPW, wnt = (w >> 2)*8;
    const unsigned gtid = (blockIdx.y * gridDim.x + blockIdx.x) * 256 + t;

    float acc[MPW][8][4] = {};

    auto issue = [&](int st) {
        const int kb = st*2;
        const uint32_t base = sb + (st % 3)*STAGE;
        #pragma unroll
        for (int i = 0; i < MF/4; i++) {
            int s = t + 256*i;
            int sfr = s >> 5, ln = s & 31;
            int mt = sfr >> 1, kt = sfr & 1;
            size_t fa = ((size_t)(mblk0 + mt)*32 + kb + kt)*32 + ln;
            cp16(base + s*16,           Ah + fa);
            cp16(base + A_BYTES + s*16, Al + fa);
        }
        #pragma unroll
        for (int i = 0; i < 2; i++) {
            int s = t + 256*i;
            int sfr = s >> 4, lp = s & 15;
            int nt = sfr >> 1, kt = sfr & 1;
            size_t fb = ((size_t)(nblk0 + nt)*32 + kb + kt)*16 + lp;
            cp16(base + 2*A_BYTES + s*16,        Bh4 + fb);
            cp16(base + 2*A_BYTES + 8192 + s*16, Bl4 + fb);
        }
        asm volatile("cp.async.commit_group;");
    };

    issue(0);
    issue(1);
    const float4 z4 = make_float4(0.f, 0.f, 0.f, 0.f);
    for (int s = 0; s < 16; s++) {
        if (s < 15) asm volatile("cp.async.wait_group 1;");
        else        asm volatile("cp.async.wait_group 0;");
        __syncthreads();

        if (ZPS > 0) {
            #pragma unroll
            for (int k = 0; k < ZPS; k++) {
                size_t off = (size_t)((unsigned)s*ZPS + k) * zstride + gtid;
                __stcs(zbuf + off, z4);
            }
        }

        const char* stg = smem + (s % 3)*STAGE;
        const uint4* AsH = (const uint4*)stg;
        const uint4* AsL = (const uint4*)(stg + A_BYTES);
        const uint2* BsH = (const uint2*)(stg + 2*A_BYTES);
        const uint2* BsL = (const uint2*)(stg + 2*A_BYTES + 8192);

        #pragma unroll
        for (int kt = 0; kt < 2; kt++) {
            uint4 ah[MPW], al[MPW];
            uint2 bh[8], bl[8];
            #pragma unroll
            for (int m = 0; m < MPW; m++) ah[m] = AsH[((wmt+m)*2 + kt)*32 + lane];
            #pragma unroll
            for (int n = 0; n < 8; n++) bh[n] = BsH[((wnt+n)*2 + kt)*32 + lane];
            #pragma unroll
            for (int m = 0; m < MPW; m++)
                #pragma unroll
                for (int n = 0; n < 8; n++)
                    mma16(acc[m][n], (const uint32_t*)&ah[m], (const uint32_t*)&bh[n]);
            #pragma unroll
            for (int n = 0; n < 8; n++) bl[n] = BsL[((wnt+n)*2 + kt)*32 + lane];
            #pragma unroll
            for (int m = 0; m < MPW; m++)
                #pragma unroll
                for (int n = 0; n < 8; n++)
                    mma16(acc[m][n], (const uint32_t*)&ah[m], (const uint32_t*)&bl[n]);
            #pragma unroll
            for (int m = 0; m < MPW; m++) al[m] = AsL[((wmt+m)*2 + kt)*32 + lane];
            #pragma unroll
            for (int m = 0; m < MPW; m++)
                #pragma unroll
                for (int n = 0; n < 8; n++)
                    mma16(acc[m][n], (const uint32_t*)&al[m], (const uint32_t*)&bh[n]);
        }

        if (s + 2 < 16) issue(s + 2);
    }

    #pragma unroll
    for (int m = 0; m < MPW; m++) {
        const int gm = mblk0*16 + (wmt + m)*16 + g;
        #pragma unroll
        for (int n = 0; n < 8; n++) {
            const int gn = bn + (wnt + n)*8 + tg*2;
            const int gl = gn & 511;
            float c0 = acc[m][n][0] + bi[gl];
            float c1 = acc[m][n][1] + bi[gl + 1];
            float c2 = acc[m][n][2] + bi[gl];
            float c3 = acc[m][n][3] + bi[gl + 1];
            if (res) {
                c0 += res[(size_t)gm*ldc + gn];
                c1 += res[(size_t)gm*ldc + gn + 1];
                c2 += res[(size_t)(gm+8)*ldc + gn];
                c3 += res[(size_t)(gm+8)*ldc + gn + 1];
            }
            *(float2*)&C[(size_t)gm*ldc + gn]     = make_float2(c0, c1);
            *(float2*)&C[(size_t)(gm+8)*ldc + gn] = make_float2(c2, c3);
        }
    }
}

// ---------------------------------------------------------------------------
__device__ __forceinline__ void st_frag(uint32_t* dH, uint32_t* dL,
                                        int m, int c, float2 v) {
    size_t fa = ((size_t)(m >> 4))*32 + (c >> 4);
    int mr = m & 15, kc = c & 15;
    int lane = (mr & 7)*4 + ((kc & 7) >> 1);
    int comp = ((mr >> 3) & 1) | ((kc >> 3) << 1);
    uint32_t h, l; packhl(v, h, l);
    size_t off = (fa*32 + lane)*4 + comp;
    dH[off] = h; dL[off] = l;
}

// Banded attention, split-d + its 22% share of the zero-fill (56 f4/thread).
__global__ __launch_bounds__(256)
void attn3(const float* __restrict__ qkv, float* __restrict__ probs,
           float4* __restrict__ zbuf)
{
    extern __shared__ float sh[];
    float* Ks = sh;                    // [134][68]
    float* Vs = sh + 134*68;           // [134][68]
    float* Pp = sh + 2*134*68;         // [2][128][9]

    const int t  = threadIdx.x;
    const int tq = t & 127;
    const int half = t >> 7;
    const int q0 = blockIdx.x * 128;
    const int h  = blockIdx.y;
    const int b  = blockIdx.z;
    const unsigned gtid = (((unsigned)blockIdx.z*HH + blockIdx.y)*gridDim.x + blockIdx.x)*256 + t;
    const float4 z4 = make_float4(0.f, 0.f, 0.f, 0.f);

    for (int i = t; i < 134*16; i += 256) {
        int r = i >> 4, d4 = i & 15;
        int row = q0 - 3 + r;
        float4 kv = z4, vv = z4;
        if ((unsigned)row < SS) {
            size_t base = (size_t)(b*SS + row)*NQKV + h*64 + d4*4;
            kv = *(const float4*)&qkv[base + 512];
            vv = *(const float4*)&qkv[base + 1024];
        }
        *(float4*)&Ks[r*68 + d4*4] = kv;
        *(float4*)&Vs[r*68 + d4*4] = vv;
    }
    // first chunk of zero-fill share (overlaps the smem-load latency)
    #pragma unroll
    for (int k = 0; k < 16; k++)
        __stcs(zbuf + (size_t)k*65536 + gtid, z4);
    __syncthreads();

    const int q = q0 + tq;
    const int dbase = half*32;
    float sc[7] = {0.f,0.f,0.f,0.f,0.f,0.f,0.f};
    const float* Qrow = &qkv[(size_t)(b*SS + q)*NQKV + h*64 + dbase];
    #pragma unroll
    for (int d4 = 0; d4 < 8; d4++) {
        float4 qv = *(const float4*)&Qrow[d4*4];
        #pragma unroll
        for (int j = 0; j < 7; j++) {
            float4 kk = *(const float4*)&Ks[(tq + j)*68 + dbase + d4*4];
            sc[j] += qv.x*kk.x + qv.y*kk.y + qv.z*kk.z + qv.w*kk.w;
        }
    }
    float* prow_s = &Pp[(half*128 + tq)*9];
    #pragma unroll
    for (int j = 0; j < 7; j++) prow_s[j] = sc[j];
    __syncthreads();
    #pragma unroll
    for (int j = 0; j < 7; j++)
        sc[j] = Pp[tq*9 + j] + Pp[(128 + tq)*9 + j];

    float mx = -1e30f;
    #pragma unroll
    for (int j = 0; j < 7; j++) {
        sc[j] *= 0.125f;
        if ((unsigned)(q - 3 + j) < SS) mx = fmaxf(mx, sc[j]);
    }
    float p[7], sum = 0.f;
    #pragma unroll
    for (int j = 0; j < 7; j++) {
        p[j] = ((unsigned)(q - 3 + j) < SS) ? expf(sc[j] - mx) : 0.f;
        sum += p[j];
    }
    float inv = 1.0f / sum;
    #pragma unroll
    for (int j = 0; j < 7; j++) p[j] *= inv;

    uint32_t* dH = (uint32_t*)g_oh;
    uint32_t* dL = (uint32_t*)g_ol;
    const int m = b*SS + q;
    #pragma unroll
    for (int d4 = 0; d4 < 8; d4++) {
        float4 o = z4;
        #pragma unroll
        for (int j = 0; j < 7; j++) {
            float4 vv = *(const float4*)&Vs[(tq + j)*68 + dbase + d4*4];
            o.x += p[j]*vv.x; o.y += p[j]*vv.y; o.z += p[j]*vv.z; o.w += p[j]*vv.w;
        }
        int c = h*64 + dbase + d4*4;
        st_frag(dH, dL, m, c,     make_float2(o.x, o.y));
        st_frag(dH, dL, m, c + 2, make_float2(o.z, o.w));
    }

    if (half == 0) {
        float* prow = &probs[((size_t)(b*HH + h)*SS + q)*8];
        *(float4*)&prow[0] = make_float4(p[0], p[1], p[2], p[3]);
        *(float4*)&prow[4] = make_float4(p[4], p[5], p[6], 0.f);
    }
    // remaining zero-fill share
    #pragma unroll
    for (int k = 16; k < 56; k++)
        __stcs(zbuf + (size_t)k*65536 + gtid, z4);
}

// ---------------------------------------------------------------------------
__global__ __launch_bounds__(256)
void band_write(const float* __restrict__ probs, float* __restrict__ attn_out) {
    int idx = blockIdx.x * blockDim.x + threadIdx.x;
    if (idx >= BB*HH*SS) return;
    int q = idx & (SS - 1);
    const float* prow = &probs[(size_t)idx * 8];
    float4 p03 = *(const float4*)&prow[0];
    float4 p46 = *(const float4*)&prow[4];
    float p[7] = {p03.x, p03.y, p03.z, p03.w, p46.x, p46.y, p46.z};
    float* arow = attn_out + (size_t)idx * SS;
    #pragma unroll
    for (int j = 0; j < 7; j++) {
        int k = q - 3 + j;
        if ((unsigned)k < SS) arow[k] = p[j];
    }
}

// ---------------------------------------------------------------------------
__global__ __launch_bounds__(128)
void ln2(const float* __restrict__ y0, const float* __restrict__ gw,
         const float* __restrict__ bt, float* __restrict__ out)
{
    const int m = blockIdx.x, t = threadIdx.x;
    float4 v = ((const float4*)(y0 + (size_t)m*DD))[t];
    float s  = v.x + v.y + v.z + v.w;
    float sq = v.x*v.x + v.y*v.y + v.z*v.z + v.w*v.w;
    #pragma unroll
    for (int o = 16; o; o >>= 1) {
        s  += __shfl_xor_sync(0xffffffffu, s,  o);
        sq += __shfl_xor_sync(0xffffffffu, sq, o);
    }
    __shared__ float ss[4], qq[4];
    int w = t >> 5;
    if ((t & 31) == 0) { ss[w] = s; qq[w] = sq; }
    __syncthreads();
    s  = ss[0] + ss[1] + ss[2] + ss[3];
    sq = qq[0] + qq[1] + qq[2] + qq[3];
    float mean = s * (1.0f/DD);
    float var  = sq * (1.0f/DD) - mean*mean;
    float rstd = rsqrtf(var + 1e-5f);
    float4 gg = ((const float4*)gw)[t];
    float4 bb = ((const float4*)bt)[t];
    float4 r;
    r.x = (v.x - mean)*rstd*gg.x + bb.x;
    r.y = (v.y - mean)*rstd*gg.y + bb.y;
    r.z = (v.z - mean)*rstd*gg.z + bb.z;
    r.w = (v.w - mean)*rstd*gg.w + bb.w;
    ((float4*)(out + (size_t)m*DD))[t] = r;
}

// ---------------------------------------------------------------------------
extern "C" void kernel_launch(void* const* d_in, const int* in_sizes, int n_in,
                              void* d_out, int out_size) {
    const float* x    = (const float*)d_in[0];
    const float* wq_w = (const float*)d_in[2];
    const float* wq_b = (const float*)d_in[3];
    const float* wk_w = (const float*)d_in[4];
    const float* wk_b = (const float*)d_in[5];
    const float* wv_w = (const float*)d_in[6];
    const float* wv_b = (const float*)d_in[7];
    const float* wo_w = (const float*)d_in[8];
    const float* wo_b = (const float*)d_in[9];
    const float* ln_g = (const float*)d_in[10];
    const float* ln_b = (const float*)d_in[11];
    const float* pe   = (const float*)d_in[12];

    float* y_out    = (float*)d_out;
    float* attn_out = (float*)d_out + YELEMS;

    static uint4 *p_ah, *p_al, *p_oh, *p_ol;
    static uint2 *p_bh, *p_bl;
    static float *p_qkv, *p_y0, *p_probs;
    static cudaStream_t s2, s3;
    static cudaEvent_t evF, evW, evG, evB;
    static bool init = false;
    if (!init) {
        cudaGetSymbolAddress((void**)&p_ah, g_ah);
        cudaGetSymbolAddress((void**)&p_al, g_al);
        cudaGetSymbolAddress((void**)&p_bh, g_bh);
        cudaGetSymbolAddress((void**)&p_bl, g_bl);
        cudaGetSymbolAddress((void**)&p_oh, g_oh);
        cudaGetSymbolAddress((void**)&p_ol, g_ol);
        cudaGetSymbolAddress((void**)&p_qkv,   g_qkv);
        cudaGetSymbolAddress((void**)&p_y0,    g_y0);
        cudaGetSymbolAddress((void**)&p_probs, g_probs);
        cudaStreamCreateWithFlags(&s2, cudaStreamNonBlocking);
        cudaStreamCreateWithFlags(&s3, cudaStreamNonBlocking);
        cudaEventCreateWithFlags(&evF, cudaEventDisableTiming);
        cudaEventCreateWithFlags(&evW, cudaEventDisableTiming);
        cudaEventCreateWithFlags(&evG, cudaEventDisableTiming);
        cudaEventCreateWithFlags(&evB, cudaEventDisableTiming);
        cudaFuncSetAttribute(attn3, cudaFuncAttributeMaxDynamicSharedMemorySize, ATTN_SMEM);
        cudaFuncSetAttribute(gemm_cp<8,7>, cudaFuncAttributeMaxDynamicSharedMemorySize, 3*(2*8*1024 + 16384));
        cudaFuncSetAttribute(gemm_cp<4,2>, cudaFuncAttributeMaxDynamicSharedMemorySize, 3*(2*4*1024 + 16384));
        init = true;
    }

    float4* z0 = (float4*)attn_out;

    cudaEventRecord(evF, 0);
    cudaStreamWaitEvent(s3, evF, 0);
    prep_w<<<8192*32/256, 256, 0, s3>>>(wq_w, wk_w, wv_w, wo_w);
    cudaEventRecord(evW, s3);

    prep_xp<<<8192*32/256, 256>>>(x, pe);
    cudaStreamWaitEvent(0, evW, 0);

    // QKV projection + 66% of attn_out zero-fill (slices 0..111 of 98304)
    gemm_cp<8,7><<<dim3(NQKV/128, MM/128), 256, 3*(2*8*1024 + 16384)>>>(
        p_ah, p_al, (const uint4*)p_bh, (const uint4*)p_bl, 0,
        wq_b, wk_b, wv_b, nullptr, p_qkv, NQKV, z0, 98304u);

    // banded attention + 22% of zero-fill
    attn3<<<dim3(SS/128, HH, BB), 256, ATTN_SMEM>>>(p_qkv, p_probs, z0 + Z2_BASE);

    // O projection + residual + final 12% of zero-fill
    gemm_cp<4,2><<<dim3(DD/128, MM/64), 256, 3*(2*4*1024 + 16384)>>>(
        p_oh, p_ol, (const uint4*)p_bh, (const uint4*)p_bl, 192,
        wo_b, wo_b, wo_b, x, p_y0, DD, z0 + Z3_BASE, 65536u);
    cudaEventRecord(evG, 0);          // zeros fully written + probs ready

    // band_write on side stream; overlaps ln2
    cudaStreamWaitEvent(s2, evG, 0);
    band_write<<<(BB*HH*SS + 255)/256, 256, 0, s2>>>(p_probs, attn_out);
    cudaEventRecord(evB, s2);

    ln2<<<MM, 128>>>(p_y0, ln_g, ln_b, y_out);

    cudaStreamWaitEvent(0, evB, 0);
}